// round 4
// baseline (speedup 1.0000x reference)
#include <cuda_runtime.h>
#include <cuda_bf16.h>
#include <math.h>
#include <stdint.h>

// ---------------- problem constants ----------------
#define Bb 4
#define Ll 512
#define Ee 256
#define Kk 8
#define Dd 6
#define LM 64
#define KN 4
#define Gg 32000
#define KE (Kk*Ee)          // 2048
#define TOK (Bb*Ll)         // 2048

// ---------------- scratch (static device memory; no allocations) ----------------
__device__ float g_xsa [TOK*Ee];
__device__ float g_xsad[TOK*Ee];
__device__ float g_t1  [TOK*Ee];
__device__ float g_q   [TOK*KE];
__device__ float g_q2  [TOK*KE];
__device__ float g_h   [(long)Bb*Ll*Kk*Ll];
__device__ float g_acat[TOK*768];                 // [t1a | t1b | z]
__device__ float g_wcat1[Dd*2*Ee*Ee];             // per layer: [wt][wtc^T]
__device__ float g_wcat2[Dd*3*Ee*Ee];             // per layer: [wtc; wt^T; wu^T]
__device__ float g_lptok[Bb*LM*Ee];
__device__ float g_xx1 [Bb*LM*KN*Ee];
__device__ float g_s   [(long)Bb*LM*KN*Ll];
__device__ float g_xx  [Bb*LM*KN*Ee];
__device__ float g_v   [Bb*LM*KN*Ee];
__device__ float g_logits[(long)Bb*LM*KN*Gg];
__device__ float g_lse [Bb*LM*KN];
__device__ float g_tval[Bb*LM*KN];

// ---------------- reductions ----------------
__device__ __forceinline__ float warp_sum(float v){
    #pragma unroll
    for (int o=16;o;o>>=1) v += __shfl_xor_sync(0xffffffffu, v, o);
    return v;
}
__device__ __forceinline__ float warp_max(float v){
    #pragma unroll
    for (int o=16;o;o>>=1) v = fmaxf(v, __shfl_xor_sync(0xffffffffu, v, o));
    return v;
}
__device__ float block_sum256(float v){
    __shared__ float sh[8];
    int lane = threadIdx.x & 31, w = threadIdx.x >> 5;
    v = warp_sum(v);
    if (lane==0) sh[w] = v;
    __syncthreads();
    float r = (threadIdx.x < 8) ? sh[threadIdx.x] : 0.f;
    if (w==0){ r = warp_sum(r); if (lane==0) sh[0]=r; }
    __syncthreads();
    float out = sh[0];
    __syncthreads();
    return out;
}
__device__ float block_max256(float v){
    __shared__ float sh[8];
    int lane = threadIdx.x & 31, w = threadIdx.x >> 5;
    v = warp_max(v);
    if (lane==0) sh[w] = v;
    __syncthreads();
    float r = (threadIdx.x < 8) ? sh[threadIdx.x] : -INFINITY;
    if (w==0){ r = warp_max(r); if (lane==0) sh[0]=r; }
    __syncthreads();
    float out = sh[0];
    __syncthreads();
    return out;
}

// ---------------- bf16 / cp.async helpers ----------------
// pack two fp32 into bf16x2 reg: low half = lo (even k), high = hi (odd k)
__device__ __forceinline__ uint32_t pk2(float lo, float hi){
    uint32_t r;
    asm("cvt.rn.bf16x2.f32 %0, %1, %2;" : "=r"(r) : "f"(hi), "f"(lo));
    return r;
}
// split a float2 into hi-bf16 pair and residual-lo-bf16 pair
__device__ __forceinline__ void split2(float2 v, uint32_t &hi, uint32_t &lo){
    __nv_bfloat16 hx = __float2bfloat16(v.x);
    __nv_bfloat16 hy = __float2bfloat16(v.y);
    float rx = v.x - __bfloat162float(hx);
    float ry = v.y - __bfloat162float(hy);
    union { __nv_bfloat162 b; uint32_t u; } c;
    c.b = __halves2bfloat162(hx, hy);
    hi = c.u;
    lo = pk2(rx, ry);
}
__device__ __forceinline__ void mma_bf16(float* d, const uint32_t* a, const uint32_t* b){
    asm volatile(
      "mma.sync.aligned.m16n8k16.row.col.f32.bf16.bf16.f32 "
      "{%0,%1,%2,%3}, {%4,%5,%6,%7}, {%8,%9}, {%0,%1,%2,%3};\n"
      : "+f"(d[0]),"+f"(d[1]),"+f"(d[2]),"+f"(d[3])
      : "r"(a[0]),"r"(a[1]),"r"(a[2]),"r"(a[3]), "r"(b[0]),"r"(b[1]));
}
__device__ __forceinline__ void cp16(float* s, const float* g){
    uint32_t sa = (uint32_t)__cvta_generic_to_shared(s);
    asm volatile("cp.async.ca.shared.global [%0], [%1], 16;\n" :: "r"(sa), "l"(g));
}
__device__ __forceinline__ void cp_commit(){ asm volatile("cp.async.commit_group;\n" ::); }
template<int W> __device__ __forceinline__ void cp_wait(){ asm volatile("cp.async.wait_group %0;\n" :: "n"(W)); }

// PMODE output index mapping:
// 0: bz*sC + r*N + c
// 1: q2 perm  (r over TOK, c over KE)
// 2: y perm   (r over L*K, c over E)
// 3: xx1 perm (r over B*LM, c over KN*E)
// 4: stage1 concat: r*768 + bz*256 + c
template<int PMODE>
__device__ __forceinline__ long out_index(int r, int c, int bz, int N, long sC){
    if (PMODE==0) return (long)bz*sC + (long)r*N + c;
    if (PMODE==1) return (((long)(r>>9))<<20) + ((long)(r&511)<<11) + c;
    if (PMODE==2) return (((long)(bz*512 + (r>>3)))<<11) + ((long)(r&7)<<8) + c;
    if (PMODE==3) return (((long)(r>>6))<<16) + ((long)(r&63)<<10) + c;
    return (long)r*768 + ((long)bz<<8) + c;
}

template<int BM,int BN,bool TRANSB>
constexpr int smem_bytes(){
    return 2*(BM*36 + (TRANSB? BN*36 : 32*(BN+8)))*4;
}

// ---------------- pipelined bf16 tensor-core GEMM ----------------
// C[M,N] = op( A[M,K] * B ).  TRANSB: B is [N,K] row-major (pitch Kd), else [K,N] (pitch N).
// A pitch = lda. Inputs fp32 (staged raw in smem; converted at fragment load).
// COMP: split-bf16 3-mma (hi/lo split in registers; ~2^-16 product accuracy).
// ROLLMODE: 0 none; 1 circular shift rows by rollShift within 512-row groups;
//           2 per-batch shift (+rollShift for bz=0, -rollShift for bz=1).
template<int BM,int BN,int WM,int WN,bool TRANSB,bool RELU,bool BIAS,int PMODE,int ROLLMODE,bool COMP>
__global__ __launch_bounds__(256, 2)
void tgemm_k(const float* __restrict__ A, const float* __restrict__ B,
             const float* __restrict__ bias, float* __restrict__ C,
             int M, int N, int Kd, int lda,
             long sA, long sB, long sC, int rollShift)
{
    constexpr int ASZ = BM*36;
    constexpr int BSZ = TRANSB ? BN*36 : 32*(BN+8);
    constexpr int STG = ASZ+BSZ;
    constexpr int MI  = WM/16, NI = WN/8;
    constexpr int WCOLS = BN/WN;
    constexpr int LDN = BN+8;

    extern __shared__ float sm[];

    const int bz = blockIdx.z;
    const float* Ap = A + (long)bz*sA;
    const float* Bp = B + (long)bz*sB;

    int rs = 0;
    if (ROLLMODE==1) rs = rollShift;
    if (ROLLMODE==2) rs = (bz==0) ? rollShift : -rollShift;

    const int row0 = blockIdx.y*BM, col0 = blockIdx.x*BN;
    const int tid  = threadIdx.x;
    const int warp = tid >> 5, lane = tid & 31;
    const int wy = warp / WCOLS, wx = warp % WCOLS;
    const int g = lane >> 2, c4 = lane & 3;

    auto load_tile = [&](int kt, int st){
        float* base = sm + st*STG;
        float* Ah = base;
        float* Bh = base + ASZ;
        const int k0 = kt*32;
        #pragma unroll
        for (int i=0;i<BM*8/256;i++){
            int ch = tid + i*256; int r = ch>>3, q = ch&7;
            int gr = row0 + r;
            if (ROLLMODE) gr = (gr & ~511) | ((gr - rs) & 511);
            cp16(Ah + r*36 + 4*q, Ap + (long)gr*lda + k0 + 4*q);
        }
        if (TRANSB){
            #pragma unroll
            for (int i=0;i<BN*8/256;i++){
                int ch = tid + i*256; int n = ch>>3, q = ch&7;
                cp16(Bh + n*36 + 4*q, Bp + (long)(col0+n)*Kd + k0 + 4*q);
            }
        } else {
            #pragma unroll
            for (int i=0;i<(32*BN/4)/256;i++){
                int ch = tid + i*256; int k = ch/(BN/4), j = ch%(BN/4);
                cp16(Bh + k*LDN + 4*j, Bp + (long)(k0+k)*N + col0 + 4*j);
            }
        }
        cp_commit();
    };

    float acc[MI][NI][4];
    #pragma unroll
    for (int i=0;i<MI;i++)
        #pragma unroll
        for (int j=0;j<NI;j++)
            #pragma unroll
            for (int t=0;t<4;t++) acc[i][j][t]=0.f;

    const int nit = Kd/32;
    load_tile(0, 0);

    for (int it=0; it<nit; it++){
        if (it+1 < nit){ load_tile(it+1, (it+1)&1); cp_wait<1>(); }
        else           { cp_wait<0>(); }
        __syncthreads();

        float* base = sm + (it&1)*STG;
        float* Ah = base;
        float* Bh = base + ASZ;

        #pragma unroll
        for (int ks=0; ks<2; ks++){
            const int kb = ks*16;
            uint32_t af[MI][4], bf[NI][2];
            uint32_t afl[COMP?MI:1][4], bfl[COMP?NI:1][2];
            #pragma unroll
            for (int mi=0; mi<MI; mi++){
                int rr = wy*WM + mi*16;
                const float* a0 = Ah + (rr+g  )*36 + kb + 2*c4;
                const float* a1 = Ah + (rr+g+8)*36 + kb + 2*c4;
                float2 v00 = *(const float2*)(a0);
                float2 v10 = *(const float2*)(a1);
                float2 v01 = *(const float2*)(a0+8);
                float2 v11 = *(const float2*)(a1+8);
                if (COMP){
                    split2(v00, af[mi][0], afl[mi][0]);
                    split2(v10, af[mi][1], afl[mi][1]);
                    split2(v01, af[mi][2], afl[mi][2]);
                    split2(v11, af[mi][3], afl[mi][3]);
                } else {
                    af[mi][0]=pk2(v00.x,v00.y); af[mi][1]=pk2(v10.x,v10.y);
                    af[mi][2]=pk2(v01.x,v01.y); af[mi][3]=pk2(v11.x,v11.y);
                }
            }
            #pragma unroll
            for (int ni=0; ni<NI; ni++){
                int cc = wx*WN + ni*8 + g;
                float2 w01, w89;
                if (TRANSB){
                    const float* b0 = Bh + cc*36 + kb + 2*c4;
                    w01 = *(const float2*)(b0);
                    w89 = *(const float2*)(b0+8);
                } else {
                    w01.x = Bh[(kb+2*c4  )*LDN + cc];
                    w01.y = Bh[(kb+2*c4+1)*LDN + cc];
                    w89.x = Bh[(kb+2*c4+8)*LDN + cc];
                    w89.y = Bh[(kb+2*c4+9)*LDN + cc];
                }
                if (COMP){
                    split2(w01, bf[ni][0], bfl[ni][0]);
                    split2(w89, bf[ni][1], bfl[ni][1]);
                } else {
                    bf[ni][0]=pk2(w01.x,w01.y);
                    bf[ni][1]=pk2(w89.x,w89.y);
                }
            }
            #pragma unroll
            for (int mi=0; mi<MI; mi++)
                #pragma unroll
                for (int ni=0; ni<NI; ni++){
                    if (COMP){
                        mma_bf16(acc[mi][ni], afl[mi], bf[ni]);
                        mma_bf16(acc[mi][ni], af[mi], bfl[ni]);
                    }
                    mma_bf16(acc[mi][ni], af[mi], bf[ni]);
                }
        }
        __syncthreads();
    }

    // ---- epilogue ----
    #pragma unroll
    for (int mi=0; mi<MI; mi++){
        #pragma unroll
        for (int half=0; half<2; half++){
            int r = row0 + wy*WM + mi*16 + g + half*8;
            #pragma unroll
            for (int ni=0; ni<NI; ni++){
                int cc = col0 + wx*WN + ni*8 + 2*c4;
                float v0 = acc[mi][ni][half*2+0];
                float v1 = acc[mi][ni][half*2+1];
                if (BIAS){ v0 += bias[cc]; v1 += bias[cc+1]; }
                if (RELU){ v0 = fmaxf(v0,0.f); v1 = fmaxf(v1,0.f); }
                long idx = out_index<PMODE>(r, cc, bz, N, sC);
                *(float2*)(C + idx) = make_float2(v0, v1);
            }
        }
    }
}

// ---------------- weight prep: concatenated transition blocks ----------------
__global__ void prep_w_k(const float* __restrict__ Wt, const float* __restrict__ Wtc,
                         const float* __restrict__ Wu,
                         float* __restrict__ wcat1, float* __restrict__ wcat2)
{
    long idx = (long)blockIdx.x*1024 + threadIdx.x;
    if (idx >= (long)Dd*5*Ee*Ee) return;
    int d = idx / (5*65536);
    int r = idx % (5*65536);
    int which = r / 65536;
    int e = r % 65536;
    int k = e >> 8, n = e & 255;
    long wb = (long)d*65536;
    if      (which==0) wcat1[(long)d*131072 +          e] = Wt [wb + (long)k*256 + n];
    else if (which==1) wcat1[(long)d*131072 + 65536 +  e] = Wtc[wb + (long)n*256 + k];
    else if (which==2) wcat2[(long)d*196608 + (long)(    k)*256 + n] = Wtc[wb + (long)k*256 + n];
    else if (which==3) wcat2[(long)d*196608 + (long)(256+k)*256 + n] = Wt [wb + (long)n*256 + k];
    else               wcat2[(long)d*196608 + (long)(512+k)*256 + n] = Wu [wb + (long)n*256 + k];
}

// ---------------- elementwise / reduction kernels ----------------
// z = norm(embed[masked]); xsa = z; also write z into Acat cols [512,768)
__global__ void embed_norm_k(const int* __restrict__ masked, const float* __restrict__ embed,
                             float* __restrict__ xsa, float* __restrict__ acat)
{
    int t = blockIdx.x;
    int g = masked[t];
    float v = embed[(long)g*Ee + threadIdx.x];
    float mean = block_sum256(v) * (1.f/Ee);
    float d = v - mean;
    float var = block_sum256(d*d) * (1.f/(Ee-1));
    float o = v / (1.f + sqrtf(var));
    xsa [(long)t*Ee + threadIdx.x] = o;
    acat[(long)t*768 + 512 + threadIdx.x] = o;
}

__global__ void softmax_k(float* __restrict__ h){
    float* row = h + (long)blockIdx.x * Ll;
    float v0 = row[threadIdx.x]       * 0.0625f;
    float v1 = row[threadIdx.x + 256] * 0.0625f;
    float mx = block_max256(fmaxf(v0, v1));
    float e0 = expf(v0 - mx), e1 = expf(v1 - mx);
    float s = block_sum256(e0 + e1);
    float inv = 1.f / s;
    row[threadIdx.x]       = e0 * inv;
    row[threadIdx.x + 256] = e1 * inv;
}

__global__ void update_norm_k(const float* __restrict__ xsad, const float* __restrict__ xid,
                              float* __restrict__ xsa)
{
    long idx = (long)blockIdx.x*Ee + threadIdx.x;
    float u = xsad[idx] + xid[idx];
    float mean = block_sum256(u) * (1.f/Ee);
    float d = u - mean;
    float var = block_sum256(d*d) * (1.f/(Ee-1));
    float un = u / (1.f + sqrtf(var));
    float w = xsa[idx] + 0.05f * un;
    float mean2 = block_sum256(w) * (1.f/Ee);
    float d2 = w - mean2;
    float var2 = block_sum256(d2*d2) * (1.f/(Ee-1));
    xsa[idx] = w / (1.f + sqrtf(var2));
}

__global__ void gather_k(const int* __restrict__ mask, const float* __restrict__ xsa,
                         float* __restrict__ lptok){
    int r = blockIdx.x; int b = r >> 6; int p = mask[r];
    lptok[(long)r*Ee + threadIdx.x] = xsa[(long)(b*Ll + p)*Ee + threadIdx.x];
}

__global__ void lse_k(const float* __restrict__ logits, const int* __restrict__ unmasked,
                      const int* __restrict__ mask, float* __restrict__ lse, float* __restrict__ tval)
{
    int row = blockIdx.x;
    const float* p = logits + (long)row * Gg;
    float m = -INFINITY;
    for (int g = threadIdx.x; g < Gg; g += 256) m = fmaxf(m, p[g]);
    m = block_max256(m);
    float s = 0.f;
    for (int g = threadIdx.x; g < Gg; g += 256) s += expf(p[g] - m);
    s = block_sum256(s);
    if (threadIdx.x == 0){
        lse[row] = m + logf(s);
        int b = row >> 8, n = row & 255, j = n >> 2;
        int tg = unmasked[b*Ll + mask[b*LM + j]];
        tval[row] = p[tg];
    }
}

__global__ void final_k(const float* __restrict__ tval, const float* __restrict__ lse,
                        float* __restrict__ out)
{
    int b = blockIdx.x, j = threadIdx.x;   // 64 threads
    float a[KN]; float m = -INFINITY;
    #pragma unroll
    for (int kn=0;kn<KN;kn++){
        int r = ((b << 6) + j) * KN + kn;
        a[kn] = tval[r] - lse[r];
        m = fmaxf(m, a[kn]);
    }
    float s = 0.f;
    #pragma unroll
    for (int kn=0;kn<KN;kn++) s += expf(a[kn] - m);
    float cent = m + logf(s) - 1.3862943611198906f;   // - log(4)
    __shared__ float sh[64];
    sh[j] = cent; __syncthreads();
    for (int o=32;o;o>>=1){ if (j<o) sh[j] += sh[j+o]; __syncthreads(); }
    if (j==0) out[b] = -sh[0] / (float)LM;
}

// ---------------- host orchestration ----------------
extern "C" void kernel_launch(void* const* d_in, const int* in_sizes, int n_in,
                              void* d_out, int out_size)
{
    (void)in_sizes; (void)n_in; (void)out_size;
    const int*   masked   = (const int*)  d_in[0];
    const int*   unmasked = (const int*)  d_in[1];
    const int*   maskp    = (const int*)  d_in[2];
    const float* embed    = (const float*)d_in[3];
    const float* Wt       = (const float*)d_in[4];
    const float* bt       = (const float*)d_in[5];
    const float* Wtc      = (const float*)d_in[6];
    const float* Wq       = (const float*)d_in[7];
    const float* Wd       = (const float*)d_in[8];
    const float* Wo       = (const float*)d_in[9];
    const float* Wu       = (const float*)d_in[10];
    const float* Wem      = (const float*)d_in[11];
    const float* Wkc      = (const float*)d_in[12];
    const float* bkc      = (const float*)d_in[13];
    float* out = (float*)d_out;

    float *xsa,*xsad,*t1,*q,*q2,*h,*acat,*wcat1,*wcat2;
    float *lptok,*xx1,*sbuf,*xx,*v,*logits,*lse,*tval;
    cudaGetSymbolAddress((void**)&xsa,    g_xsa);
    cudaGetSymbolAddress((void**)&xsad,   g_xsad);
    cudaGetSymbolAddress((void**)&t1,     g_t1);
    cudaGetSymbolAddress((void**)&q,      g_q);
    cudaGetSymbolAddress((void**)&q2,     g_q2);
    cudaGetSymbolAddress((void**)&h,      g_h);
    cudaGetSymbolAddress((void**)&acat,   g_acat);
    cudaGetSymbolAddress((void**)&wcat1,  g_wcat1);
    cudaGetSymbolAddress((void**)&wcat2,  g_wcat2);
    cudaGetSymbolAddress((void**)&lptok,  g_lptok);
    cudaGetSymbolAddress((void**)&xx1,    g_xx1);
    cudaGetSymbolAddress((void**)&sbuf,   g_s);
    cudaGetSymbolAddress((void**)&xx,     g_xx);
    cudaGetSymbolAddress((void**)&v,      g_v);
    cudaGetSymbolAddress((void**)&logits, g_logits);
    cudaGetSymbolAddress((void**)&lse,    g_lse);
    cudaGetSymbolAddress((void**)&tval,   g_tval);

    // ---- kernel instantiations + opt-in dynamic smem ----
    // layers: plain bf16
    auto kS1  = tgemm_k<64,64,32,16,false,true ,false,4,2,false>;
    auto kS2  = tgemm_k<64,64,32,16,false,false,true ,0,0,false>;
    auto kWq  = tgemm_k<128,128,64,32,true ,false,false,1,0,false>;
    auto kQK  = tgemm_k<128,128,64,32,true ,false,false,0,0,false>;
    auto kPV  = tgemm_k<128,128,64,32,false,false,false,2,0,false>;
    auto kWd  = tgemm_k<128,128,64,32,true ,true ,false,0,0,false>;
    auto kWo  = tgemm_k<64,64,32,16,false,false,false,0,0,false>;
    // head: split-bf16 3-mma (COMP)
    auto kG1  = tgemm_k<64,64,32,16,true ,false,true ,3,0,true >;
    auto kG2  = tgemm_k<64,64,32,16,true ,false,false,0,0,true >;
    auto kG3  = tgemm_k<64,64,32,16,false,false,false,0,0,true >;
    auto kG4  = tgemm_k<64,64,32,16,false,false,false,0,0,true >;
    auto kG5  = tgemm_k<64,64,32,16,true ,false,false,0,0,true >;

    constexpr int SM_BT = smem_bytes<128,128,true >();  // 73728
    constexpr int SM_BN = smem_bytes<128,128,false>();  // 71680
    constexpr int SM_ST = smem_bytes<64,64,true >();    // 36864
    constexpr int SM_SN = smem_bytes<64,64,false>();    // 36864

    cudaFuncSetAttribute(kWq, cudaFuncAttributeMaxDynamicSharedMemorySize, SM_BT);
    cudaFuncSetAttribute(kQK, cudaFuncAttributeMaxDynamicSharedMemorySize, SM_BT);
    cudaFuncSetAttribute(kPV, cudaFuncAttributeMaxDynamicSharedMemorySize, SM_BN);
    cudaFuncSetAttribute(kWd, cudaFuncAttributeMaxDynamicSharedMemorySize, SM_BT);

    // ---- one-time preprocessing (per launch) ----
    prep_w_k<<<(Dd*5*65536+1023)/1024,1024>>>(Wt, Wtc, Wu, wcat1, wcat2);
    embed_norm_k<<<TOK,256>>>(masked, embed, xsa, acat);

    for (int d=0; d<Dd; d++){
        const float* wq  = Wq  + (long)d*KE*Ee;
        const float* wd  = Wd  + (long)d*KE*KE;
        const float* wo  = Wo  + (long)d*KE*Ee;
        const float* btd = bt  + (long)d*Ee;

        // transitions: 2 fused GEMMs
        kS1<<<dim3(4,32,2),256,SM_SN>>>(xsa, wcat1+(long)d*131072, 0, acat,
                                        TOK,Ee,Ee,Ee, 0, 65536, 0, 1);
        kS2<<<dim3(4,32,1),256,SM_SN>>>(acat, wcat2+(long)d*196608, btd, xsad,
                                        TOK,Ee,768,768, 0,0,0, 0);

        // attention
        kWq<<<dim3(16,16,1),256,SM_BT>>>(xsa, wq, 0, q2,
                                         TOK,KE,Ee,Ee, 0,0,0, 0);
        kQK<<<dim3(4,32,Bb),256,SM_BT>>>(q2, xsa, 0, h,
                                         Ll*Kk,Ll,Ee,Ee, (long)Ll*Kk*Ee, (long)Ll*Ee, (long)Ll*Kk*Ll, 0);
        softmax_k<<<Bb*Ll*Kk,256>>>(h);
        kPV<<<dim3(2,32,Bb),256,SM_BN>>>(h, xsa, 0, q,
                                         Ll*Kk,Ee,Ll,Ll, (long)Ll*Kk*Ll, (long)Ll*Ee, 0, 0);

        // dense -> relu -> dense
        kWd<<<dim3(16,16,1),256,SM_BT>>>(q, wd, 0, q2,
                                         TOK,KE,KE,KE, 0,0,0, 0);
        kWo<<<dim3(4,32,1),256,SM_SN>>>(q2, wo, 0, t1,
                                        TOK,Ee,KE,KE, 0,0,0, 0);

        update_norm_k<<<TOK,256>>>(xsad, t1, xsa);
    }

    // ---- head (split-bf16 3-mma, fp32-in fp32-out) ----
    gather_k<<<Bb*LM,256>>>(maskp, xsa, lptok);

    kG1<<<dim3(16,4,1),256,SM_ST>>>(lptok, Wkc, bkc, xx1,
                                    Bb*LM, KN*Ee, Ee, Ee, 0,0,0, 0);
    kG2<<<dim3(8,4,Bb),256,SM_ST>>>(xx1, xsa, 0, sbuf,
                                    LM*KN, Ll, Ee, Ee, (long)LM*KN*Ee, (long)Ll*Ee, (long)LM*KN*Ll, 0);
    kG3<<<dim3(4,4,Bb),256,SM_SN>>>(sbuf, xsa, 0, xx,
                                    LM*KN, Ee, Ll, Ll, (long)LM*KN*Ll, (long)Ll*Ee, (long)LM*KN*Ee, 0);
    kG4<<<dim3(4,16,1),256,SM_SN>>>(xx, Wem, 0, v,
                                    Bb*LM*KN, Ee, Ee, Ee, 0,0,0, 0);
    kG5<<<dim3(500,16,1),256,SM_ST>>>(v, embed, 0, logits,
                                      Bb*LM*KN, Gg, Ee, Ee, 0,0,0, 0);

    lse_k<<<Bb*LM*KN,256>>>(logits, unmasked, maskp, lse, tval);
    final_k<<<Bb,64>>>(tval, lse, out);
}

// round 5
// speedup vs baseline: 1.4793x; 1.4793x over previous
#include <cuda_runtime.h>
#include <cuda_bf16.h>
#include <math.h>
#include <stdint.h>

// ---------------- problem constants ----------------
#define Bb 4
#define Ll 512
#define Ee 256
#define Kk 8
#define Dd 6
#define LM 64
#define KN 4
#define Gg 32000
#define KE (Kk*Ee)          // 2048
#define TOK (Bb*Ll)         // 2048

typedef __nv_bfloat16 bf;

// ---------------- scratch (static device memory; no allocations) ----------------
__device__ float g_xsa [TOK*Ee];
__device__ float g_xsad[TOK*Ee];
__device__ float g_t1  [TOK*Ee];
__device__ float g_h   [(long)Bb*Ll*Kk*Ll];          // attention logits fp32
__device__ bf    g_xsab[TOK*Ee];                     // xsa bf16 [t][e]
__device__ bf    g_xsat[Ee*TOK];                     // xsa bf16 transposed [e][t]
__device__ bf    g_acat[TOK*768];                    // [t1a | t1b | z] bf16
__device__ bf    g_q2b [TOK*KE];
__device__ bf    g_pb  [(long)Bb*Ll*Kk*Ll];          // softmax probs bf16
__device__ bf    g_yb  [TOK*KE];
__device__ bf    g_midb[TOK*KE];
// bf16 weights (prep)
__device__ bf    g_wq [(long)Dd*KE*Ee];
__device__ bf    g_wd [(long)Dd*KE*KE];
__device__ bf    g_wot[(long)Dd*Ee*KE];              // Wo^T  [n=E][k=KE]
__device__ bf    g_wc1[Dd*2*Ee*Ee];                  // [Wt^T][Wtc] as [n][k]
__device__ bf    g_wc2[Dd*Ee*768];                   // [Wtc^T|Wt|Wu] rows n, k=768
// head hi/lo bf16 splits
__device__ bf    g_ehi[(long)Gg*Ee], g_elo[(long)Gg*Ee];
__device__ bf    g_xhhi[TOK*Ee],  g_xhlo[TOK*Ee];
__device__ bf    g_xthi[Ee*TOK],  g_xtlo[Ee*TOK];
__device__ bf    g_wkhi[KN*Ee*Ee],g_wklo[KN*Ee*Ee];
__device__ bf    g_wmhi[Ee*Ee],   g_wmlo[Ee*Ee];     // Wem^T hi/lo
__device__ bf    g_lphi[Bb*LM*Ee],g_lplo[Bb*LM*Ee];
__device__ bf    g_x1hi[Bb*LM*KN*Ee], g_x1lo[Bb*LM*KN*Ee];
__device__ bf    g_shi[(long)Bb*LM*KN*Ll], g_slo[(long)Bb*LM*KN*Ll];
__device__ bf    g_xxhi[Bb*LM*KN*Ee], g_xxlo[Bb*LM*KN*Ee];
__device__ bf    g_vhi[Bb*LM*KN*Ee],  g_vlo[Bb*LM*KN*Ee];
__device__ float g_logits[(long)Bb*LM*KN*Gg];
__device__ float g_lse [Bb*LM*KN];
__device__ float g_tval[Bb*LM*KN];

// ---------------- reductions ----------------
__device__ __forceinline__ float warp_sum(float v){
    #pragma unroll
    for (int o=16;o;o>>=1) v += __shfl_xor_sync(0xffffffffu, v, o);
    return v;
}
__device__ __forceinline__ float warp_max(float v){
    #pragma unroll
    for (int o=16;o;o>>=1) v = fmaxf(v, __shfl_xor_sync(0xffffffffu, v, o));
    return v;
}
__device__ float block_sum256(float v){
    __shared__ float sh[8];
    int lane = threadIdx.x & 31, w = threadIdx.x >> 5;
    v = warp_sum(v);
    if (lane==0) sh[w] = v;
    __syncthreads();
    float r = (threadIdx.x < 8) ? sh[threadIdx.x] : 0.f;
    if (w==0){ r = warp_sum(r); if (lane==0) sh[0]=r; }
    __syncthreads();
    float out = sh[0];
    __syncthreads();
    return out;
}
__device__ float block_max256(float v){
    __shared__ float sh[8];
    int lane = threadIdx.x & 31, w = threadIdx.x >> 5;
    v = warp_max(v);
    if (lane==0) sh[w] = v;
    __syncthreads();
    float r = (threadIdx.x < 8) ? sh[threadIdx.x] : -INFINITY;
    if (w==0){ r = warp_max(r); if (lane==0) sh[0]=r; }
    __syncthreads();
    float out = sh[0];
    __syncthreads();
    return out;
}

// ---------------- bf16 / mma / cp.async helpers ----------------
__device__ __forceinline__ uint32_t pk2(float lo, float hi){
    uint32_t r;
    asm("cvt.rn.bf16x2.f32 %0, %1, %2;" : "=r"(r) : "f"(hi), "f"(lo));
    return r;
}
__device__ __forceinline__ void mma_bf16(float* d, const uint32_t* a, const uint32_t* b){
    asm volatile(
      "mma.sync.aligned.m16n8k16.row.col.f32.bf16.bf16.f32 "
      "{%0,%1,%2,%3}, {%4,%5,%6,%7}, {%8,%9}, {%0,%1,%2,%3};\n"
      : "+f"(d[0]),"+f"(d[1]),"+f"(d[2]),"+f"(d[3])
      : "r"(a[0]),"r"(a[1]),"r"(a[2]),"r"(a[3]), "r"(b[0]),"r"(b[1]));
}
__device__ __forceinline__ void cp16b(uint32_t* s, const bf* g){
    uint32_t sa = (uint32_t)__cvta_generic_to_shared(s);
    asm volatile("cp.async.ca.shared.global [%0], [%1], 16;\n" :: "r"(sa), "l"(g));
}
__device__ __forceinline__ void cp_commit(){ asm volatile("cp.async.commit_group;\n" ::); }
template<int W> __device__ __forceinline__ void cp_wait(){ asm volatile("cp.async.wait_group %0;\n" :: "n"(W)); }

// PMODE output index mapping (element index):
// 0: bz*sC + r*N + c
// 1: q2 perm  (r over TOK, c over KE)
// 2: y perm   (r over L*K per batch, c over E)
// 3: xx1 perm (r over B*LM, c over KN*E)
// 4: acat: r*768 + bz*256 + c
template<int PMODE>
__device__ __forceinline__ long out_index(int r, int c, int bz, int N, long sC){
    if (PMODE==0) return (long)bz*sC + (long)r*N + c;
    if (PMODE==1) return (((long)(r>>9))<<20) + ((long)(r&511)<<11) + c;
    if (PMODE==2) return (((long)(bz*512 + (r>>3)))<<11) + ((long)(r&7)<<8) + c;
    if (PMODE==3) return (((long)(r>>6))<<16) + ((long)(r&63)<<10) + c;
    return (long)r*768 + ((long)bz<<8) + c;
}

// ---------------- unified bf16 tensor-core GEMM ----------------
// C[M,N] = A[M,K] * B^T where A row-major [M][K] (pitch lda), B row-major [N][K] (pitch ldb).
// All GEMM inputs are bf16. Smem layout per tile: [row][kpair] uint32 words, pitch 20
// (16 data words = 32 k-elems + 4 pad): fragment LDS addresses (20*g + c4) mod 32 hit
// all 32 banks -> conflict-free. 16B cp.async fills 4-word chunks inside the data region.
// COMP: split-bf16 3-mma using separate hi/lo operand arrays.
// OUTMODE: 0 = fp32 C; 1 = bf16 Cb; 2 = hi/lo bf16 pair (Cb, Clo).
// ROLLMODE: 0 none; 2 per-batch circular row shift (+rollShift bz=0, -rollShift bz=1)
//           within 512-row groups.
template<int BM,int BN,int WM,int WN,bool RELU,bool BIAS,int PMODE,int ROLLMODE,bool COMP,int OUTMODE>
__global__ __launch_bounds__(256, 2)
void bgemm_k(const bf* __restrict__ A, const bf* __restrict__ Alo,
             const bf* __restrict__ B, const bf* __restrict__ Blo,
             const float* __restrict__ bias,
             float* __restrict__ C, bf* __restrict__ Cb, bf* __restrict__ Clo,
             int M, int N, int Kd, int lda, int ldb,
             long sA, long sB, long sC, int rollShift)
{
    constexpr int P   = 20;                 // words per smem row (16 data + 4 pad)
    constexpr int NST = COMP ? 2 : 1;
    constexpr int TA  = BM*P, TB = BN*P;
    constexpr int STG = NST*(TA+TB);
    constexpr int MI  = WM/16, NI = WN/8;
    constexpr int WCOLS = BN/WN;

    extern __shared__ uint32_t smw[];

    const int bz = blockIdx.z;
    const bf* Ap  = A + (long)bz*sA;
    const bf* Alp = COMP ? Alo + (long)bz*sA : nullptr;
    const bf* Bp  = B + (long)bz*sB;
    const bf* Blp = COMP ? Blo + (long)bz*sB : nullptr;

    int rs = 0;
    if (ROLLMODE==2) rs = (bz==0) ? rollShift : -rollShift;

    const int row0 = blockIdx.y*BM, col0 = blockIdx.x*BN;
    const int tid  = threadIdx.x;
    const int warp = tid >> 5, lane = tid & 31;
    const int wy = warp / WCOLS, wx = warp % WCOLS;
    const int g = lane >> 2, c4 = lane & 3;

    auto load_tile = [&](int kt, int st){
        uint32_t* base = smw + st*STG;
        uint32_t* Ah = base;
        uint32_t* Al = base + TA;                 // valid only if COMP
        uint32_t* Bh = base + NST*TA;
        uint32_t* Bl = Bh + TB;
        const int k0 = kt*32;
        #pragma unroll
        for (int i=0;i<BM*4/256;i++){
            int id = tid + i*256; int r = id>>2, q = id&3;
            int gr = row0 + r;
            if (ROLLMODE) gr = (gr & ~511) | ((gr - rs) & 511);
            long go = (long)gr*lda + k0 + 8*q;
            cp16b(Ah + r*P + 4*q, Ap + go);
            if (COMP) cp16b(Al + r*P + 4*q, Alp + go);
        }
        #pragma unroll
        for (int i=0;i<BN*4/256;i++){
            int id = tid + i*256; int n = id>>2, q = id&3;
            long go = (long)(col0+n)*ldb + k0 + 8*q;
            cp16b(Bh + n*P + 4*q, Bp + go);
            if (COMP) cp16b(Bl + n*P + 4*q, Blp + go);
        }
        cp_commit();
    };

    float acc[MI][NI][4];
    #pragma unroll
    for (int i=0;i<MI;i++)
        #pragma unroll
        for (int j=0;j<NI;j++)
            #pragma unroll
            for (int t=0;t<4;t++) acc[i][j][t]=0.f;

    const int nit = Kd/32;
    load_tile(0, 0);

    for (int it=0; it<nit; it++){
        if (it+1 < nit){ load_tile(it+1, (it+1)&1); cp_wait<1>(); }
        else           { cp_wait<0>(); }
        __syncthreads();

        uint32_t* base = smw + (it&1)*STG;
        uint32_t* Ah = base;
        uint32_t* Al = base + TA;
        uint32_t* Bh = base + NST*TA;
        uint32_t* Bl = Bh + TB;

        #pragma unroll
        for (int ks=0; ks<2; ks++){
            const int kb = ks*8 + c4;
            uint32_t af[MI][4], bfr[NI][2];
            uint32_t afl[COMP?MI:1][4], bfl[COMP?NI:1][2];
            #pragma unroll
            for (int mi=0; mi<MI; mi++){
                int idx = (wy*WM + mi*16 + g)*P + kb;
                af[mi][0] = Ah[idx];
                af[mi][1] = Ah[idx + 8*P];
                af[mi][2] = Ah[idx + 4];
                af[mi][3] = Ah[idx + 8*P + 4];
                if (COMP){
                    afl[mi][0] = Al[idx];
                    afl[mi][1] = Al[idx + 8*P];
                    afl[mi][2] = Al[idx + 4];
                    afl[mi][3] = Al[idx + 8*P + 4];
                }
            }
            #pragma unroll
            for (int ni=0; ni<NI; ni++){
                int idx = (wx*WN + ni*8 + g)*P + kb;
                bfr[ni][0] = Bh[idx];
                bfr[ni][1] = Bh[idx + 4];
                if (COMP){
                    bfl[ni][0] = Bl[idx];
                    bfl[ni][1] = Bl[idx + 4];
                }
            }
            #pragma unroll
            for (int mi=0; mi<MI; mi++)
                #pragma unroll
                for (int ni=0; ni<NI; ni++){
                    if (COMP){
                        mma_bf16(acc[mi][ni], afl[mi], bfr[ni]);
                        mma_bf16(acc[mi][ni], af[mi], bfl[ni]);
                    }
                    mma_bf16(acc[mi][ni], af[mi], bfr[ni]);
                }
        }
        __syncthreads();
    }

    // ---- epilogue ----
    #pragma unroll
    for (int mi=0; mi<MI; mi++){
        #pragma unroll
        for (int half=0; half<2; half++){
            int r = row0 + wy*WM + mi*16 + g + half*8;
            #pragma unroll
            for (int ni=0; ni<NI; ni++){
                int cc = col0 + wx*WN + ni*8 + 2*c4;
                float v0 = acc[mi][ni][half*2+0];
                float v1 = acc[mi][ni][half*2+1];
                if (BIAS){ v0 += bias[cc]; v1 += bias[cc+1]; }
                if (RELU){ v0 = fmaxf(v0,0.f); v1 = fmaxf(v1,0.f); }
                long idx = out_index<PMODE>(r, cc, bz, N, sC);
                if (OUTMODE==0){
                    *(float2*)(C + idx) = make_float2(v0, v1);
                } else if (OUTMODE==1){
                    *(uint32_t*)(Cb + idx) = pk2(v0, v1);
                } else {
                    bf h0 = __float2bfloat16(v0);
                    bf h1 = __float2bfloat16(v1);
                    union { __nv_bfloat162 b; uint32_t u; } cu;
                    cu.b = __halves2bfloat162(h0, h1);
                    *(uint32_t*)(Cb + idx)  = cu.u;
                    *(uint32_t*)(Clo + idx) = pk2(v0 - __bfloat162float(h0),
                                                  v1 - __bfloat162float(h1));
                }
            }
        }
    }
}

// ---------------- prep kernels ----------------
// transition concat blocks (bf16, [n][k] layouts)
__global__ void prep_w_k(const float* __restrict__ Wt, const float* __restrict__ Wtc,
                         const float* __restrict__ Wu,
                         bf* __restrict__ wc1, bf* __restrict__ wc2)
{
    long idx = (long)blockIdx.x*1024 + threadIdx.x;
    if (idx >= (long)Dd*5*65536) return;
    int d = idx / (5*65536);
    int r = idx % (5*65536);
    int which = r / 65536;
    int e = r % 65536;
    int n = e >> 8, k = e & 255;
    long wb = (long)d*65536;
    if      (which==0) wc1[(long)d*131072 +         n*256+k] = __float2bfloat16(Wt [wb + (long)k*256 + n]);
    else if (which==1) wc1[(long)d*131072 + 65536 + n*256+k] = __float2bfloat16(Wtc[wb + (long)n*256 + k]);
    else if (which==2) wc2[(long)d*196608 + (long)n*768 +       k] = __float2bfloat16(Wtc[wb + (long)k*256 + n]);
    else if (which==3) wc2[(long)d*196608 + (long)n*768 + 256 + k] = __float2bfloat16(Wt [wb + (long)n*256 + k]);
    else               wc2[(long)d*196608 + (long)n*768 + 512 + k] = __float2bfloat16(Wu [wb + (long)n*256 + k]);
}

// fp32 -> bf16 copy (2 elems/thread)
__global__ void conv_b(const float* __restrict__ in, bf* __restrict__ outp, long n2){
    long i = (long)blockIdx.x*256 + threadIdx.x;
    if (i >= n2) return;
    float2 v = ((const float2*)in)[i];
    ((uint32_t*)outp)[i] = pk2(v.x, v.y);
}

// fp32 -> bf16 hi/lo split (2 elems/thread)
__global__ void split_b(const float* __restrict__ in, bf* __restrict__ hi,
                        bf* __restrict__ lo, long n2){
    long i = (long)blockIdx.x*256 + threadIdx.x;
    if (i >= n2) return;
    float2 v = ((const float2*)in)[i];
    bf hx = __float2bfloat16(v.x), hy = __float2bfloat16(v.y);
    union { __nv_bfloat162 b; uint32_t u; } cu;
    cu.b = __halves2bfloat162(hx, hy);
    ((uint32_t*)hi)[i] = cu.u;
    ((uint32_t*)lo)[i] = pk2(v.x - __bfloat162float(hx), v.y - __bfloat162float(hy));
}

// fp32 [R][C] -> bf16 [C][R] transpose (batched)
__global__ void t32_f2b(const float* __restrict__ src, bf* __restrict__ dst, int R, int C){
    __shared__ bf t[32][33];
    const float* s = src + (long)blockIdx.z*R*C;
    bf* d = dst + (long)blockIdx.z*R*C;
    int r0 = blockIdx.x*32, c0 = blockIdx.y*32;
    int tx = threadIdx.x & 31, ty = threadIdx.x >> 5;
    #pragma unroll
    for (int i=0;i<4;i++) t[ty+8*i][tx] = __float2bfloat16(s[(long)(r0+ty+8*i)*C + c0+tx]);
    __syncthreads();
    #pragma unroll
    for (int i=0;i<4;i++) d[(long)(c0+ty+8*i)*R + r0+tx] = t[tx][ty+8*i];
}

// fp32 [R][C] -> bf16 hi/lo [C][R] transpose
__global__ void t32_f2b2(const float* __restrict__ src, bf* __restrict__ dh,
                         bf* __restrict__ dl, int R, int C){
    __shared__ bf th[32][33];
    __shared__ bf tl[32][33];
    int r0 = blockIdx.x*32, c0 = blockIdx.y*32;
    int tx = threadIdx.x & 31, ty = threadIdx.x >> 5;
    #pragma unroll
    for (int i=0;i<4;i++){
        float v = src[(long)(r0+ty+8*i)*C + c0+tx];
        bf h = __float2bfloat16(v);
        th[ty+8*i][tx] = h;
        tl[ty+8*i][tx] = __float2bfloat16(v - __bfloat162float(h));
    }
    __syncthreads();
    #pragma unroll
    for (int i=0;i<4;i++){
        dh[(long)(c0+ty+8*i)*R + r0+tx] = th[tx][ty+8*i];
        dl[(long)(c0+ty+8*i)*R + r0+tx] = tl[tx][ty+8*i];
    }
}

// bf16 [R][C] -> bf16 [C][R]
__global__ void transpose_b(const bf* __restrict__ src, bf* __restrict__ dst, int R, int C){
    __shared__ bf t[32][33];
    int r0 = blockIdx.x*32, c0 = blockIdx.y*32;
    int tx = threadIdx.x & 31, ty = threadIdx.x >> 5;
    #pragma unroll
    for (int i=0;i<4;i++) t[ty+8*i][tx] = src[(long)(r0+ty+8*i)*C + c0+tx];
    __syncthreads();
    #pragma unroll
    for (int i=0;i<4;i++) dst[(long)(c0+ty+8*i)*R + r0+tx] = t[tx][ty+8*i];
}

// ---------------- elementwise / reduction kernels ----------------
__global__ void embed_norm_k(const int* __restrict__ masked, const float* __restrict__ embed,
                             float* __restrict__ xsa, bf* __restrict__ xsab,
                             bf* __restrict__ acat)
{
    int t = blockIdx.x;
    int g = masked[t];
    float v = embed[(long)g*Ee + threadIdx.x];
    float mean = block_sum256(v) * (1.f/Ee);
    float d = v - mean;
    float var = block_sum256(d*d) * (1.f/(Ee-1));
    float o = v / (1.f + sqrtf(var));
    xsa [(long)t*Ee + threadIdx.x] = o;
    bf ob = __float2bfloat16(o);
    xsab[(long)t*Ee + threadIdx.x] = ob;
    acat[(long)t*768 + 512 + threadIdx.x] = ob;
}

// softmax over rows of 512 (1/16 scale); fp32 in, bf16 probs out
__global__ void softmax_k(const float* __restrict__ h, bf* __restrict__ pb){
    const float* row = h + (long)blockIdx.x * Ll;
    float2 v = ((const float2*)row)[threadIdx.x];
    float v0 = v.x * 0.0625f, v1 = v.y * 0.0625f;
    float mx = block_max256(fmaxf(v0, v1));
    float e0 = expf(v0 - mx), e1 = expf(v1 - mx);
    float s = block_sum256(e0 + e1);
    float inv = 1.f / s;
    ((uint32_t*)pb)[(long)blockIdx.x*256 + threadIdx.x] = pk2(e0*inv, e1*inv);
}

__global__ void update_norm_k(const float* __restrict__ xsad, const float* __restrict__ xid,
                              float* __restrict__ xsa, bf* __restrict__ xsab)
{
    long idx = (long)blockIdx.x*Ee + threadIdx.x;
    float u = xsad[idx] + xid[idx];
    float mean = block_sum256(u) * (1.f/Ee);
    float d = u - mean;
    float var = block_sum256(d*d) * (1.f/(Ee-1));
    float un = u / (1.f + sqrtf(var));
    float w = xsa[idx] + 0.05f * un;
    float mean2 = block_sum256(w) * (1.f/Ee);
    float d2 = w - mean2;
    float var2 = block_sum256(d2*d2) * (1.f/(Ee-1));
    float o = w / (1.f + sqrtf(var2));
    xsa[idx]  = o;
    xsab[idx] = __float2bfloat16(o);
}

__global__ void gather_split_k(const int* __restrict__ mask, const float* __restrict__ xsa,
                               bf* __restrict__ hi, bf* __restrict__ lo){
    int r = blockIdx.x; int b = r >> 6; int p = mask[r];
    float v = xsa[(long)(b*Ll + p)*Ee + threadIdx.x];
    bf h = __float2bfloat16(v);
    hi[(long)r*Ee + threadIdx.x] = h;
    lo[(long)r*Ee + threadIdx.x] = __float2bfloat16(v - __bfloat162float(h));
}

__global__ void lse_k(const float* __restrict__ logits, const int* __restrict__ unmasked,
                      const int* __restrict__ mask, float* __restrict__ lse, float* __restrict__ tval)
{
    int row = blockIdx.x;
    const float* p = logits + (long)row * Gg;
    float m = -INFINITY;
    for (int g = threadIdx.x; g < Gg; g += 256) m = fmaxf(m, p[g]);
    m = block_max256(m);
    float s = 0.f;
    for (int g = threadIdx.x; g < Gg; g += 256) s += expf(p[g] - m);
    s = block_sum256(s);
    if (threadIdx.x == 0){
        lse[row] = m + logf(s);
        int b = row >> 8, n = row & 255, j = n >> 2;
        int tg = unmasked[b*Ll + mask[b*LM + j]];
        tval[row] = p[tg];
    }
}

__global__ void final_k(const float* __restrict__ tval, const float* __restrict__ lse,
                        float* __restrict__ out)
{
    int b = blockIdx.x, j = threadIdx.x;   // 64 threads
    float a[KN]; float m = -INFINITY;
    #pragma unroll
    for (int kn=0;kn<KN;kn++){
        int r = ((b << 6) + j) * KN + kn;
        a[kn] = tval[r] - lse[r];
        m = fmaxf(m, a[kn]);
    }
    float s = 0.f;
    #pragma unroll
    for (int kn=0;kn<KN;kn++) s += expf(a[kn] - m);
    float cent = m + logf(s) - 1.3862943611198906f;   // - log(4)
    __shared__ float sh[64];
    sh[j] = cent; __syncthreads();
    for (int o=32;o;o>>=1){ if (j<o) sh[j] += sh[j+o]; __syncthreads(); }
    if (j==0) out[b] = -sh[0] / (float)LM;
}

// ---------------- host orchestration ----------------
#define GSYM(p, s) cudaGetSymbolAddress((void**)&p, s)

extern "C" void kernel_launch(void* const* d_in, const int* in_sizes, int n_in,
                              void* d_out, int out_size)
{
    (void)in_sizes; (void)n_in; (void)out_size;
    const int*   masked   = (const int*)  d_in[0];
    const int*   unmasked = (const int*)  d_in[1];
    const int*   maskp    = (const int*)  d_in[2];
    const float* embed    = (const float*)d_in[3];
    const float* Wt       = (const float*)d_in[4];
    const float* bt       = (const float*)d_in[5];
    const float* Wtc      = (const float*)d_in[6];
    const float* Wq       = (const float*)d_in[7];
    const float* Wd       = (const float*)d_in[8];
    const float* Wo       = (const float*)d_in[9];
    const float* Wu       = (const float*)d_in[10];
    const float* Wem      = (const float*)d_in[11];
    const float* Wkc      = (const float*)d_in[12];
    const float* bkc      = (const float*)d_in[13];
    float* out = (float*)d_out;

    float *xsa,*xsad,*t1,*h,*logits,*lse,*tval;
    bf *xsab,*xsat,*acat,*q2b,*pb,*yb,*midb;
    bf *wq,*wd,*wot,*wc1,*wc2;
    bf *ehi,*elo,*xhhi,*xhlo,*xthi,*xtlo,*wkhi,*wklo,*wmhi,*wmlo;
    bf *lphi,*lplo,*x1hi,*x1lo,*shi,*slo,*xxhi,*xxlo,*vhi,*vlo;
    GSYM(xsa,g_xsa); GSYM(xsad,g_xsad); GSYM(t1,g_t1); GSYM(h,g_h);
    GSYM(logits,g_logits); GSYM(lse,g_lse); GSYM(tval,g_tval);
    GSYM(xsab,g_xsab); GSYM(xsat,g_xsat); GSYM(acat,g_acat);
    GSYM(q2b,g_q2b); GSYM(pb,g_pb); GSYM(yb,g_yb); GSYM(midb,g_midb);
    GSYM(wq,g_wq); GSYM(wd,g_wd); GSYM(wot,g_wot); GSYM(wc1,g_wc1); GSYM(wc2,g_wc2);
    GSYM(ehi,g_ehi); GSYM(elo,g_elo); GSYM(xhhi,g_xhhi); GSYM(xhlo,g_xhlo);
    GSYM(xthi,g_xthi); GSYM(xtlo,g_xtlo); GSYM(wkhi,g_wkhi); GSYM(wklo,g_wklo);
    GSYM(wmhi,g_wmhi); GSYM(wmlo,g_wmlo); GSYM(lphi,g_lphi); GSYM(lplo,g_lplo);
    GSYM(x1hi,g_x1hi); GSYM(x1lo,g_x1lo); GSYM(shi,g_shi); GSYM(slo,g_slo);
    GSYM(xxhi,g_xxhi); GSYM(xxlo,g_xxlo); GSYM(vhi,g_vhi); GSYM(vlo,g_vlo);

    // kernel instantiations
    auto kS1 = bgemm_k<64,64,32,16,true ,false,4,2,false,1>;   // transitions stage1 -> acat bf16
    auto kS2 = bgemm_k<64,64,32,16,false,true ,0,0,false,0>;   // stage2 -> xsad fp32
    auto kWq = bgemm_k<128,128,64,32,false,false,1,0,false,1>; // q -> q2b (perm)
    auto kQK = bgemm_k<128,128,64,32,false,false,0,0,false,0>; // scores -> h fp32
    auto kPV = bgemm_k<128,128,64,32,false,false,2,0,false,1>; // probs@V -> yb (perm)
    auto kWd = bgemm_k<128,128,64,32,true ,false,0,0,false,1>; // dense+relu -> midb
    auto kWo = bgemm_k<64,64,32,16,false,false,0,0,false,0>;   // -> t1 fp32
    auto kG1 = bgemm_k<64,64,32,16,false,true ,3,0,true ,2>;   // kchoice -> xx1 hi/lo (perm)
    auto kG2 = bgemm_k<64,64,32,16,false,false,0,0,true ,2>;   // -> s hi/lo
    auto kG3 = bgemm_k<64,64,32,16,false,false,0,0,true ,2>;   // -> xx hi/lo
    auto kG4 = bgemm_k<64,64,32,16,false,false,0,0,true ,2>;   // -> v hi/lo
    auto kG5 = bgemm_k<64,64,32,16,false,false,0,0,true ,0>;   // logits fp32

    constexpr int SM_BIG = 2*1*(128+128)*20*4;   // 40960 B
    constexpr int SM_SML = 2*1*(64+64)*20*4;     // 20480 B
    constexpr int SM_CMP = 2*2*(64+64)*20*4;     // 40960 B

    // ---- prep: bf16 weights (per launch; graph-captured) ----
    prep_w_k<<<(Dd*5*65536+1023)/1024,1024>>>(Wt, Wtc, Wu, wc1, wc2);
    conv_b<<<((long)Dd*KE*Ee/2+255)/256,256>>>(Wq, wq, (long)Dd*KE*Ee/2);
    conv_b<<<((long)Dd*KE*KE/2+255)/256,256>>>(Wd, wd, (long)Dd*KE*KE/2);
    t32_f2b<<<dim3(KE/32,Ee/32,Dd),256>>>(Wo, wot, KE, Ee);
    split_b<<<((long)Gg*Ee/2+255)/256,256>>>(embed, ehi, elo, (long)Gg*Ee/2);
    split_b<<<(KN*Ee*Ee/2+255)/256,256>>>(Wkc, wkhi, wklo, KN*Ee*Ee/2);
    t32_f2b2<<<dim3(Ee/32,Ee/32,1),256>>>(Wem, wmhi, wmlo, Ee, Ee);

    embed_norm_k<<<TOK,256>>>(masked, embed, xsa, xsab, acat);

    for (int d=0; d<Dd; d++){
        // xsa_t for PV (current xsa)
        transpose_b<<<dim3(TOK/32,Ee/32),256>>>(xsab, xsat, TOK, Ee);

        // transitions
        kS1<<<dim3(4,32,2),256,SM_SML>>>(xsab,0, wc1+(long)d*131072,0, 0, 0,acat,0,
                                         TOK,Ee,Ee, Ee,Ee, 0, 65536, 0, 1);
        kS2<<<dim3(4,32,1),256,SM_SML>>>(acat,0, wc2+(long)d*196608,0, bt+(long)d*Ee, xsad,0,0,
                                         TOK,Ee,768, 768,768, 0,0,0, 0);

        // attention
        kWq<<<dim3(16,16,1),256,SM_BIG>>>(xsab,0, wq+(long)d*KE*Ee,0, 0, 0,q2b,0,
                                          TOK,KE,Ee, Ee,Ee, 0,0,0, 0);
        kQK<<<dim3(4,32,Bb),256,SM_BIG>>>(q2b,0, xsab,0, 0, h,0,0,
                                          Ll*Kk,Ll,Ee, Ee,Ee,
                                          (long)Ll*Kk*Ee, (long)Ll*Ee, (long)Ll*Kk*Ll, 0);
        softmax_k<<<Bb*Ll*Kk,256>>>(h, pb);
        kPV<<<dim3(2,32,Bb),256,SM_BIG>>>(pb,0, xsat,0, 0, 0,yb,0,
                                          Ll*Kk,Ee,Ll, Ll,TOK,
                                          (long)Ll*Kk*Ll, (long)Ll, 0, 0);

        // dense -> relu -> dense
        kWd<<<dim3(16,16,1),256,SM_BIG>>>(yb,0, wd+(long)d*KE*KE,0, 0, 0,midb,0,
                                          TOK,KE,KE, KE,KE, 0,0,0, 0);
        kWo<<<dim3(4,32,1),256,SM_SML>>>(midb,0, wot+(long)d*Ee*KE,0, 0, t1,0,0,
                                         TOK,Ee,KE, KE,KE, 0,0,0, 0);

        update_norm_k<<<TOK,256>>>(xsad, t1, xsa, xsab);
    }

    // ---- head (split-bf16 3-mma) ----
    split_b<<<(TOK*Ee/2+255)/256,256>>>(xsa, xhhi, xhlo, TOK*Ee/2);
    transpose_b<<<dim3(TOK/32,Ee/32),256>>>(xhhi, xthi, TOK, Ee);
    transpose_b<<<dim3(TOK/32,Ee/32),256>>>(xhlo, xtlo, TOK, Ee);
    gather_split_k<<<Bb*LM,256>>>(maskp, xsa, lphi, lplo);

    kG1<<<dim3(16,4,1),256,SM_CMP>>>(lphi,lplo, wkhi,wklo, bkc, 0,x1hi,x1lo,
                                     Bb*LM, KN*Ee, Ee, Ee,Ee, 0,0,0, 0);
    kG2<<<dim3(8,4,Bb),256,SM_CMP>>>(x1hi,x1lo, xhhi,xhlo, 0, 0,shi,slo,
                                     LM*KN, Ll, Ee, Ee,Ee,
                                     (long)LM*KN*Ee, (long)Ll*Ee, (long)LM*KN*Ll, 0);
    kG3<<<dim3(4,4,Bb),256,SM_CMP>>>(shi,slo, xthi,xtlo, 0, 0,xxhi,xxlo,
                                     LM*KN, Ee, Ll, Ll,TOK,
                                     (long)LM*KN*Ll, (long)Ll, (long)LM*KN*Ee, 0);
    kG4<<<dim3(4,16,1),256,SM_CMP>>>(xxhi,xxlo, wmhi,wmlo, 0, 0,vhi,vlo,
                                     Bb*LM*KN, Ee, Ee, Ee,Ee, 0,0,0, 0);
    kG5<<<dim3(500,16,1),256,SM_CMP>>>(vhi,vlo, ehi,elo, 0, logits,0,0,
                                       Bb*LM*KN, Gg, Ee, Ee,Ee, 0,0,0, 0);

    lse_k<<<Bb*LM*KN,256>>>(logits, unmasked, maskp, lse, tval);
    final_k<<<Bb,64>>>(tval, lse, out);
}

// round 6
// speedup vs baseline: 1.5560x; 1.0518x over previous
#include <cuda_runtime.h>
#include <cuda_bf16.h>
#include <math.h>
#include <stdint.h>

// ---------------- problem constants ----------------
#define Bb 4
#define Ll 512
#define Ee 256
#define Kk 8
#define Dd 6
#define LM 64
#define KN 4
#define Gg 32000
#define KE (Kk*Ee)          // 2048
#define TOK (Bb*Ll)         // 2048

typedef __nv_bfloat16 bf;

// ---------------- scratch (static device memory; no allocations) ----------------
__device__ float g_xsa [TOK*Ee];
__device__ float g_xsad[TOK*Ee];
__device__ float g_t1p [4L*TOK*Ee];                  // kWo split-K partials
__device__ bf    g_hb  [(long)Bb*Ll*Kk*Ll];          // attention logits bf16
__device__ bf    g_xsab[TOK*Ee];                     // xsa bf16 [t][e]
__device__ bf    g_xsat[Ee*TOK];                     // xsa bf16 transposed [e][t]
__device__ bf    g_acat[TOK*768];                    // [t1a | t1b | z] bf16
__device__ bf    g_q2b [TOK*KE];
__device__ bf    g_pb  [(long)Bb*Ll*Kk*Ll];          // softmax probs bf16
__device__ bf    g_yb  [TOK*KE];
__device__ bf    g_midb[TOK*KE];
// bf16 weights (prep)
__device__ bf    g_wq [(long)Dd*KE*Ee];
__device__ bf    g_wd [(long)Dd*KE*KE];
__device__ bf    g_wot[(long)Dd*Ee*KE];              // Wo^T  [n=E][k=KE]
__device__ bf    g_wc1[Dd*2*Ee*Ee];                  // [Wt^T][Wtc] as [n][k]
__device__ bf    g_wc2[Dd*Ee*768];                   // [Wtc^T|Wt|Wu] rows n, k=768
// head hi/lo bf16 splits (hi of xsa == xsab/xsat)
__device__ bf    g_ehi[(long)Gg*Ee], g_elo[(long)Gg*Ee];
__device__ bf    g_xhlo[TOK*Ee];
__device__ bf    g_xtlo[Ee*TOK];
__device__ bf    g_wkhi[KN*Ee*Ee],g_wklo[KN*Ee*Ee];
__device__ bf    g_wmhi[Ee*Ee],   g_wmlo[Ee*Ee];     // Wem^T hi/lo
__device__ bf    g_lphi[Bb*LM*Ee],g_lplo[Bb*LM*Ee];
__device__ bf    g_x1hi[Bb*LM*KN*Ee], g_x1lo[Bb*LM*KN*Ee];
__device__ bf    g_shi[(long)Bb*LM*KN*Ll], g_slo[(long)Bb*LM*KN*Ll];
__device__ bf    g_xxhi[Bb*LM*KN*Ee], g_xxlo[Bb*LM*KN*Ee];
__device__ bf    g_vhi[Bb*LM*KN*Ee],  g_vlo[Bb*LM*KN*Ee];
__device__ float g_logits[(long)Bb*LM*KN*Gg];
__device__ float g_lse [Bb*LM*KN];
__device__ float g_tval[Bb*LM*KN];

// ---------------- reductions ----------------
__device__ __forceinline__ float warp_sum(float v){
    #pragma unroll
    for (int o=16;o;o>>=1) v += __shfl_xor_sync(0xffffffffu, v, o);
    return v;
}
__device__ __forceinline__ float warp_max(float v){
    #pragma unroll
    for (int o=16;o;o>>=1) v = fmaxf(v, __shfl_xor_sync(0xffffffffu, v, o));
    return v;
}
__device__ float block_sum256(float v){
    __shared__ float sh[8];
    int lane = threadIdx.x & 31, w = threadIdx.x >> 5;
    v = warp_sum(v);
    if (lane==0) sh[w] = v;
    __syncthreads();
    float r = (threadIdx.x < 8) ? sh[threadIdx.x] : 0.f;
    if (w==0){ r = warp_sum(r); if (lane==0) sh[0]=r; }
    __syncthreads();
    float out = sh[0];
    __syncthreads();
    return out;
}
__device__ float block_max256(float v){
    __shared__ float sh[8];
    int lane = threadIdx.x & 31, w = threadIdx.x >> 5;
    v = warp_max(v);
    if (lane==0) sh[w] = v;
    __syncthreads();
    float r = (threadIdx.x < 8) ? sh[threadIdx.x] : -INFINITY;
    if (w==0){ r = warp_max(r); if (lane==0) sh[0]=r; }
    __syncthreads();
    float out = sh[0];
    __syncthreads();
    return out;
}

// ---------------- bf16 / mma / cp.async helpers ----------------
__device__ __forceinline__ uint32_t pk2(float lo, float hi){
    uint32_t r;
    asm("cvt.rn.bf16x2.f32 %0, %1, %2;" : "=r"(r) : "f"(hi), "f"(lo));
    return r;
}
__device__ __forceinline__ void mma_bf16(float* d, const uint32_t* a, const uint32_t* b){
    asm volatile(
      "mma.sync.aligned.m16n8k16.row.col.f32.bf16.bf16.f32 "
      "{%0,%1,%2,%3}, {%4,%5,%6,%7}, {%8,%9}, {%0,%1,%2,%3};\n"
      : "+f"(d[0]),"+f"(d[1]),"+f"(d[2]),"+f"(d[3])
      : "r"(a[0]),"r"(a[1]),"r"(a[2]),"r"(a[3]), "r"(b[0]),"r"(b[1]));
}
__device__ __forceinline__ void cp16b(uint32_t* s, const bf* g){
    uint32_t sa = (uint32_t)__cvta_generic_to_shared(s);
    asm volatile("cp.async.ca.shared.global [%0], [%1], 16;\n" :: "r"(sa), "l"(g));
}
__device__ __forceinline__ void cp_commit(){ asm volatile("cp.async.commit_group;\n" ::); }
template<int W> __device__ __forceinline__ void cp_wait(){ asm volatile("cp.async.wait_group %0;\n" :: "n"(W)); }

// PMODE output index mapping (element index):
// 0: bz*sC + r*N + c
// 1: q2 perm  (r over TOK, c over KE)
// 2: y perm   (r over L*K per batch, c over E)
// 3: xx1 perm (r over B*LM, c over KN*E)
// 4: acat: r*768 + bz*256 + c
template<int PMODE>
__device__ __forceinline__ long out_index(int r, int c, int bz, int N, long sC){
    if (PMODE==0) return (long)bz*sC + (long)r*N + c;
    if (PMODE==1) return (((long)(r>>9))<<20) + ((long)(r&511)<<11) + c;
    if (PMODE==2) return (((long)(bz*512 + (r>>3)))<<11) + ((long)(r&7)<<8) + c;
    if (PMODE==3) return (((long)(r>>6))<<16) + ((long)(r&63)<<10) + c;
    return (long)r*768 + ((long)bz<<8) + c;
}

// ---------------- unified bf16 tensor-core GEMM (3-stage pipeline) ----------------
// C[M,N] = A[M,K] * B^T, A row-major [M][K] (pitch lda), B row-major [N][K] (pitch ldb).
// Smem rows pitch 20 words (16 data + 4 pad) -> conflict-free fragment LDS.
// COMP: split-bf16 3-mma with separate hi/lo arrays.
// OUTMODE: 0 fp32 C; 1 bf16 Cb; 2 hi/lo pair (Cb, Clo).
// ROLLMODE: 0 none; 2 per-batch circular row shift within 512-row groups.
template<int BM,int BN,int WM,int WN,bool RELU,bool BIAS,int PMODE,int ROLLMODE,bool COMP,int OUTMODE>
__global__ __launch_bounds__(256, 2)
void bgemm_k(const bf* __restrict__ A, const bf* __restrict__ Alo,
             const bf* __restrict__ B, const bf* __restrict__ Blo,
             const float* __restrict__ bias,
             float* __restrict__ C, bf* __restrict__ Cb, bf* __restrict__ Clo,
             int M, int N, int Kd, int lda, int ldb,
             long sA, long sB, long sC, int rollShift)
{
    constexpr int P   = 20;
    constexpr int NST = COMP ? 2 : 1;
    constexpr int TA  = BM*P, TB = BN*P;
    constexpr int STG = NST*(TA+TB);
    constexpr int MI  = WM/16, NI = WN/8;
    constexpr int WCOLS = BN/WN;

    extern __shared__ uint32_t smw[];

    const int bz = blockIdx.z;
    const bf* Ap  = A + (long)bz*sA;
    const bf* Alp = COMP ? Alo + (long)bz*sA : nullptr;
    const bf* Bp  = B + (long)bz*sB;
    const bf* Blp = COMP ? Blo + (long)bz*sB : nullptr;

    int rs = 0;
    if (ROLLMODE==2) rs = (bz==0) ? rollShift : -rollShift;

    const int row0 = blockIdx.y*BM, col0 = blockIdx.x*BN;
    const int tid  = threadIdx.x;
    const int warp = tid >> 5, lane = tid & 31;
    const int wy = warp / WCOLS, wx = warp % WCOLS;
    const int g = lane >> 2, c4 = lane & 3;

    auto load_tile = [&](int kt, int st){
        uint32_t* base = smw + st*STG;
        uint32_t* Ah = base;
        uint32_t* Al = base + TA;
        uint32_t* Bh = base + NST*TA;
        uint32_t* Bl = Bh + TB;
        const int k0 = kt*32;
        #pragma unroll
        for (int i=0;i<BM*4/256;i++){
            int id = tid + i*256; int r = id>>2, q = id&3;
            int gr = row0 + r;
            if (ROLLMODE) gr = (gr & ~511) | ((gr - rs) & 511);
            long go = (long)gr*lda + k0 + 8*q;
            cp16b(Ah + r*P + 4*q, Ap + go);
            if (COMP) cp16b(Al + r*P + 4*q, Alp + go);
        }
        #pragma unroll
        for (int i=0;i<BN*4/256;i++){
            int id = tid + i*256; int n = id>>2, q = id&3;
            long go = (long)(col0+n)*ldb + k0 + 8*q;
            cp16b(Bh + n*P + 4*q, Bp + go);
            if (COMP) cp16b(Bl + n*P + 4*q, Blp + go);
        }
        cp_commit();
    };

    float acc[MI][NI][4];
    #pragma unroll
    for (int i=0;i<MI;i++)
        #pragma unroll
        for (int j=0;j<NI;j++)
            #pragma unroll
            for (int t=0;t<4;t++) acc[i][j][t]=0.f;

    const int nit = Kd/32;
    load_tile(0, 0);
    load_tile(1, 1);

    int st = 0;
    for (int it=0; it<nit; it++){
        if (it+2 < nit){ load_tile(it+2, (it+2)%3); cp_wait<2>(); }
        else if (it+1 < nit){ cp_wait<1>(); }
        else { cp_wait<0>(); }
        __syncthreads();

        uint32_t* base = smw + st*STG;
        uint32_t* Ah = base;
        uint32_t* Al = base + TA;
        uint32_t* Bh = base + NST*TA;
        uint32_t* Bl = Bh + TB;

        #pragma unroll
        for (int ks=0; ks<2; ks++){
            const int kb = ks*8 + c4;
            uint32_t af[MI][4], bfr[NI][2];
            uint32_t afl[COMP?MI:1][4], bfl[COMP?NI:1][2];
            #pragma unroll
            for (int mi=0; mi<MI; mi++){
                int idx = (wy*WM + mi*16 + g)*P + kb;
                af[mi][0] = Ah[idx];
                af[mi][1] = Ah[idx + 8*P];
                af[mi][2] = Ah[idx + 4];
                af[mi][3] = Ah[idx + 8*P + 4];
                if (COMP){
                    afl[mi][0] = Al[idx];
                    afl[mi][1] = Al[idx + 8*P];
                    afl[mi][2] = Al[idx + 4];
                    afl[mi][3] = Al[idx + 8*P + 4];
                }
            }
            #pragma unroll
            for (int ni=0; ni<NI; ni++){
                int idx = (wx*WN + ni*8 + g)*P + kb;
                bfr[ni][0] = Bh[idx];
                bfr[ni][1] = Bh[idx + 4];
                if (COMP){
                    bfl[ni][0] = Bl[idx];
                    bfl[ni][1] = Bl[idx + 4];
                }
            }
            #pragma unroll
            for (int mi=0; mi<MI; mi++)
                #pragma unroll
                for (int ni=0; ni<NI; ni++){
                    if (COMP){
                        mma_bf16(acc[mi][ni], afl[mi], bfr[ni]);
                        mma_bf16(acc[mi][ni], af[mi], bfl[ni]);
                    }
                    mma_bf16(acc[mi][ni], af[mi], bfr[ni]);
                }
        }
        __syncthreads();
        st = (st==2) ? 0 : st+1;
    }

    // ---- epilogue ----
    #pragma unroll
    for (int mi=0; mi<MI; mi++){
        #pragma unroll
        for (int half=0; half<2; half++){
            int r = row0 + wy*WM + mi*16 + g + half*8;
            #pragma unroll
            for (int ni=0; ni<NI; ni++){
                int cc = col0 + wx*WN + ni*8 + 2*c4;
                float v0 = acc[mi][ni][half*2+0];
                float v1 = acc[mi][ni][half*2+1];
                if (BIAS){ v0 += bias[cc]; v1 += bias[cc+1]; }
                if (RELU){ v0 = fmaxf(v0,0.f); v1 = fmaxf(v1,0.f); }
                long idx = out_index<PMODE>(r, cc, bz, N, sC);
                if (OUTMODE==0){
                    *(float2*)(C + idx) = make_float2(v0, v1);
                } else if (OUTMODE==1){
                    *(uint32_t*)(Cb + idx) = pk2(v0, v1);
                } else {
                    bf h0 = __float2bfloat16(v0);
                    bf h1 = __float2bfloat16(v1);
                    union { __nv_bfloat162 b; uint32_t u; } cu;
                    cu.b = __halves2bfloat162(h0, h1);
                    *(uint32_t*)(Cb + idx)  = cu.u;
                    *(uint32_t*)(Clo + idx) = pk2(v0 - __bfloat162float(h0),
                                                  v1 - __bfloat162float(h1));
                }
            }
        }
    }
}

// ---------------- prep kernels ----------------
__global__ void prep_w_k(const float* __restrict__ Wt, const float* __restrict__ Wtc,
                         const float* __restrict__ Wu,
                         bf* __restrict__ wc1, bf* __restrict__ wc2)
{
    long idx = (long)blockIdx.x*1024 + threadIdx.x;
    if (idx >= (long)Dd*5*65536) return;
    int d = idx / (5*65536);
    int r = idx % (5*65536);
    int which = r / 65536;
    int e = r % 65536;
    int n = e >> 8, k = e & 255;
    long wb = (long)d*65536;
    if      (which==0) wc1[(long)d*131072 +         n*256+k] = __float2bfloat16(Wt [wb + (long)k*256 + n]);
    else if (which==1) wc1[(long)d*131072 + 65536 + n*256+k] = __float2bfloat16(Wtc[wb + (long)n*256 + k]);
    else if (which==2) wc2[(long)d*196608 + (long)n*768 +       k] = __float2bfloat16(Wtc[wb + (long)k*256 + n]);
    else if (which==3) wc2[(long)d*196608 + (long)n*768 + 256 + k] = __float2bfloat16(Wt [wb + (long)n*256 + k]);
    else               wc2[(long)d*196608 + (long)n*768 + 512 + k] = __float2bfloat16(Wu [wb + (long)n*256 + k]);
}

// fp32 -> bf16 copy (4 elems/thread)
__global__ void conv_b4(const float4* __restrict__ in, uint2* __restrict__ outp, long n4){
    long i = (long)blockIdx.x*256 + threadIdx.x;
    if (i >= n4) return;
    float4 v = in[i];
    uint2 o; o.x = pk2(v.x, v.y); o.y = pk2(v.z, v.w);
    outp[i] = o;
}

// fp32 -> bf16 hi/lo split (4 elems/thread)
__global__ void split_b4(const float4* __restrict__ in, uint2* __restrict__ hi,
                         uint2* __restrict__ lo, long n4){
    long i = (long)blockIdx.x*256 + threadIdx.x;
    if (i >= n4) return;
    float4 v = in[i];
    bf hx=__float2bfloat16(v.x), hy=__float2bfloat16(v.y);
    bf hz=__float2bfloat16(v.z), hw=__float2bfloat16(v.w);
    union { __nv_bfloat162 b; uint32_t u; } c0, c1;
    c0.b = __halves2bfloat162(hx, hy);
    c1.b = __halves2bfloat162(hz, hw);
    uint2 h; h.x=c0.u; h.y=c1.u;
    uint2 l;
    l.x = pk2(v.x-__bfloat162float(hx), v.y-__bfloat162float(hy));
    l.y = pk2(v.z-__bfloat162float(hz), v.w-__bfloat162float(hw));
    hi[i]=h; lo[i]=l;
}

// fp32 -> residual-lo bf16 only
__global__ void split_lo4(const float4* __restrict__ in, uint2* __restrict__ lo, long n4){
    long i = (long)blockIdx.x*256 + threadIdx.x;
    if (i >= n4) return;
    float4 v = in[i];
    bf hx=__float2bfloat16(v.x), hy=__float2bfloat16(v.y);
    bf hz=__float2bfloat16(v.z), hw=__float2bfloat16(v.w);
    uint2 l;
    l.x = pk2(v.x-__bfloat162float(hx), v.y-__bfloat162float(hy));
    l.y = pk2(v.z-__bfloat162float(hz), v.w-__bfloat162float(hw));
    lo[i]=l;
}

// fp32 [R][C] -> bf16 [C][R] transpose (batched)
__global__ void t32_f2b(const float* __restrict__ src, bf* __restrict__ dst, int R, int C){
    __shared__ bf t[32][33];
    const float* s = src + (long)blockIdx.z*R*C;
    bf* d = dst + (long)blockIdx.z*R*C;
    int r0 = blockIdx.x*32, c0 = blockIdx.y*32;
    int tx = threadIdx.x & 31, ty = threadIdx.x >> 5;
    #pragma unroll
    for (int i=0;i<4;i++) t[ty+8*i][tx] = __float2bfloat16(s[(long)(r0+ty+8*i)*C + c0+tx]);
    __syncthreads();
    #pragma unroll
    for (int i=0;i<4;i++) d[(long)(c0+ty+8*i)*R + r0+tx] = t[tx][ty+8*i];
}

// fp32 [R][C] -> bf16 hi/lo [C][R] transpose
__global__ void t32_f2b2(const float* __restrict__ src, bf* __restrict__ dh,
                         bf* __restrict__ dl, int R, int C){
    __shared__ bf th[32][33];
    __shared__ bf tl[32][33];
    int r0 = blockIdx.x*32, c0 = blockIdx.y*32;
    int tx = threadIdx.x & 31, ty = threadIdx.x >> 5;
    #pragma unroll
    for (int i=0;i<4;i++){
        float v = src[(long)(r0+ty+8*i)*C + c0+tx];
        bf h = __float2bfloat16(v);
        th[ty+8*i][tx] = h;
        tl[ty+8*i][tx] = __float2bfloat16(v - __bfloat162float(h));
    }
    __syncthreads();
    #pragma unroll
    for (int i=0;i<4;i++){
        dh[(long)(c0+ty+8*i)*R + r0+tx] = th[tx][ty+8*i];
        dl[(long)(c0+ty+8*i)*R + r0+tx] = tl[tx][ty+8*i];
    }
}

// bf16 [R][C] -> bf16 [C][R]
__global__ void transpose_b(const bf* __restrict__ src, bf* __restrict__ dst, int R, int C){
    __shared__ bf t[32][33];
    int r0 = blockIdx.x*32, c0 = blockIdx.y*32;
    int tx = threadIdx.x & 31, ty = threadIdx.x >> 5;
    #pragma unroll
    for (int i=0;i<4;i++) t[ty+8*i][tx] = src[(long)(r0+ty+8*i)*C + c0+tx];
    __syncthreads();
    #pragma unroll
    for (int i=0;i<4;i++) dst[(long)(c0+ty+8*i)*R + r0+tx] = t[tx][ty+8*i];
}

// ---------------- elementwise / reduction kernels ----------------
__global__ void embed_norm_k(const int* __restrict__ masked, const float* __restrict__ embed,
                             float* __restrict__ xsa, bf* __restrict__ xsab,
                             bf* __restrict__ xsat, bf* __restrict__ acat)
{
    int t = blockIdx.x;
    int g = masked[t];
    float v = embed[(long)g*Ee + threadIdx.x];
    float mean = block_sum256(v) * (1.f/Ee);
    float d = v - mean;
    float var = block_sum256(d*d) * (1.f/(Ee-1));
    float o = v / (1.f + sqrtf(var));
    xsa [(long)t*Ee + threadIdx.x] = o;
    bf ob = __float2bfloat16(o);
    xsab[(long)t*Ee + threadIdx.x] = ob;
    xsat[(long)threadIdx.x*TOK + t] = ob;
    acat[(long)t*768 + 512 + threadIdx.x] = ob;
}

// softmax over rows of 512 (1/16 scale); bf16 logits in, bf16 probs out
__global__ void softmax_k(const bf* __restrict__ hb, bf* __restrict__ pb){
    long base = (long)blockIdx.x*256;
    uint32_t w = ((const uint32_t*)hb)[base + threadIdx.x];
    union { uint32_t u; __nv_bfloat162 b; } cv; cv.u = w;
    float v0 = __bfloat162float(__low2bfloat16(cv.b))  * 0.0625f;
    float v1 = __bfloat162float(__high2bfloat16(cv.b)) * 0.0625f;
    float mx = block_max256(fmaxf(v0, v1));
    float e0 = expf(v0 - mx), e1 = expf(v1 - mx);
    float s = block_sum256(e0 + e1);
    float inv = 1.f / s;
    ((uint32_t*)pb)[base + threadIdx.x] = pk2(e0*inv, e1*inv);
}

__global__ void update_norm_k(const float* __restrict__ xsad, const float* __restrict__ t1p,
                              float* __restrict__ xsa, bf* __restrict__ xsab,
                              bf* __restrict__ xsat)
{
    long idx = (long)blockIdx.x*Ee + threadIdx.x;
    const long S = (long)TOK*Ee;
    float u = xsad[idx] + t1p[idx] + t1p[idx+S] + t1p[idx+2*S] + t1p[idx+3*S];
    float mean = block_sum256(u) * (1.f/Ee);
    float d = u - mean;
    float var = block_sum256(d*d) * (1.f/(Ee-1));
    float un = u / (1.f + sqrtf(var));
    float w = xsa[idx] + 0.05f * un;
    float mean2 = block_sum256(w) * (1.f/Ee);
    float d2 = w - mean2;
    float var2 = block_sum256(d2*d2) * (1.f/(Ee-1));
    float o = w / (1.f + sqrtf(var2));
    xsa[idx]  = o;
    bf ob = __float2bfloat16(o);
    xsab[idx] = ob;
    xsat[(long)threadIdx.x*TOK + blockIdx.x] = ob;
}

__global__ void gather_split_k(const int* __restrict__ mask, const float* __restrict__ xsa,
                               bf* __restrict__ hi, bf* __restrict__ lo){
    int r = blockIdx.x; int b = r >> 6; int p = mask[r];
    float v = xsa[(long)(b*Ll + p)*Ee + threadIdx.x];
    bf h = __float2bfloat16(v);
    hi[(long)r*Ee + threadIdx.x] = h;
    lo[(long)r*Ee + threadIdx.x] = __float2bfloat16(v - __bfloat162float(h));
}

// single-pass online logsumexp over rows of 32000 + target logit fetch
__device__ __forceinline__ void ols_merge(float& m, float& s, float mo, float so){
    float mn = fmaxf(m, mo);
    s = s*expf(m - mn) + so*expf(mo - mn);
    m = mn;
}
__global__ void lse_k(const float* __restrict__ logits, const int* __restrict__ unmasked,
                      const int* __restrict__ mask, float* __restrict__ lse, float* __restrict__ tval)
{
    int row = blockIdx.x;
    const float* p = logits + (long)row * Gg;
    const float4* p4 = (const float4*)p;
    float m = -INFINITY, s = 0.f;
    for (int i = threadIdx.x; i < Gg/4; i += 256){
        float4 v = p4[i];
        float a[4] = {v.x, v.y, v.z, v.w};
        #pragma unroll
        for (int j=0;j<4;j++){
            float x = a[j];
            if (x <= m) s += expf(x - m);
            else { s = s*expf(m - x) + 1.f; m = x; }
        }
    }
    #pragma unroll
    for (int o=16;o;o>>=1){
        float mo = __shfl_xor_sync(0xffffffffu, m, o);
        float so = __shfl_xor_sync(0xffffffffu, s, o);
        ols_merge(m, s, mo, so);
    }
    __shared__ float shm[8], shs[8];
    int lane = threadIdx.x & 31, w = threadIdx.x >> 5;
    if (lane==0){ shm[w]=m; shs[w]=s; }
    __syncthreads();
    if (threadIdx.x==0){
        float M=shm[0], S=shs[0];
        #pragma unroll
        for (int i=1;i<8;i++) ols_merge(M, S, shm[i], shs[i]);
        lse[row] = M + logf(S);
        int b = row >> 8, n = row & 255, j = n >> 2;
        int tg = unmasked[b*Ll + mask[b*LM + j]];
        tval[row] = p[tg];
    }
}

__global__ void final_k(const float* __restrict__ tval, const float* __restrict__ lse,
                        float* __restrict__ out)
{
    int b = blockIdx.x, j = threadIdx.x;   // 64 threads
    float a[KN]; float m = -INFINITY;
    #pragma unroll
    for (int kn=0;kn<KN;kn++){
        int r = ((b << 6) + j) * KN + kn;
        a[kn] = tval[r] - lse[r];
        m = fmaxf(m, a[kn]);
    }
    float s = 0.f;
    #pragma unroll
    for (int kn=0;kn<KN;kn++) s += expf(a[kn] - m);
    float cent = m + logf(s) - 1.3862943611198906f;   // - log(4)
    __shared__ float sh[64];
    sh[j] = cent; __syncthreads();
    for (int o=32;o;o>>=1){ if (j<o) sh[j] += sh[j+o]; __syncthreads(); }
    if (j==0) out[b] = -sh[0] / (float)LM;
}

// ---------------- host orchestration ----------------
#define GSYM(p, s) cudaGetSymbolAddress((void**)&p, s)

extern "C" void kernel_launch(void* const* d_in, const int* in_sizes, int n_in,
                              void* d_out, int out_size)
{
    (void)in_sizes; (void)n_in; (void)out_size;
    const int*   masked   = (const int*)  d_in[0];
    const int*   unmasked = (const int*)  d_in[1];
    const int*   maskp    = (const int*)  d_in[2];
    const float* embed    = (const float*)d_in[3];
    const float* Wt       = (const float*)d_in[4];
    const float* bt       = (const float*)d_in[5];
    const float* Wtc      = (const float*)d_in[6];
    const float* Wq       = (const float*)d_in[7];
    const float* Wd       = (const float*)d_in[8];
    const float* Wo       = (const float*)d_in[9];
    const float* Wu       = (const float*)d_in[10];
    const float* Wem      = (const float*)d_in[11];
    const float* Wkc      = (const float*)d_in[12];
    const float* bkc      = (const float*)d_in[13];
    float* out = (float*)d_out;

    float *xsa,*xsad,*t1p,*logits,*lse,*tval;
    bf *hb,*xsab,*xsat,*acat,*q2b,*pb,*yb,*midb;
    bf *wq,*wd,*wot,*wc1,*wc2;
    bf *ehi,*elo,*xhlo,*xtlo,*wkhi,*wklo,*wmhi,*wmlo;
    bf *lphi,*lplo,*x1hi,*x1lo,*shi,*slo,*xxhi,*xxlo,*vhi,*vlo;
    GSYM(xsa,g_xsa); GSYM(xsad,g_xsad); GSYM(t1p,g_t1p); GSYM(hb,g_hb);
    GSYM(logits,g_logits); GSYM(lse,g_lse); GSYM(tval,g_tval);
    GSYM(xsab,g_xsab); GSYM(xsat,g_xsat); GSYM(acat,g_acat);
    GSYM(q2b,g_q2b); GSYM(pb,g_pb); GSYM(yb,g_yb); GSYM(midb,g_midb);
    GSYM(wq,g_wq); GSYM(wd,g_wd); GSYM(wot,g_wot); GSYM(wc1,g_wc1); GSYM(wc2,g_wc2);
    GSYM(ehi,g_ehi); GSYM(elo,g_elo); GSYM(xhlo,g_xhlo); GSYM(xtlo,g_xtlo);
    GSYM(wkhi,g_wkhi); GSYM(wklo,g_wklo); GSYM(wmhi,g_wmhi); GSYM(wmlo,g_wmlo);
    GSYM(lphi,g_lphi); GSYM(lplo,g_lplo);
    GSYM(x1hi,g_x1hi); GSYM(x1lo,g_x1lo); GSYM(shi,g_shi); GSYM(slo,g_slo);
    GSYM(xxhi,g_xxhi); GSYM(xxlo,g_xxlo); GSYM(vhi,g_vhi); GSYM(vlo,g_vlo);

    // kernel instantiations
    auto kS1 = bgemm_k<64,64,32,16,true ,false,4,2,false,1>;   // transitions stage1 -> acat bf16
    auto kS2 = bgemm_k<64,64,32,16,false,true ,0,0,false,0>;   // stage2 -> xsad fp32
    auto kWq = bgemm_k<128,128,64,32,false,false,1,0,false,1>; // q -> q2b (perm)
    auto kQK = bgemm_k<128,128,64,32,false,false,0,0,false,1>; // scores -> hb bf16
    auto kPV = bgemm_k<128,128,64,32,false,false,2,0,false,1>; // probs@V -> yb (perm)
    auto kWd = bgemm_k<128,128,64,32,true ,false,0,0,false,1>; // dense+relu -> midb
    auto kWo = bgemm_k<64,64,32,16,false,false,0,0,false,0>;   // split-K -> t1p partials
    auto kG1 = bgemm_k<64,64,32,16,false,true ,3,0,true ,2>;   // kchoice -> xx1 hi/lo (perm)
    auto kG2 = bgemm_k<64,64,32,16,false,false,0,0,true ,2>;   // -> s hi/lo
    auto kG3 = bgemm_k<64,64,32,16,false,false,0,0,true ,2>;   // -> xx hi/lo
    auto kG4 = bgemm_k<64,64,32,16,false,false,0,0,true ,2>;   // -> v hi/lo
    auto kG5 = bgemm_k<64,64,32,16,false,false,0,0,true ,0>;   // logits fp32

    constexpr int SM_BIG = 3*(128+128)*20*4;    // 61440 B
    constexpr int SM_SML = 3*(64+64)*20*4;      // 30720 B
    constexpr int SM_CMP = 3*2*(64+64)*20*4;    // 61440 B

    cudaFuncSetAttribute(kWq, cudaFuncAttributeMaxDynamicSharedMemorySize, SM_BIG);
    cudaFuncSetAttribute(kQK, cudaFuncAttributeMaxDynamicSharedMemorySize, SM_BIG);
    cudaFuncSetAttribute(kPV, cudaFuncAttributeMaxDynamicSharedMemorySize, SM_BIG);
    cudaFuncSetAttribute(kWd, cudaFuncAttributeMaxDynamicSharedMemorySize, SM_BIG);
    cudaFuncSetAttribute(kG1, cudaFuncAttributeMaxDynamicSharedMemorySize, SM_CMP);
    cudaFuncSetAttribute(kG2, cudaFuncAttributeMaxDynamicSharedMemorySize, SM_CMP);
    cudaFuncSetAttribute(kG3, cudaFuncAttributeMaxDynamicSharedMemorySize, SM_CMP);
    cudaFuncSetAttribute(kG4, cudaFuncAttributeMaxDynamicSharedMemorySize, SM_CMP);
    cudaFuncSetAttribute(kG5, cudaFuncAttributeMaxDynamicSharedMemorySize, SM_CMP);

    // ---- prep: bf16 weights (per launch; graph-captured) ----
    prep_w_k<<<(Dd*5*65536+1023)/1024,1024>>>(Wt, Wtc, Wu, wc1, wc2);
    conv_b4<<<((long)Dd*KE*Ee/4+255)/256,256>>>((const float4*)Wq, (uint2*)wq, (long)Dd*KE*Ee/4);
    conv_b4<<<((long)Dd*KE*KE/4+255)/256,256>>>((const float4*)Wd, (uint2*)wd, (long)Dd*KE*KE/4);
    t32_f2b<<<dim3(KE/32,Ee/32,Dd),256>>>(Wo, wot, KE, Ee);
    split_b4<<<((long)Gg*Ee/4+255)/256,256>>>((const float4*)embed, (uint2*)ehi, (uint2*)elo, (long)Gg*Ee/4);
    split_b4<<<(KN*Ee*Ee/4+255)/256,256>>>((const float4*)Wkc, (uint2*)wkhi, (uint2*)wklo, KN*Ee*Ee/4);
    t32_f2b2<<<dim3(Ee/32,Ee/32,1),256>>>(Wem, wmhi, wmlo, Ee, Ee);

    embed_norm_k<<<TOK,256>>>(masked, embed, xsa, xsab, xsat, acat);

    for (int d=0; d<Dd; d++){
        // transitions
        kS1<<<dim3(4,32,2),256,SM_SML>>>(xsab,0, wc1+(long)d*131072,0, 0, 0,acat,0,
                                         TOK,Ee,Ee, Ee,Ee, 0, 65536, 0, 1);
        kS2<<<dim3(4,32,1),256,SM_SML>>>(acat,0, wc2+(long)d*196608,0, bt+(long)d*Ee, xsad,0,0,
                                         TOK,Ee,768, 768,768, 0,0,0, 0);

        // attention
        kWq<<<dim3(16,16,1),256,SM_BIG>>>(xsab,0, wq+(long)d*KE*Ee,0, 0, 0,q2b,0,
                                          TOK,KE,Ee, Ee,Ee, 0,0,0, 0);
        kQK<<<dim3(4,32,Bb),256,SM_BIG>>>(q2b,0, xsab,0, 0, 0,hb,0,
                                          Ll*Kk,Ll,Ee, Ee,Ee,
                                          (long)Ll*Kk*Ee, (long)Ll*Ee, (long)Ll*Kk*Ll, 0);
        softmax_k<<<Bb*Ll*Kk,256>>>(hb, pb);
        kPV<<<dim3(2,32,Bb),256,SM_BIG>>>(pb,0, xsat,0, 0, 0,yb,0,
                                          Ll*Kk,Ee,Ll, Ll,TOK,
                                          (long)Ll*Kk*Ll, (long)Ll, 0, 0);

        // dense -> relu -> dense (Wo via split-K=4)
        kWd<<<dim3(16,16,1),256,SM_BIG>>>(yb,0, wd+(long)d*KE*KE,0, 0, 0,midb,0,
                                          TOK,KE,KE, KE,KE, 0,0,0, 0);
        kWo<<<dim3(4,32,4),256,SM_SML>>>(midb,0, wot+(long)d*Ee*KE,0, 0, t1p,0,0,
                                         TOK,Ee,512, KE,KE, 512, 512, (long)TOK*Ee, 0);

        update_norm_k<<<TOK,256>>>(xsad, t1p, xsa, xsab, xsat);
    }

    // ---- head (split-bf16 3-mma; hi of xsa == xsab/xsat) ----
    split_lo4<<<(TOK*Ee/4+255)/256,256>>>((const float4*)xsa, (uint2*)xhlo, TOK*Ee/4);
    transpose_b<<<dim3(TOK/32,Ee/32),256>>>(xhlo, xtlo, TOK, Ee);
    gather_split_k<<<Bb*LM,256>>>(maskp, xsa, lphi, lplo);

    kG1<<<dim3(16,4,1),256,SM_CMP>>>(lphi,lplo, wkhi,wklo, bkc, 0,x1hi,x1lo,
                                     Bb*LM, KN*Ee, Ee, Ee,Ee, 0,0,0, 0);
    kG2<<<dim3(8,4,Bb),256,SM_CMP>>>(x1hi,x1lo, xsab,xhlo, 0, 0,shi,slo,
                                     LM*KN, Ll, Ee, Ee,Ee,
                                     (long)LM*KN*Ee, (long)Ll*Ee, (long)LM*KN*Ll, 0);
    kG3<<<dim3(4,4,Bb),256,SM_CMP>>>(shi,slo, xsat,xtlo, 0, 0,xxhi,xxlo,
                                     LM*KN, Ee, Ll, Ll,TOK,
                                     (long)LM*KN*Ll, (long)Ll, (long)LM*KN*Ee, 0);
    kG4<<<dim3(4,16,1),256,SM_CMP>>>(xxhi,xxlo, wmhi,wmlo, 0, 0,vhi,vlo,
                                     Bb*LM*KN, Ee, Ee, Ee,Ee, 0,0,0, 0);
    kG5<<<dim3(500,16,1),256,SM_CMP>>>(vhi,vlo, ehi,elo, 0, logits,0,0,
                                       Bb*LM*KN, Gg, Ee, Ee,Ee, 0,0,0, 0);

    lse_k<<<Bb*LM*KN,256>>>(logits, unmasked, maskp, lse, tval);
    final_k<<<Bb,64>>>(tval, lse, out);
}

// round 8
// speedup vs baseline: 1.6667x; 1.0712x over previous
#include <cuda_runtime.h>
#include <cuda_bf16.h>
#include <math.h>
#include <stdint.h>

// ---------------- problem constants ----------------
#define Bb 4
#define Ll 512
#define Ee 256
#define Kk 8
#define Dd 6
#define LM 64
#define KN 4
#define Gg 32000
#define KE (Kk*Ee)          // 2048
#define TOK (Bb*Ll)         // 2048

typedef __nv_bfloat16 bf;

// ---------------- scratch (static device memory; no allocations) ----------------
__device__ float g_xsa [TOK*Ee];
__device__ float g_xsad[TOK*Ee];
__device__ float g_t1p [4L*TOK*Ee];                  // kWo split-K partials
__device__ bf    g_hb  [(long)Bb*Ll*Kk*Ll];          // attention logits bf16
__device__ bf    g_xsab[TOK*Ee];                     // xsa bf16 [t][e]
__device__ bf    g_xsat[Ee*TOK];                     // xsa bf16 transposed [e][t]
__device__ bf    g_acat[TOK*768];                    // [t1a | t1b | z] bf16
__device__ bf    g_q2b [TOK*KE];
__device__ bf    g_pb  [(long)Bb*Ll*Kk*Ll];          // softmax probs bf16
__device__ bf    g_yb  [TOK*KE];
__device__ bf    g_midb[TOK*KE];
// bf16 weights (prep)
__device__ bf    g_wq [(long)Dd*KE*Ee];
__device__ bf    g_wd [(long)Dd*KE*KE];
__device__ bf    g_wot[(long)Dd*Ee*KE];              // Wo^T  [n=E][k=KE]
__device__ bf    g_wc1[Dd*2*Ee*Ee];                  // [Wt^T][Wtc] as [n][k]
__device__ bf    g_wc2[Dd*Ee*768];                   // [Wtc^T|Wt|Wu] rows n, k=768
// head hi/lo bf16 splits (hi of xsa == xsab/xsat)
__device__ bf    g_ehi[(long)Gg*Ee], g_elo[(long)Gg*Ee];
__device__ bf    g_xhlo[TOK*Ee];
__device__ bf    g_xtlo[Ee*TOK];
__device__ bf    g_wkhi[KN*Ee*Ee],g_wklo[KN*Ee*Ee];
__device__ bf    g_wmhi[Ee*Ee],   g_wmlo[Ee*Ee];     // Wem^T hi/lo
__device__ bf    g_lphi[Bb*LM*Ee],g_lplo[Bb*LM*Ee];
__device__ bf    g_x1hi[Bb*LM*KN*Ee], g_x1lo[Bb*LM*KN*Ee];
__device__ bf    g_shi[(long)Bb*LM*KN*Ll], g_slo[(long)Bb*LM*KN*Ll];
__device__ bf    g_xxhi[Bb*LM*KN*Ee], g_xxlo[Bb*LM*KN*Ee];
__device__ bf    g_vhi[Bb*LM*KN*Ee],  g_vlo[Bb*LM*KN*Ee];
__device__ float g_logits[(long)Bb*LM*KN*Gg];
__device__ float g_lse [Bb*LM*KN];
__device__ float g_tval[Bb*LM*KN];

// ---------------- reductions ----------------
__device__ __forceinline__ float warp_sum(float v){
    #pragma unroll
    for (int o=16;o;o>>=1) v += __shfl_xor_sync(0xffffffffu, v, o);
    return v;
}
__device__ __forceinline__ float warp_max(float v){
    #pragma unroll
    for (int o=16;o;o>>=1) v = fmaxf(v, __shfl_xor_sync(0xffffffffu, v, o));
    return v;
}
__device__ float block_sum256(float v){
    __shared__ float sh[8];
    int lane = threadIdx.x & 31, w = threadIdx.x >> 5;
    v = warp_sum(v);
    if (lane==0) sh[w] = v;
    __syncthreads();
    float r = (threadIdx.x < 8) ? sh[threadIdx.x] : 0.f;
    if (w==0){ r = warp_sum(r); if (lane==0) sh[0]=r; }
    __syncthreads();
    float out = sh[0];
    __syncthreads();
    return out;
}
__device__ float block_max256(float v){
    __shared__ float sh[8];
    int lane = threadIdx.x & 31, w = threadIdx.x >> 5;
    v = warp_max(v);
    if (lane==0) sh[w] = v;
    __syncthreads();
    float r = (threadIdx.x < 8) ? sh[threadIdx.x] : -INFINITY;
    if (w==0){ r = warp_max(r); if (lane==0) sh[0]=r; }
    __syncthreads();
    float out = sh[0];
    __syncthreads();
    return out;
}

// ---------------- bf16 / mma / cp.async / ldmatrix helpers ----------------
__device__ __forceinline__ uint32_t pk2(float lo, float hi){
    uint32_t r;
    asm("cvt.rn.bf16x2.f32 %0, %1, %2;" : "=r"(r) : "f"(hi), "f"(lo));
    return r;
}
__device__ __forceinline__ void mma_bf16(float* d, const uint32_t* a, const uint32_t* b){
    asm volatile(
      "mma.sync.aligned.m16n8k16.row.col.f32.bf16.bf16.f32 "
      "{%0,%1,%2,%3}, {%4,%5,%6,%7}, {%8,%9}, {%0,%1,%2,%3};\n"
      : "+f"(d[0]),"+f"(d[1]),"+f"(d[2]),"+f"(d[3])
      : "r"(a[0]),"r"(a[1]),"r"(a[2]),"r"(a[3]), "r"(b[0]),"r"(b[1]));
}
__device__ __forceinline__ void cp16b(void* s, const bf* g){
    uint32_t sa = (uint32_t)__cvta_generic_to_shared(s);
    asm volatile("cp.async.ca.shared.global [%0], [%1], 16;\n" :: "r"(sa), "l"(g));
}
__device__ __forceinline__ void cp_commit(){ asm volatile("cp.async.commit_group;\n" ::); }
template<int W> __device__ __forceinline__ void cp_wait(){ asm volatile("cp.async.wait_group %0;\n" :: "n"(W)); }
__device__ __forceinline__ uint32_t s2u(const void* p){
    uint32_t a;
    asm("{ .reg .u64 t; cvta.to.shared.u64 t, %1; cvt.u32.u64 %0, t; }" : "=r"(a) : "l"(p));
    return a;
}
__device__ __forceinline__ void ldsm4(uint32_t& r0, uint32_t& r1, uint32_t& r2, uint32_t& r3,
                                      uint32_t addr){
    asm volatile("ldmatrix.sync.aligned.m8n8.x4.shared.b16 {%0,%1,%2,%3}, [%4];"
        : "=r"(r0),"=r"(r1),"=r"(r2),"=r"(r3) : "r"(addr));
}

// PMODE output index mapping (element index):
// 0: bz*sC + r*N + c
// 1: q2 perm  (r over TOK, c over KE)
// 2: y perm   (r over L*K per batch, c over E)
// 3: xx1 perm (r over B*LM, c over KN*E)
// 4: acat: r*768 + bz*256 + c
template<int PMODE>
__device__ __forceinline__ long out_index(int r, int c, int bz, int N, long sC){
    if (PMODE==0) return (long)bz*sC + (long)r*N + c;
    if (PMODE==1) return (((long)(r>>9))<<20) + ((long)(r&511)<<11) + c;
    if (PMODE==2) return (((long)(bz*512 + (r>>3)))<<11) + ((long)(r&7)<<8) + c;
    if (PMODE==3) return (((long)(r>>6))<<16) + ((long)(r&63)<<10) + c;
    return (long)r*768 + ((long)bz<<8) + c;
}

// ---------------- unified bf16 tensor-core GEMM (3-stage pipeline, ldmatrix) ----------------
// C[M,N] = A[M,K] * B^T, A row-major [M][K] (pitch lda), B row-major [N][K] (pitch ldb).
// Smem rows pitch 20 words (16 data + 4 pad): 8 consecutive rows' 16B chunks fall
// in 8 distinct 4-bank groups -> ldmatrix conflict-free.
// COMP: split-bf16 3-mma with separate hi/lo arrays.
// OUTMODE: 0 fp32 C; 1 bf16 Cb; 2 hi/lo pair (Cb, Clo).
// ROLLMODE: 0 none; 2 per-batch circular row shift within 512-row groups.
template<int BM,int BN,int WM,int WN,bool RELU,bool BIAS,int PMODE,int ROLLMODE,bool COMP,int OUTMODE>
__global__ __launch_bounds__(256, 2)
void bgemm_k(const bf* __restrict__ A, const bf* __restrict__ Alo,
             const bf* __restrict__ B, const bf* __restrict__ Blo,
             const float* __restrict__ bias,
             float* __restrict__ C, bf* __restrict__ Cb, bf* __restrict__ Clo,
             int M, int N, int Kd, int lda, int ldb,
             long sA, long sB, long sC, int rollShift)
{
    constexpr int P   = 20;
    constexpr int NST = COMP ? 2 : 1;
    constexpr int TA  = BM*P, TB = BN*P;
    constexpr int STG = NST*(TA+TB);
    constexpr int MI  = WM/16, NI = WN/8;
    constexpr int NJ  = NI/2;
    constexpr int WCOLS = BN/WN;

    extern __shared__ uint32_t smw[];
    const uint32_t smem_u = s2u(smw);

    const int bz = blockIdx.z;
    const bf* Ap  = A + (long)bz*sA;
    const bf* Alp = COMP ? Alo + (long)bz*sA : nullptr;
    const bf* Bp  = B + (long)bz*sB;
    const bf* Blp = COMP ? Blo + (long)bz*sB : nullptr;

    int rs = 0;
    if (ROLLMODE==2) rs = (bz==0) ? rollShift : -rollShift;

    const int row0 = blockIdx.y*BM, col0 = blockIdx.x*BN;
    const int tid  = threadIdx.x;
    const int warp = tid >> 5, lane = tid & 31;
    const int wy = warp / WCOLS, wx = warp % WCOLS;
    const int g = lane >> 2, c4 = lane & 3;

    // ldmatrix per-lane relative byte offsets
    // A x4: mat0 rows 0-7 @k0-7, mat1 rows 8-15 @k0-7, mat2 rows 0-7 @k8-15, mat3 rows 8-15 @k8-15
    uint32_t aoff[MI];
    #pragma unroll
    for (int mi=0; mi<MI; mi++)
        aoff[mi] = (uint32_t)(((wy*WM + mi*16 + (lane & 15))*P + (lane>>4)*4) * 4);
    // B x4: mat0 (ni rows, k0-7), mat1 (ni rows, k8-15), mat2 (ni+1 rows, k0-7), mat3 (ni+1, k8-15)
    uint32_t boff[NJ];
    #pragma unroll
    for (int j=0; j<NJ; j++)
        boff[j] = (uint32_t)(((wx*WN + j*16 + ((lane>>4)<<3) + (lane & 7))*P + ((lane>>3)&1)*4) * 4);

    auto load_tile = [&](int kt, int st){
        uint32_t* base = smw + st*STG;
        uint32_t* Ah = base;
        uint32_t* Al = base + TA;
        uint32_t* Bh = base + NST*TA;
        uint32_t* Bl = Bh + TB;
        const int k0 = kt*32;
        #pragma unroll
        for (int i=0;i<BM*4/256;i++){
            int id = tid + i*256; int r = id>>2, q = id&3;
            int gr = row0 + r;
            if (ROLLMODE) gr = (gr & ~511) | ((gr - rs) & 511);
            long go = (long)gr*lda + k0 + 8*q;
            cp16b(Ah + r*P + 4*q, Ap + go);
            if (COMP) cp16b(Al + r*P + 4*q, Alp + go);
        }
        #pragma unroll
        for (int i=0;i<BN*4/256;i++){
            int id = tid + i*256; int n = id>>2, q = id&3;
            long go = (long)(col0+n)*ldb + k0 + 8*q;
            cp16b(Bh + n*P + 4*q, Bp + go);
            if (COMP) cp16b(Bl + n*P + 4*q, Blp + go);
        }
        cp_commit();
    };

    float acc[MI][NI][4];
    #pragma unroll
    for (int i=0;i<MI;i++)
        #pragma unroll
        for (int j=0;j<NI;j++)
            #pragma unroll
            for (int t=0;t<4;t++) acc[i][j][t]=0.f;

    const int nit = Kd/32;
    load_tile(0, 0);
    load_tile(1, 1);

    int st = 0;
    for (int it=0; it<nit; it++){
        if (it+2 < nit){ load_tile(it+2, (it+2)%3); cp_wait<2>(); }
        else if (it+1 < nit){ cp_wait<1>(); }
        else { cp_wait<0>(); }
        __syncthreads();

        const uint32_t AhB = smem_u + (uint32_t)(st*STG*4);
        const uint32_t AlB = AhB + TA*4;
        const uint32_t BhB = AhB + NST*TA*4;
        const uint32_t BlB = BhB + TB*4;

        #pragma unroll
        for (int ks=0; ks<2; ks++){
            const uint32_t ko = ks*32;   // 8 words
            uint32_t af[MI][4], bfr[NI][2];
            uint32_t afl[COMP?MI:1][4], bfl[COMP?NI:1][2];
            #pragma unroll
            for (int mi=0; mi<MI; mi++){
                ldsm4(af[mi][0], af[mi][1], af[mi][2], af[mi][3], AhB + aoff[mi] + ko);
                if (COMP)
                    ldsm4(afl[mi][0], afl[mi][1], afl[mi][2], afl[mi][3], AlB + aoff[mi] + ko);
            }
            #pragma unroll
            for (int j=0; j<NJ; j++){
                ldsm4(bfr[2*j][0], bfr[2*j][1], bfr[2*j+1][0], bfr[2*j+1][1], BhB + boff[j] + ko);
                if (COMP)
                    ldsm4(bfl[2*j][0], bfl[2*j][1], bfl[2*j+1][0], bfl[2*j+1][1], BlB + boff[j] + ko);
            }
            #pragma unroll
            for (int mi=0; mi<MI; mi++)
                #pragma unroll
                for (int ni=0; ni<NI; ni++){
                    if (COMP){
                        mma_bf16(acc[mi][ni], afl[mi], bfr[ni]);
                        mma_bf16(acc[mi][ni], af[mi], bfl[ni]);
                    }
                    mma_bf16(acc[mi][ni], af[mi], bfr[ni]);
                }
        }
        __syncthreads();
        st = (st==2) ? 0 : st+1;
    }

    // ---- epilogue ----
    #pragma unroll
    for (int mi=0; mi<MI; mi++){
        #pragma unroll
        for (int half=0; half<2; half++){
            int r = row0 + wy*WM + mi*16 + g + half*8;
            #pragma unroll
            for (int ni=0; ni<NI; ni++){
                int cc = col0 + wx*WN + ni*8 + 2*c4;
                float v0 = acc[mi][ni][half*2+0];
                float v1 = acc[mi][ni][half*2+1];
                if (BIAS){ v0 += bias[cc]; v1 += bias[cc+1]; }
                if (RELU){ v0 = fmaxf(v0,0.f); v1 = fmaxf(v1,0.f); }
                long idx = out_index<PMODE>(r, cc, bz, N, sC);
                if (OUTMODE==0){
                    *(float2*)(C + idx) = make_float2(v0, v1);
                } else if (OUTMODE==1){
                    *(uint32_t*)(Cb + idx) = pk2(v0, v1);
                } else {
                    bf h0 = __float2bfloat16(v0);
                    bf h1 = __float2bfloat16(v1);
                    union { __nv_bfloat162 b; uint32_t u; } cu;
                    cu.b = __halves2bfloat162(h0, h1);
                    *(uint32_t*)(Cb + idx)  = cu.u;
                    *(uint32_t*)(Clo + idx) = pk2(v0 - __bfloat162float(h0),
                                                  v1 - __bfloat162float(h1));
                }
            }
        }
    }
}

// ---------------- prep kernels ----------------
__global__ void prep_w_k(const float* __restrict__ Wt, const float* __restrict__ Wtc,
                         const float* __restrict__ Wu,
                         bf* __restrict__ wc1, bf* __restrict__ wc2)
{
    long idx = (long)blockIdx.x*1024 + threadIdx.x;
    if (idx >= (long)Dd*5*65536) return;
    int d = idx / (5*65536);
    int r = idx % (5*65536);
    int which = r / 65536;
    int e = r % 65536;
    int n = e >> 8, k = e & 255;
    long wb = (long)d*65536;
    if      (which==0) wc1[(long)d*131072 +         n*256+k] = __float2bfloat16(Wt [wb + (long)k*256 + n]);
    else if (which==1) wc1[(long)d*131072 + 65536 + n*256+k] = __float2bfloat16(Wtc[wb + (long)n*256 + k]);
    else if (which==2) wc2[(long)d*196608 + (long)n*768 +       k] = __float2bfloat16(Wtc[wb + (long)k*256 + n]);
    else if (which==3) wc2[(long)d*196608 + (long)n*768 + 256 + k] = __float2bfloat16(Wt [wb + (long)n*256 + k]);
    else               wc2[(long)d*196608 + (long)n*768 + 512 + k] = __float2bfloat16(Wu [wb + (long)n*256 + k]);
}

__global__ void conv_b4(const float4* __restrict__ in, uint2* __restrict__ outp, long n4){
    long i = (long)blockIdx.x*256 + threadIdx.x;
    if (i >= n4) return;
    float4 v = in[i];
    uint2 o; o.x = pk2(v.x, v.y); o.y = pk2(v.z, v.w);
    outp[i] = o;
}

__global__ void split_b4(const float4* __restrict__ in, uint2* __restrict__ hi,
                         uint2* __restrict__ lo, long n4){
    long i = (long)blockIdx.x*256 + threadIdx.x;
    if (i >= n4) return;
    float4 v = in[i];
    bf hx=__float2bfloat16(v.x), hy=__float2bfloat16(v.y);
    bf hz=__float2bfloat16(v.z), hw=__float2bfloat16(v.w);
    union { __nv_bfloat162 b; uint32_t u; } c0, c1;
    c0.b = __halves2bfloat162(hx, hy);
    c1.b = __halves2bfloat162(hz, hw);
    uint2 h; h.x=c0.u; h.y=c1.u;
    uint2 l;
    l.x = pk2(v.x-__bfloat162float(hx), v.y-__bfloat162float(hy));
    l.y = pk2(v.z-__bfloat162float(hz), v.w-__bfloat162float(hw));
    hi[i]=h; lo[i]=l;
}

__global__ void split_lo4(const float4* __restrict__ in, uint2* __restrict__ lo, long n4){
    long i = (long)blockIdx.x*256 + threadIdx.x;
    if (i >= n4) return;
    float4 v = in[i];
    bf hx=__float2bfloat16(v.x), hy=__float2bfloat16(v.y);
    bf hz=__float2bfloat16(v.z), hw=__float2bfloat16(v.w);
    uint2 l;
    l.x = pk2(v.x-__bfloat162float(hx), v.y-__bfloat162float(hy));
    l.y = pk2(v.z-__bfloat162float(hz), v.w-__bfloat162float(hw));
    lo[i]=l;
}

__global__ void t32_f2b(const float* __restrict__ src, bf* __restrict__ dst, int R, int C){
    __shared__ bf t[32][33];
    const float* s = src + (long)blockIdx.z*R*C;
    bf* d = dst + (long)blockIdx.z*R*C;
    int r0 = blockIdx.x*32, c0 = blockIdx.y*32;
    int tx = threadIdx.x & 31, ty = threadIdx.x >> 5;
    #pragma unroll
    for (int i=0;i<4;i++) t[ty+8*i][tx] = __float2bfloat16(s[(long)(r0+ty+8*i)*C + c0+tx]);
    __syncthreads();
    #pragma unroll
    for (int i=0;i<4;i++) d[(long)(c0+ty+8*i)*R + r0+tx] = t[tx][ty+8*i];
}

__global__ void t32_f2b2(const float* __restrict__ src, bf* __restrict__ dh,
                         bf* __restrict__ dl, int R, int C){
    __shared__ bf th[32][33];
    __shared__ bf tl[32][33];
    int r0 = blockIdx.x*32, c0 = blockIdx.y*32;
    int tx = threadIdx.x & 31, ty = threadIdx.x >> 5;
    #pragma unroll
    for (int i=0;i<4;i++){
        float v = src[(long)(r0+ty+8*i)*C + c0+tx];
        bf h = __float2bfloat16(v);
        th[ty+8*i][tx] = h;
        tl[ty+8*i][tx] = __float2bfloat16(v - __bfloat162float(h));
    }
    __syncthreads();
    #pragma unroll
    for (int i=0;i<4;i++){
        dh[(long)(c0+ty+8*i)*R + r0+tx] = th[tx][ty+8*i];
        dl[(long)(c0+ty+8*i)*R + r0+tx] = tl[tx][ty+8*i];
    }
}

__global__ void transpose_b(const bf* __restrict__ src, bf* __restrict__ dst, int R, int C){
    __shared__ bf t[32][33];
    int r0 = blockIdx.x*32, c0 = blockIdx.y*32;
    int tx = threadIdx.x & 31, ty = threadIdx.x >> 5;
    #pragma unroll
    for (int i=0;i<4;i++) t[ty+8*i][tx] = src[(long)(r0+ty+8*i)*C + c0+tx];
    __syncthreads();
    #pragma unroll
    for (int i=0;i<4;i++) dst[(long)(c0+ty+8*i)*R + r0+tx] = t[tx][ty+8*i];
}

// ---------------- elementwise / reduction kernels ----------------
__global__ void embed_norm_k(const int* __restrict__ masked, const float* __restrict__ embed,
                             float* __restrict__ xsa, bf* __restrict__ xsab,
                             bf* __restrict__ xsat, bf* __restrict__ acat)
{
    int t = blockIdx.x;
    int g = masked[t];
    float v = embed[(long)g*Ee + threadIdx.x];
    float mean = block_sum256(v) * (1.f/Ee);
    float d = v - mean;
    float var = block_sum256(d*d) * (1.f/(Ee-1));
    float o = v / (1.f + sqrtf(var));
    xsa [(long)t*Ee + threadIdx.x] = o;
    bf ob = __float2bfloat16(o);
    xsab[(long)t*Ee + threadIdx.x] = ob;
    xsat[(long)threadIdx.x*TOK + t] = ob;
    acat[(long)t*768 + 512 + threadIdx.x] = ob;
}

__global__ void softmax_k(const bf* __restrict__ hb, bf* __restrict__ pb){
    long base = (long)blockIdx.x*256;
    uint32_t w = ((const uint32_t*)hb)[base + threadIdx.x];
    union { uint32_t u; __nv_bfloat162 b; } cv; cv.u = w;
    float v0 = __bfloat162float(__low2bfloat16(cv.b))  * 0.0625f;
    float v1 = __bfloat162float(__high2bfloat16(cv.b)) * 0.0625f;
    float mx = block_max256(fmaxf(v0, v1));
    float e0 = expf(v0 - mx), e1 = expf(v1 - mx);
    float s = block_sum256(e0 + e1);
    float inv = 1.f / s;
    ((uint32_t*)pb)[base + threadIdx.x] = pk2(e0*inv, e1*inv);
}

__global__ void update_norm_k(const float* __restrict__ xsad, const float* __restrict__ t1p,
                              float* __restrict__ xsa, bf* __restrict__ xsab,
                              bf* __restrict__ xsat)
{
    long idx = (long)blockIdx.x*Ee + threadIdx.x;
    const long S = (long)TOK*Ee;
    float u = xsad[idx] + t1p[idx] + t1p[idx+S] + t1p[idx+2*S] + t1p[idx+3*S];
    float mean = block_sum256(u) * (1.f/Ee);
    float d = u - mean;
    float var = block_sum256(d*d) * (1.f/(Ee-1));
    float un = u / (1.f + sqrtf(var));
    float w = xsa[idx] + 0.05f * un;
    float mean2 = block_sum256(w) * (1.f/Ee);
    float d2 = w - mean2;
    float var2 = block_sum256(d2*d2) * (1.f/(Ee-1));
    float o = w / (1.f + sqrtf(var2));
    xsa[idx]  = o;
    bf ob = __float2bfloat16(o);
    xsab[idx] = ob;
    xsat[(long)threadIdx.x*TOK + blockIdx.x] = ob;
}

__global__ void gather_split_k(const int* __restrict__ mask, const float* __restrict__ xsa,
                               bf* __restrict__ hi, bf* __restrict__ lo){
    int r = blockIdx.x; int b = r >> 6; int p = mask[r];
    float v = xsa[(long)(b*Ll + p)*Ee + threadIdx.x];
    bf h = __float2bfloat16(v);
    hi[(long)r*Ee + threadIdx.x] = h;
    lo[(long)r*Ee + threadIdx.x] = __float2bfloat16(v - __bfloat162float(h));
}

__device__ __forceinline__ void ols_merge(float& m, float& s, float mo, float so){
    float mn = fmaxf(m, mo);
    s = s*expf(m - mn) + so*expf(mo - mn);
    m = mn;
}
__global__ void lse_k(const float* __restrict__ logits, const int* __restrict__ unmasked,
                      const int* __restrict__ mask, float* __restrict__ lse, float* __restrict__ tval)
{
    int row = blockIdx.x;
    const float* p = logits + (long)row * Gg;
    const float4* p4 = (const float4*)p;
    float m = -INFINITY, s = 0.f;
    for (int i = threadIdx.x; i < Gg/4; i += 256){
        float4 v = p4[i];
        float a[4] = {v.x, v.y, v.z, v.w};
        #pragma unroll
        for (int j=0;j<4;j++){
            float x = a[j];
            if (x <= m) s += expf(x - m);
            else { s = s*expf(m - x) + 1.f; m = x; }
        }
    }
    #pragma unroll
    for (int o=16;o;o>>=1){
        float mo = __shfl_xor_sync(0xffffffffu, m, o);
        float so = __shfl_xor_sync(0xffffffffu, s, o);
        ols_merge(m, s, mo, so);
    }
    __shared__ float shm[8], shs[8];
    int lane = threadIdx.x & 31, w = threadIdx.x >> 5;
    if (lane==0){ shm[w]=m; shs[w]=s; }
    __syncthreads();
    if (threadIdx.x==0){
        float M=shm[0], S=shs[0];
        #pragma unroll
        for (int i=1;i<8;i++) ols_merge(M, S, shm[i], shs[i]);
        lse[row] = M + logf(S);
        int b = row >> 8, n = row & 255, j = n >> 2;
        int tg = unmasked[b*Ll + mask[b*LM + j]];
        tval[row] = p[tg];
    }
}

__global__ void final_k(const float* __restrict__ tval, const float* __restrict__ lse,
                        float* __restrict__ out)
{
    int b = blockIdx.x, j = threadIdx.x;   // 64 threads
    float a[KN]; float m = -INFINITY;
    #pragma unroll
    for (int kn=0;kn<KN;kn++){
        int r = ((b << 6) + j) * KN + kn;
        a[kn] = tval[r] - lse[r];
        m = fmaxf(m, a[kn]);
    }
    float s = 0.f;
    #pragma unroll
    for (int kn=0;kn<KN;kn++) s += expf(a[kn] - m);
    float cent = m + logf(s) - 1.3862943611198906f;   // - log(4)
    __shared__ float sh[64];
    sh[j] = cent; __syncthreads();
    for (int o=32;o;o>>=1){ if (j<o) sh[j] += sh[j+o]; __syncthreads(); }
    if (j==0) out[b] = -sh[0] / (float)LM;
}

// ---------------- host orchestration ----------------
#define GSYM(p, s) cudaGetSymbolAddress((void**)&p, s)

extern "C" void kernel_launch(void* const* d_in, const int* in_sizes, int n_in,
                              void* d_out, int out_size)
{
    (void)in_sizes; (void)n_in; (void)out_size;
    const int*   masked   = (const int*)  d_in[0];
    const int*   unmasked = (const int*)  d_in[1];
    const int*   maskp    = (const int*)  d_in[2];
    const float* embed    = (const float*)d_in[3];
    const float* Wt       = (const float*)d_in[4];
    const float* bt       = (const float*)d_in[5];
    const float* Wtc      = (const float*)d_in[6];
    const float* Wq       = (const float*)d_in[7];
    const float* Wd       = (const float*)d_in[8];
    const float* Wo       = (const float*)d_in[9];
    const float* Wu       = (const float*)d_in[10];
    const float* Wem      = (const float*)d_in[11];
    const float* Wkc      = (const float*)d_in[12];
    const float* bkc      = (const float*)d_in[13];
    float* out = (float*)d_out;

    float *xsa,*xsad,*t1p,*logits,*lse,*tval;
    bf *hb,*xsab,*xsat,*acat,*q2b,*pb,*yb,*midb;
    bf *wq,*wd,*wot,*wc1,*wc2;
    bf *ehi,*elo,*xhlo,*xtlo,*wkhi,*wklo,*wmhi,*wmlo;
    bf *lphi,*lplo,*x1hi,*x1lo,*shi,*slo,*xxhi,*xxlo,*vhi,*vlo;
    GSYM(xsa,g_xsa); GSYM(xsad,g_xsad); GSYM(t1p,g_t1p); GSYM(hb,g_hb);
    GSYM(logits,g_logits); GSYM(lse,g_lse); GSYM(tval,g_tval);
    GSYM(xsab,g_xsab); GSYM(xsat,g_xsat); GSYM(acat,g_acat);
    GSYM(q2b,g_q2b); GSYM(pb,g_pb); GSYM(yb,g_yb); GSYM(midb,g_midb);
    GSYM(wq,g_wq); GSYM(wd,g_wd); GSYM(wot,g_wot); GSYM(wc1,g_wc1); GSYM(wc2,g_wc2);
    GSYM(ehi,g_ehi); GSYM(elo,g_elo); GSYM(xhlo,g_xhlo); GSYM(xtlo,g_xtlo);
    GSYM(wkhi,g_wkhi); GSYM(wklo,g_wklo); GSYM(wmhi,g_wmhi); GSYM(wmlo,g_wmlo);
    GSYM(lphi,g_lphi); GSYM(lplo,g_lplo);
    GSYM(x1hi,g_x1hi); GSYM(x1lo,g_x1lo); GSYM(shi,g_shi); GSYM(slo,g_slo);
    GSYM(xxhi,g_xxhi); GSYM(xxlo,g_xxlo); GSYM(vhi,g_vhi); GSYM(vlo,g_vlo);

    // kernel instantiations
    auto kS1 = bgemm_k<64,64,32,16,true ,false,4,2,false,1>;   // transitions stage1 -> acat bf16
    auto kS2 = bgemm_k<64,64,32,16,false,true ,0,0,false,0>;   // stage2 -> xsad fp32
    auto kWq = bgemm_k<128,128,64,32,false,false,1,0,false,1>; // q -> q2b (perm)
    auto kQK = bgemm_k<128,128,64,32,false,false,0,0,false,1>; // scores -> hb bf16
    auto kPV = bgemm_k<128,128,64,32,false,false,2,0,false,1>; // probs@V -> yb (perm)
    auto kWd = bgemm_k<128,128,64,32,true ,false,0,0,false,1>; // dense+relu -> midb
    auto kWo = bgemm_k<64,64,32,16,false,false,0,0,false,0>;   // split-K -> t1p partials
    auto kG1 = bgemm_k<64,64,32,16,false,true ,3,0,true ,2>;   // kchoice -> xx1 hi/lo (perm)
    auto kG2 = bgemm_k<64,64,32,16,false,false,0,0,true ,2>;   // -> s hi/lo
    auto kG3 = bgemm_k<64,64,32,16,false,false,0,0,true ,2>;   // -> xx hi/lo
    auto kG4 = bgemm_k<64,64,32,16,false,false,0,0,true ,2>;   // -> v hi/lo
    auto kG5 = bgemm_k<64,64,32,16,false,false,0,0,true ,0>;   // logits fp32

    constexpr int SM_BIG = 3*(128+128)*20*4;    // 61440 B
    constexpr int SM_SML = 3*(64+64)*20*4;      // 30720 B
    constexpr int SM_CMP = 3*2*(64+64)*20*4;    // 61440 B

    cudaFuncSetAttribute(kWq, cudaFuncAttributeMaxDynamicSharedMemorySize, SM_BIG);
    cudaFuncSetAttribute(kQK, cudaFuncAttributeMaxDynamicSharedMemorySize, SM_BIG);
    cudaFuncSetAttribute(kPV, cudaFuncAttributeMaxDynamicSharedMemorySize, SM_BIG);
    cudaFuncSetAttribute(kWd, cudaFuncAttributeMaxDynamicSharedMemorySize, SM_BIG);
    cudaFuncSetAttribute(kG1, cudaFuncAttributeMaxDynamicSharedMemorySize, SM_CMP);
    cudaFuncSetAttribute(kG2, cudaFuncAttributeMaxDynamicSharedMemorySize, SM_CMP);
    cudaFuncSetAttribute(kG3, cudaFuncAttributeMaxDynamicSharedMemorySize, SM_CMP);
    cudaFuncSetAttribute(kG4, cudaFuncAttributeMaxDynamicSharedMemorySize, SM_CMP);
    cudaFuncSetAttribute(kG5, cudaFuncAttributeMaxDynamicSharedMemorySize, SM_CMP);

    // ---- prep: bf16 weights (per launch; graph-captured) ----
    prep_w_k<<<(Dd*5*65536+1023)/1024,1024>>>(Wt, Wtc, Wu, wc1, wc2);
    conv_b4<<<((long)Dd*KE*Ee/4+255)/256,256>>>((const float4*)Wq, (uint2*)wq, (long)Dd*KE*Ee/4);
    conv_b4<<<((long)Dd*KE*KE/4+255)/256,256>>>((const float4*)Wd, (uint2*)wd, (long)Dd*KE*KE/4);
    t32_f2b<<<dim3(KE/32,Ee/32,Dd),256>>>(Wo, wot, KE, Ee);
    split_b4<<<((long)Gg*Ee/4+255)/256,256>>>((const float4*)embed, (uint2*)ehi, (uint2*)elo, (long)Gg*Ee/4);
    split_b4<<<(KN*Ee*Ee/4+255)/256,256>>>((const float4*)Wkc, (uint2*)wkhi, (uint2*)wklo, KN*Ee*Ee/4);
    t32_f2b2<<<dim3(Ee/32,Ee/32,1),256>>>(Wem, wmhi, wmlo, Ee, Ee);

    embed_norm_k<<<TOK,256>>>(masked, embed, xsa, xsab, xsat, acat);

    for (int d=0; d<Dd; d++){
        // transitions
        kS1<<<dim3(4,32,2),256,SM_SML>>>(xsab,0, wc1+(long)d*131072,0, 0, 0,acat,0,
                                         TOK,Ee,Ee, Ee,Ee, 0, 65536, 0, 1);
        kS2<<<dim3(4,32,1),256,SM_SML>>>(acat,0, wc2+(long)d*196608,0, bt+(long)d*Ee, xsad,0,0,
                                         TOK,Ee,768, 768,768, 0,0,0, 0);

        // attention
        kWq<<<dim3(16,16,1),256,SM_BIG>>>(xsab,0, wq+(long)d*KE*Ee,0, 0, 0,q2b,0,
                                          TOK,KE,Ee, Ee,Ee, 0,0,0, 0);
        kQK<<<dim3(4,32,Bb),256,SM_BIG>>>(q2b,0, xsab,0, 0, 0,hb,0,
                                          Ll*Kk,Ll,Ee, Ee,Ee,
                                          (long)Ll*Kk*Ee, (long)Ll*Ee, (long)Ll*Kk*Ll, 0);
        softmax_k<<<Bb*Ll*Kk,256>>>(hb, pb);
        kPV<<<dim3(2,32,Bb),256,SM_BIG>>>(pb,0, xsat,0, 0, 0,yb,0,
                                          Ll*Kk,Ee,Ll, Ll,TOK,
                                          (long)Ll*Kk*Ll, (long)Ll, 0, 0);

        // dense -> relu -> dense (Wo via split-K=4)
        kWd<<<dim3(16,16,1),256,SM_BIG>>>(yb,0, wd+(long)d*KE*KE,0, 0, 0,midb,0,
                                          TOK,KE,KE, KE,KE, 0,0,0, 0);
        kWo<<<dim3(4,32,4),256,SM_SML>>>(midb,0, wot+(long)d*Ee*KE,0, 0, t1p,0,0,
                                         TOK,Ee,512, KE,KE, 512, 512, (long)TOK*Ee, 0);

        update_norm_k<<<TOK,256>>>(xsad, t1p, xsa, xsab, xsat);
    }

    // ---- head (split-bf16 3-mma; hi of xsa == xsab/xsat) ----
    split_lo4<<<(TOK*Ee/4+255)/256,256>>>((const float4*)xsa, (uint2*)xhlo, TOK*Ee/4);
    transpose_b<<<dim3(TOK/32,Ee/32),256>>>(xhlo, xtlo, TOK, Ee);
    gather_split_k<<<Bb*LM,256>>>(maskp, xsa, lphi, lplo);

    kG1<<<dim3(16,4,1),256,SM_CMP>>>(lphi,lplo, wkhi,wklo, bkc, 0,x1hi,x1lo,
                                     Bb*LM, KN*Ee, Ee, Ee,Ee, 0,0,0, 0);
    kG2<<<dim3(8,4,Bb),256,SM_CMP>>>(x1hi,x1lo, xsab,xhlo, 0, 0,shi,slo,
                                     LM*KN, Ll, Ee, Ee,Ee,
                                     (long)LM*KN*Ee, (long)Ll*Ee, (long)LM*KN*Ll, 0);
    kG3<<<dim3(4,4,Bb),256,SM_CMP>>>(shi,slo, xsat,xtlo, 0, 0,xxhi,xxlo,
                                     LM*KN, Ee, Ll, Ll,TOK,
                                     (long)LM*KN*Ll, (long)Ll, (long)LM*KN*Ee, 0);
    kG4<<<dim3(4,16,1),256,SM_CMP>>>(xxhi,xxlo, wmhi,wmlo, 0, 0,vhi,vlo,
                                     Bb*LM*KN, Ee, Ee, Ee,Ee, 0,0,0, 0);
    kG5<<<dim3(500,16,1),256,SM_CMP>>>(vhi,vlo, ehi,elo, 0, logits,0,0,
                                       Bb*LM*KN, Gg, Ee, Ee,Ee, 0,0,0, 0);

    lse_k<<<Bb*LM*KN,256>>>(logits, unmasked, maskp, lse, tval);
    final_k<<<Bb,64>>>(tval, lse, out);
}

// round 9
// speedup vs baseline: 1.8125x; 1.0875x over previous
#include <cuda_runtime.h>
#include <cuda_bf16.h>
#include <math.h>
#include <stdint.h>

// ---------------- problem constants ----------------
#define Bb 4
#define Ll 512
#define Ee 256
#define Kk 8
#define Dd 6
#define LM 64
#define KN 4
#define Gg 32000
#define KE (Kk*Ee)          // 2048
#define TOK (Bb*Ll)         // 2048

typedef __nv_bfloat16 bf;

// ---------------- scratch (static device memory; no allocations) ----------------
__device__ float g_xsa [TOK*Ee];
__device__ float g_xsad[TOK*Ee];
__device__ float g_t1p [4L*TOK*Ee];                  // kWo split-K partials
__device__ bf    g_xsab[TOK*Ee];                     // xsa bf16 [t][e]
__device__ bf    g_xsat[Ee*TOK];                     // xsa bf16 transposed [e][t]
__device__ bf    g_acat[TOK*768];                    // [t1a | t1b | z] bf16
__device__ bf    g_q2b [TOK*KE];
__device__ bf    g_pb  [(long)Bb*Ll*Kk*Ll];          // softmax probs bf16
__device__ bf    g_yb  [TOK*KE];
__device__ bf    g_midb[TOK*KE];
// bf16 weights (prep)
__device__ bf    g_wq [(long)Dd*KE*Ee];
__device__ bf    g_wd [(long)Dd*KE*KE];
__device__ bf    g_wot[(long)Dd*Ee*KE];              // Wo^T  [n=E][k=KE]
__device__ bf    g_wc1[Dd*2*Ee*Ee];                  // [Wt^T][Wtc] as [n][k]
__device__ bf    g_wc2[Dd*Ee*768];                   // [Wtc^T|Wt|Wu] rows n, k=768
// head hi/lo bf16 splits (hi of xsa == xsab/xsat)
__device__ bf    g_ehi[(long)Gg*Ee], g_elo[(long)Gg*Ee];
__device__ bf    g_xhlo[TOK*Ee];
__device__ bf    g_xtlo[Ee*TOK];
__device__ bf    g_wkhi[KN*Ee*Ee],g_wklo[KN*Ee*Ee];
__device__ bf    g_wmhi[Ee*Ee],   g_wmlo[Ee*Ee];     // Wem^T hi/lo
__device__ bf    g_lphi[Bb*LM*Ee],g_lplo[Bb*LM*Ee];
__device__ bf    g_x1hi[Bb*LM*KN*Ee], g_x1lo[Bb*LM*KN*Ee];
__device__ bf    g_shi[(long)Bb*LM*KN*Ll], g_slo[(long)Bb*LM*KN*Ll];
__device__ bf    g_xxhi[Bb*LM*KN*Ee], g_xxlo[Bb*LM*KN*Ee];
__device__ bf    g_vhi[Bb*LM*KN*Ee],  g_vlo[Bb*LM*KN*Ee];
// fused-LSE partials (1024 rows x 500 col-blocks)
__device__ float g_pm[(long)Bb*LM*KN*500];
__device__ float g_ps[(long)Bb*LM*KN*500];
__device__ float g_lse [Bb*LM*KN];
__device__ float g_tval[Bb*LM*KN];

// ---------------- reductions ----------------
__device__ __forceinline__ float warp_sum(float v){
    #pragma unroll
    for (int o=16;o;o>>=1) v += __shfl_xor_sync(0xffffffffu, v, o);
    return v;
}
__device__ __forceinline__ float warp_max(float v){
    #pragma unroll
    for (int o=16;o;o>>=1) v = fmaxf(v, __shfl_xor_sync(0xffffffffu, v, o));
    return v;
}
__device__ float block_sum256(float v){
    __shared__ float sh[8];
    int lane = threadIdx.x & 31, w = threadIdx.x >> 5;
    v = warp_sum(v);
    if (lane==0) sh[w] = v;
    __syncthreads();
    float r = (threadIdx.x < 8) ? sh[threadIdx.x] : 0.f;
    if (w==0){ r = warp_sum(r); if (lane==0) sh[0]=r; }
    __syncthreads();
    float out = sh[0];
    __syncthreads();
    return out;
}
__device__ float block_max256(float v){
    __shared__ float sh[8];
    int lane = threadIdx.x & 31, w = threadIdx.x >> 5;
    v = warp_max(v);
    if (lane==0) sh[w] = v;
    __syncthreads();
    float r = (threadIdx.x < 8) ? sh[threadIdx.x] : -INFINITY;
    if (w==0){ r = warp_max(r); if (lane==0) sh[0]=r; }
    __syncthreads();
    float out = sh[0];
    __syncthreads();
    return out;
}

// ---------------- bf16 / mma / cp.async / ldmatrix helpers ----------------
__device__ __forceinline__ uint32_t pk2(float lo, float hi){
    uint32_t r;
    asm("cvt.rn.bf16x2.f32 %0, %1, %2;" : "=r"(r) : "f"(hi), "f"(lo));
    return r;
}
__device__ __forceinline__ void mma_bf16(float* d, const uint32_t* a, const uint32_t* b){
    asm volatile(
      "mma.sync.aligned.m16n8k16.row.col.f32.bf16.bf16.f32 "
      "{%0,%1,%2,%3}, {%4,%5,%6,%7}, {%8,%9}, {%0,%1,%2,%3};\n"
      : "+f"(d[0]),"+f"(d[1]),"+f"(d[2]),"+f"(d[3])
      : "r"(a[0]),"r"(a[1]),"r"(a[2]),"r"(a[3]), "r"(b[0]),"r"(b[1]));
}
__device__ __forceinline__ void cp16b(void* s, const bf* g){
    uint32_t sa = (uint32_t)__cvta_generic_to_shared(s);
    asm volatile("cp.async.ca.shared.global [%0], [%1], 16;\n" :: "r"(sa), "l"(g));
}
__device__ __forceinline__ void cp_commit(){ asm volatile("cp.async.commit_group;\n" ::); }
template<int W> __device__ __forceinline__ void cp_wait(){ asm volatile("cp.async.wait_group %0;\n" :: "n"(W)); }
__device__ __forceinline__ uint32_t s2u(const void* p){
    uint32_t a;
    asm("{ .reg .u64 t; cvta.to.shared.u64 t, %1; cvt.u32.u64 %0, t; }" : "=r"(a) : "l"(p));
    return a;
}
__device__ __forceinline__ void ldsm4(uint32_t& r0, uint32_t& r1, uint32_t& r2, uint32_t& r3,
                                      uint32_t addr){
    asm volatile("ldmatrix.sync.aligned.m8n8.x4.shared.b16 {%0,%1,%2,%3}, [%4];"
        : "=r"(r0),"=r"(r1),"=r"(r2),"=r"(r3) : "r"(addr));
}
__device__ __forceinline__ void ols_merge(float& m, float& s, float mo, float so){
    float mn = fmaxf(m, mo);
    s = s*expf(m - mn) + so*expf(mo - mn);
    m = mn;
}

// PMODE output index mapping (element index):
// 0: bz*sC + r*N + c
// 1: q2 perm  (r over TOK, c over KE)
// 2: y perm   (r over L*K per batch, c over E)
// 3: xx1 perm (r over B*LM, c over KN*E)
// 4: acat: r*768 + bz*256 + c
template<int PMODE>
__device__ __forceinline__ long out_index(int r, int c, int bz, int N, long sC){
    if (PMODE==0) return (long)bz*sC + (long)r*N + c;
    if (PMODE==1) return (((long)(r>>9))<<20) + ((long)(r&511)<<11) + c;
    if (PMODE==2) return (((long)(bz*512 + (r>>3)))<<11) + ((long)(r&7)<<8) + c;
    if (PMODE==3) return (((long)(r>>6))<<16) + ((long)(r&63)<<10) + c;
    return (long)r*768 + ((long)bz<<8) + c;
}

// ---------------- unified bf16 tensor-core GEMM (3-stage pipeline, ldmatrix) ----------------
template<int BM,int BN,int WM,int WN,bool RELU,bool BIAS,int PMODE,int ROLLMODE,bool COMP,int OUTMODE>
__global__ __launch_bounds__(256, 2)
void bgemm_k(const bf* __restrict__ A, const bf* __restrict__ Alo,
             const bf* __restrict__ B, const bf* __restrict__ Blo,
             const float* __restrict__ bias,
             float* __restrict__ C, bf* __restrict__ Cb, bf* __restrict__ Clo,
             int M, int N, int Kd, int lda, int ldb,
             long sA, long sB, long sC, int rollShift)
{
    constexpr int P   = 20;
    constexpr int NST = COMP ? 2 : 1;
    constexpr int TA  = BM*P, TB = BN*P;
    constexpr int STG = NST*(TA+TB);
    constexpr int MI  = WM/16, NI = WN/8;
    constexpr int NJ  = NI/2;
    constexpr int WCOLS = BN/WN;

    extern __shared__ uint32_t smw[];
    const uint32_t smem_u = s2u(smw);

    const int bz = blockIdx.z;
    const bf* Ap  = A + (long)bz*sA;
    const bf* Alp = COMP ? Alo + (long)bz*sA : nullptr;
    const bf* Bp  = B + (long)bz*sB;
    const bf* Blp = COMP ? Blo + (long)bz*sB : nullptr;

    int rs = 0;
    if (ROLLMODE==2) rs = (bz==0) ? rollShift : -rollShift;

    const int row0 = blockIdx.y*BM, col0 = blockIdx.x*BN;
    const int tid  = threadIdx.x;
    const int warp = tid >> 5, lane = tid & 31;
    const int wy = warp / WCOLS, wx = warp % WCOLS;
    const int g = lane >> 2, c4 = lane & 3;

    uint32_t aoff[MI];
    #pragma unroll
    for (int mi=0; mi<MI; mi++)
        aoff[mi] = (uint32_t)(((wy*WM + mi*16 + (lane & 15))*P + (lane>>4)*4) * 4);
    uint32_t boff[NJ];
    #pragma unroll
    for (int j=0; j<NJ; j++)
        boff[j] = (uint32_t)(((wx*WN + j*16 + ((lane>>4)<<3) + (lane & 7))*P + ((lane>>3)&1)*4) * 4);

    auto load_tile = [&](int kt, int st){
        uint32_t* base = smw + st*STG;
        uint32_t* Ah = base;
        uint32_t* Al = base + TA;
        uint32_t* Bh = base + NST*TA;
        uint32_t* Bl = Bh + TB;
        const int k0 = kt*32;
        #pragma unroll
        for (int i=0;i<BM*4/256;i++){
            int id = tid + i*256; int r = id>>2, q = id&3;
            int gr = row0 + r;
            if (ROLLMODE) gr = (gr & ~511) | ((gr - rs) & 511);
            long go = (long)gr*lda + k0 + 8*q;
            cp16b(Ah + r*P + 4*q, Ap + go);
            if (COMP) cp16b(Al + r*P + 4*q, Alp + go);
        }
        #pragma unroll
        for (int i=0;i<BN*4/256;i++){
            int id = tid + i*256; int n = id>>2, q = id&3;
            long go = (long)(col0+n)*ldb + k0 + 8*q;
            cp16b(Bh + n*P + 4*q, Bp + go);
            if (COMP) cp16b(Bl + n*P + 4*q, Blp + go);
        }
        cp_commit();
    };

    float acc[MI][NI][4];
    #pragma unroll
    for (int i=0;i<MI;i++)
        #pragma unroll
        for (int j=0;j<NI;j++)
            #pragma unroll
            for (int t=0;t<4;t++) acc[i][j][t]=0.f;

    const int nit = Kd/32;
    load_tile(0, 0);
    load_tile(1, 1);

    int st = 0;
    for (int it=0; it<nit; it++){
        if (it+2 < nit){ load_tile(it+2, (it+2)%3); cp_wait<2>(); }
        else if (it+1 < nit){ cp_wait<1>(); }
        else { cp_wait<0>(); }
        __syncthreads();

        const uint32_t AhB = smem_u + (uint32_t)(st*STG*4);
        const uint32_t AlB = AhB + TA*4;
        const uint32_t BhB = AhB + NST*TA*4;
        const uint32_t BlB = BhB + TB*4;

        #pragma unroll
        for (int ks=0; ks<2; ks++){
            const uint32_t ko = ks*32;
            uint32_t af[MI][4], bfr[NI][2];
            uint32_t afl[COMP?MI:1][4], bfl[COMP?NI:1][2];
            #pragma unroll
            for (int mi=0; mi<MI; mi++){
                ldsm4(af[mi][0], af[mi][1], af[mi][2], af[mi][3], AhB + aoff[mi] + ko);
                if (COMP)
                    ldsm4(afl[mi][0], afl[mi][1], afl[mi][2], afl[mi][3], AlB + aoff[mi] + ko);
            }
            #pragma unroll
            for (int j=0; j<NJ; j++){
                ldsm4(bfr[2*j][0], bfr[2*j][1], bfr[2*j+1][0], bfr[2*j+1][1], BhB + boff[j] + ko);
                if (COMP)
                    ldsm4(bfl[2*j][0], bfl[2*j][1], bfl[2*j+1][0], bfl[2*j+1][1], BlB + boff[j] + ko);
            }
            #pragma unroll
            for (int mi=0; mi<MI; mi++)
                #pragma unroll
                for (int ni=0; ni<NI; ni++){
                    if (COMP){
                        mma_bf16(acc[mi][ni], afl[mi], bfr[ni]);
                        mma_bf16(acc[mi][ni], af[mi], bfl[ni]);
                    }
                    mma_bf16(acc[mi][ni], af[mi], bfr[ni]);
                }
        }
        __syncthreads();
        st = (st==2) ? 0 : st+1;
    }

    // ---- epilogue ----
    #pragma unroll
    for (int mi=0; mi<MI; mi++){
        #pragma unroll
        for (int half=0; half<2; half++){
            int r = row0 + wy*WM + mi*16 + g + half*8;
            #pragma unroll
            for (int ni=0; ni<NI; ni++){
                int cc = col0 + wx*WN + ni*8 + 2*c4;
                float v0 = acc[mi][ni][half*2+0];
                float v1 = acc[mi][ni][half*2+1];
                if (BIAS){ v0 += bias[cc]; v1 += bias[cc+1]; }
                if (RELU){ v0 = fmaxf(v0,0.f); v1 = fmaxf(v1,0.f); }
                long idx = out_index<PMODE>(r, cc, bz, N, sC);
                if (OUTMODE==0){
                    *(float2*)(C + idx) = make_float2(v0, v1);
                } else if (OUTMODE==1){
                    *(uint32_t*)(Cb + idx) = pk2(v0, v1);
                } else {
                    bf h0 = __float2bfloat16(v0);
                    bf h1 = __float2bfloat16(v1);
                    union { __nv_bfloat162 b; uint32_t u; } cu;
                    cu.b = __halves2bfloat162(h0, h1);
                    *(uint32_t*)(Cb + idx)  = cu.u;
                    *(uint32_t*)(Clo + idx) = pk2(v0 - __bfloat162float(h0),
                                                  v1 - __bfloat162float(h1));
                }
            }
        }
    }
}

// ---------------- fused QK + softmax ----------------
// scores tile 64x512 (full attention row), softmax in epilogue, bf16 probs out.
// A = q2b [4096 rows][256] per batch; B = xsab [512 rows][256] per batch.
__global__ __launch_bounds__(512, 1)
void qk_softmax_k(const bf* __restrict__ A, const bf* __restrict__ B,
                  bf* __restrict__ Pout, long sA, long sB, long sC)
{
    constexpr int Pw = 20;
    constexpr int TA = 64*Pw, TB = 512*Pw, STG = TA+TB;
    extern __shared__ uint32_t smw[];
    const uint32_t smem_u = s2u(smw);

    const int bz = blockIdx.z;
    const bf* Ap = A + (long)bz*sA;
    const bf* Bp = B + (long)bz*sB;
    const int row0 = blockIdx.y*64;
    const int tid = threadIdx.x, warp = tid>>5, lane = tid&31;
    const int wy = warp>>3, wx = warp&7;      // 2 x 8 warps; WM=32, WN=64
    const int g = lane>>2, c4 = lane&3;

    uint32_t aoff[2];
    #pragma unroll
    for (int mi=0;mi<2;mi++)
        aoff[mi] = (uint32_t)(((wy*32 + mi*16 + (lane & 15))*Pw + (lane>>4)*4) * 4);
    uint32_t boff[4];
    #pragma unroll
    for (int j=0;j<4;j++)
        boff[j] = (uint32_t)(((wx*64 + j*16 + ((lane>>4)<<3) + (lane & 7))*Pw + ((lane>>3)&1)*4) * 4);

    auto load_tile = [&](int kt, int st){
        uint32_t* base = smw + st*STG;
        uint32_t* Ah = base;
        uint32_t* Bh = base + TA;
        const int k0 = kt*32;
        if (tid < 256){
            int r = tid>>2, q = tid&3;
            cp16b(Ah + r*Pw + 4*q, Ap + (long)(row0+r)*256 + k0 + 8*q);
        }
        #pragma unroll
        for (int i=0;i<4;i++){
            int id = tid + i*512; int n = id>>2, q = id&3;
            cp16b(Bh + n*Pw + 4*q, Bp + (long)n*256 + k0 + 8*q);
        }
        cp_commit();
    };

    float acc[2][8][4];
    #pragma unroll
    for (int i=0;i<2;i++)
        #pragma unroll
        for (int j=0;j<8;j++)
            #pragma unroll
            for (int t=0;t<4;t++) acc[i][j][t]=0.f;

    const int nit = 8;   // K=256
    load_tile(0, 0);
    load_tile(1, 1);
    int st = 0;
    for (int it=0; it<nit; it++){
        if (it+2 < nit){ load_tile(it+2, (it+2)%3); cp_wait<2>(); }
        else if (it+1 < nit){ cp_wait<1>(); }
        else { cp_wait<0>(); }
        __syncthreads();

        const uint32_t AhB = smem_u + (uint32_t)(st*STG*4);
        const uint32_t BhB = AhB + TA*4;
        #pragma unroll
        for (int ks=0; ks<2; ks++){
            const uint32_t ko = ks*32;
            uint32_t af[2][4], bfr[8][2];
            #pragma unroll
            for (int mi=0; mi<2; mi++)
                ldsm4(af[mi][0], af[mi][1], af[mi][2], af[mi][3], AhB + aoff[mi] + ko);
            #pragma unroll
            for (int j=0; j<4; j++)
                ldsm4(bfr[2*j][0], bfr[2*j][1], bfr[2*j+1][0], bfr[2*j+1][1], BhB + boff[j] + ko);
            #pragma unroll
            for (int mi=0; mi<2; mi++)
                #pragma unroll
                for (int ni=0; ni<8; ni++)
                    mma_bf16(acc[mi][ni], af[mi], bfr[ni]);
        }
        __syncthreads();
        st = (st==2) ? 0 : st+1;
    }

    // ---- softmax epilogue (scale 1/16) ----
    float* red_m = (float*)smw;          // [64][8]
    float* red_s = red_m + 64*8;
    #pragma unroll
    for (int mi=0; mi<2; mi++){
        #pragma unroll
        for (int half=0; half<2; half++){
            float mx = -INFINITY;
            #pragma unroll
            for (int ni=0; ni<8; ni++)
                mx = fmaxf(mx, fmaxf(acc[mi][ni][half*2], acc[mi][ni][half*2+1]));
            mx *= 0.0625f;
            float s = 0.f;
            #pragma unroll
            for (int ni=0; ni<8; ni++){
                s += expf(acc[mi][ni][half*2+0]*0.0625f - mx);
                s += expf(acc[mi][ni][half*2+1]*0.0625f - mx);
            }
            float m = mx;
            #pragma unroll
            for (int o=1; o<=2; o<<=1){
                float mo = __shfl_xor_sync(0xffffffffu, m, o);
                float so = __shfl_xor_sync(0xffffffffu, s, o);
                ols_merge(m, s, mo, so);
            }
            int rt = wy*32 + mi*16 + half*8 + g;
            if (c4==0){ red_m[rt*8+wx] = m; red_s[rt*8+wx] = s; }
        }
    }
    __syncthreads();
    if (tid < 64){
        float M = red_m[tid*8], S = red_s[tid*8];
        #pragma unroll
        for (int i=1;i<8;i++) ols_merge(M, S, red_m[tid*8+i], red_s[tid*8+i]);
        red_m[tid*8] = M;
        red_s[tid*8] = 1.f/S;
    }
    __syncthreads();
    #pragma unroll
    for (int mi=0; mi<2; mi++){
        #pragma unroll
        for (int half=0; half<2; half++){
            int rt = wy*32 + mi*16 + half*8 + g;
            float M = red_m[rt*8], inv = red_s[rt*8];
            long rowbase = (long)bz*sC + (long)(row0+rt)*512;
            #pragma unroll
            for (int ni=0; ni<8; ni++){
                int c = wx*64 + ni*8 + 2*c4;
                float p0 = expf(acc[mi][ni][half*2+0]*0.0625f - M)*inv;
                float p1 = expf(acc[mi][ni][half*2+1]*0.0625f - M)*inv;
                *(uint32_t*)(Pout + rowbase + c) = pk2(p0, p1);
            }
        }
    }
}

// ---------------- fused logits GEMM + online-LSE partials (COMP, 64x64) ----------------
// A = v hi/lo [1024][256], B = embed hi/lo [32000][256]. No logits output:
// per-block per-row (m,s) partials written to pm/ps [row][500].
__global__ __launch_bounds__(256, 2)
void glse_k(const bf* __restrict__ A, const bf* __restrict__ Alo,
            const bf* __restrict__ B, const bf* __restrict__ Blo,
            float* __restrict__ pm, float* __restrict__ ps)
{
    constexpr int Pw = 20;
    constexpr int TA = 64*Pw, TB = 64*Pw;
    constexpr int STG = 2*(TA+TB);
    extern __shared__ uint32_t smw[];
    const uint32_t smem_u = s2u(smw);

    const int row0 = blockIdx.y*64, col0 = blockIdx.x*64, bx = blockIdx.x;
    const int tid = threadIdx.x, warp = tid>>5, lane = tid&31;
    const int wy = warp>>2, wx = warp&3;     // WM=32, WN=16
    const int g = lane>>2, c4 = lane&3;

    uint32_t aoff[2];
    #pragma unroll
    for (int mi=0;mi<2;mi++)
        aoff[mi] = (uint32_t)(((wy*32 + mi*16 + (lane & 15))*Pw + (lane>>4)*4) * 4);
    uint32_t boff0 = (uint32_t)(((wx*16 + ((lane>>4)<<3) + (lane & 7))*Pw + ((lane>>3)&1)*4) * 4);

    auto load_tile = [&](int kt, int st){
        uint32_t* base = smw + st*STG;
        uint32_t* Ah = base;
        uint32_t* Al = base + TA;
        uint32_t* Bh = base + 2*TA;
        uint32_t* Bl = Bh + TB;
        const int k0 = kt*32;
        {
            int r = tid>>2, q = tid&3;
            long go = (long)(row0+r)*256 + k0 + 8*q;
            cp16b(Ah + r*Pw + 4*q, A + go);
            cp16b(Al + r*Pw + 4*q, Alo + go);
            long gb = (long)(col0+r)*256 + k0 + 8*q;
            cp16b(Bh + r*Pw + 4*q, B + gb);
            cp16b(Bl + r*Pw + 4*q, Blo + gb);
        }
        cp_commit();
    };

    float acc[2][2][4];
    #pragma unroll
    for (int i=0;i<2;i++)
        #pragma unroll
        for (int j=0;j<2;j++)
            #pragma unroll
            for (int t=0;t<4;t++) acc[i][j][t]=0.f;

    const int nit = 8;   // K=256
    load_tile(0, 0);
    load_tile(1, 1);
    int st = 0;
    for (int it=0; it<nit; it++){
        if (it+2 < nit){ load_tile(it+2, (it+2)%3); cp_wait<2>(); }
        else if (it+1 < nit){ cp_wait<1>(); }
        else { cp_wait<0>(); }
        __syncthreads();

        const uint32_t AhB = smem_u + (uint32_t)(st*STG*4);
        const uint32_t AlB = AhB + TA*4;
        const uint32_t BhB = AhB + 2*TA*4;
        const uint32_t BlB = BhB + TB*4;
        #pragma unroll
        for (int ks=0; ks<2; ks++){
            const uint32_t ko = ks*32;
            uint32_t af[2][4], afl[2][4], bfr[2][2], bfl[2][2];
            #pragma unroll
            for (int mi=0; mi<2; mi++){
                ldsm4(af[mi][0], af[mi][1], af[mi][2], af[mi][3], AhB + aoff[mi] + ko);
                ldsm4(afl[mi][0], afl[mi][1], afl[mi][2], afl[mi][3], AlB + aoff[mi] + ko);
            }
            ldsm4(bfr[0][0], bfr[0][1], bfr[1][0], bfr[1][1], BhB + boff0 + ko);
            ldsm4(bfl[0][0], bfl[0][1], bfl[1][0], bfl[1][1], BlB + boff0 + ko);
            #pragma unroll
            for (int mi=0; mi<2; mi++)
                #pragma unroll
                for (int ni=0; ni<2; ni++){
                    mma_bf16(acc[mi][ni], afl[mi], bfr[ni]);
                    mma_bf16(acc[mi][ni], af[mi], bfl[ni]);
                    mma_bf16(acc[mi][ni], af[mi], bfr[ni]);
                }
        }
        __syncthreads();
        st = (st==2) ? 0 : st+1;
    }

    // ---- online-LSE partial epilogue ----
    float* red_m = (float*)smw;       // [64][4]
    float* red_s = red_m + 64*4;
    #pragma unroll
    for (int mi=0; mi<2; mi++){
        #pragma unroll
        for (int half=0; half<2; half++){
            float mx = fmaxf(fmaxf(acc[mi][0][half*2], acc[mi][0][half*2+1]),
                             fmaxf(acc[mi][1][half*2], acc[mi][1][half*2+1]));
            float s = expf(acc[mi][0][half*2+0]-mx) + expf(acc[mi][0][half*2+1]-mx)
                    + expf(acc[mi][1][half*2+0]-mx) + expf(acc[mi][1][half*2+1]-mx);
            float m = mx;
            #pragma unroll
            for (int o=1; o<=2; o<<=1){
                float mo = __shfl_xor_sync(0xffffffffu, m, o);
                float so = __shfl_xor_sync(0xffffffffu, s, o);
                ols_merge(m, s, mo, so);
            }
            int rt = wy*32 + mi*16 + half*8 + g;
            if (c4==0){ red_m[rt*4+wx] = m; red_s[rt*4+wx] = s; }
        }
    }
    __syncthreads();
    if (tid < 64){
        float M = red_m[tid*4], S = red_s[tid*4];
        #pragma unroll
        for (int i=1;i<4;i++) ols_merge(M, S, red_m[tid*4+i], red_s[tid*4+i]);
        long idx = (long)(row0+tid)*500 + bx;
        pm[idx] = M;
        ps[idx] = S;
    }
}

// merge 500 partials per row -> lse
__global__ void lse_red_k(const float* __restrict__ pm, const float* __restrict__ ps,
                          float* __restrict__ lse){
    int row = blockIdx.x*8 + (threadIdx.x>>5);
    int lane = threadIdx.x & 31;
    float m = -INFINITY, s = 0.f;
    for (int i=lane; i<500; i+=32)
        ols_merge(m, s, pm[(long)row*500+i], ps[(long)row*500+i]);
    #pragma unroll
    for (int o=16;o;o>>=1){
        float mo = __shfl_xor_sync(0xffffffffu, m, o);
        float so = __shfl_xor_sync(0xffffffffu, s, o);
        ols_merge(m, s, mo, so);
    }
    if (lane==0) lse[row] = m + logf(s);
}

// exact fp32 target logit: dot(v[row], embed[tg]) from hi/lo reconstructions
__global__ void tval_k(const bf* __restrict__ vhi, const bf* __restrict__ vlo,
                       const bf* __restrict__ ehi, const bf* __restrict__ elo,
                       const int* __restrict__ unmasked, const int* __restrict__ mask,
                       float* __restrict__ tval){
    int row = blockIdx.x;
    int b = row >> 8, n = row & 255, j = n >> 2;
    int tg = unmasked[b*Ll + mask[b*LM + j]];
    long vi = (long)row*Ee + threadIdx.x;
    long ei = (long)tg*Ee + threadIdx.x;
    float v = (__bfloat162float(vhi[vi]) + __bfloat162float(vlo[vi]))
            * (__bfloat162float(ehi[ei]) + __bfloat162float(elo[ei]));
    float s = block_sum256(v);
    if (threadIdx.x==0) tval[row] = s;
}

// ---------------- prep kernels ----------------
__global__ void prep_w_k(const float* __restrict__ Wt, const float* __restrict__ Wtc,
                         const float* __restrict__ Wu,
                         bf* __restrict__ wc1, bf* __restrict__ wc2)
{
    long idx = (long)blockIdx.x*1024 + threadIdx.x;
    if (idx >= (long)Dd*5*65536) return;
    int d = idx / (5*65536);
    int r = idx % (5*65536);
    int which = r / 65536;
    int e = r % 65536;
    int n = e >> 8, k = e & 255;
    long wb = (long)d*65536;
    if      (which==0) wc1[(long)d*131072 +         n*256+k] = __float2bfloat16(Wt [wb + (long)k*256 + n]);
    else if (which==1) wc1[(long)d*131072 + 65536 + n*256+k] = __float2bfloat16(Wtc[wb + (long)n*256 + k]);
    else if (which==2) wc2[(long)d*196608 + (long)n*768 +       k] = __float2bfloat16(Wtc[wb + (long)k*256 + n]);
    else if (which==3) wc2[(long)d*196608 + (long)n*768 + 256 + k] = __float2bfloat16(Wt [wb + (long)n*256 + k]);
    else               wc2[(long)d*196608 + (long)n*768 + 512 + k] = __float2bfloat16(Wu [wb + (long)n*256 + k]);
}

__global__ void conv_b4(const float4* __restrict__ in, uint2* __restrict__ outp, long n4){
    long i = (long)blockIdx.x*256 + threadIdx.x;
    if (i >= n4) return;
    float4 v = in[i];
    uint2 o; o.x = pk2(v.x, v.y); o.y = pk2(v.z, v.w);
    outp[i] = o;
}

__global__ void split_b4(const float4* __restrict__ in, uint2* __restrict__ hi,
                         uint2* __restrict__ lo, long n4){
    long i = (long)blockIdx.x*256 + threadIdx.x;
    if (i >= n4) return;
    float4 v = in[i];
    bf hx=__float2bfloat16(v.x), hy=__float2bfloat16(v.y);
    bf hz=__float2bfloat16(v.z), hw=__float2bfloat16(v.w);
    union { __nv_bfloat162 b; uint32_t u; } c0, c1;
    c0.b = __halves2bfloat162(hx, hy);
    c1.b = __halves2bfloat162(hz, hw);
    uint2 h; h.x=c0.u; h.y=c1.u;
    uint2 l;
    l.x = pk2(v.x-__bfloat162float(hx), v.y-__bfloat162float(hy));
    l.y = pk2(v.z-__bfloat162float(hz), v.w-__bfloat162float(hw));
    hi[i]=h; lo[i]=l;
}

__global__ void split_lo4(const float4* __restrict__ in, uint2* __restrict__ lo, long n4){
    long i = (long)blockIdx.x*256 + threadIdx.x;
    if (i >= n4) return;
    float4 v = in[i];
    bf hx=__float2bfloat16(v.x), hy=__float2bfloat16(v.y);
    bf hz=__float2bfloat16(v.z), hw=__float2bfloat16(v.w);
    uint2 l;
    l.x = pk2(v.x-__bfloat162float(hx), v.y-__bfloat162float(hy));
    l.y = pk2(v.z-__bfloat162float(hz), v.w-__bfloat162float(hw));
    lo[i]=l;
}

__global__ void t32_f2b(const float* __restrict__ src, bf* __restrict__ dst, int R, int C){
    __shared__ bf t[32][33];
    const float* s = src + (long)blockIdx.z*R*C;
    bf* d = dst + (long)blockIdx.z*R*C;
    int r0 = blockIdx.x*32, c0 = blockIdx.y*32;
    int tx = threadIdx.x & 31, ty = threadIdx.x >> 5;
    #pragma unroll
    for (int i=0;i<4;i++) t[ty+8*i][tx] = __float2bfloat16(s[(long)(r0+ty+8*i)*C + c0+tx]);
    __syncthreads();
    #pragma unroll
    for (int i=0;i<4;i++) d[(long)(c0+ty+8*i)*R + r0+tx] = t[tx][ty+8*i];
}

__global__ void t32_f2b2(const float* __restrict__ src, bf* __restrict__ dh,
                         bf* __restrict__ dl, int R, int C){
    __shared__ bf th[32][33];
    __shared__ bf tl[32][33];
    int r0 = blockIdx.x*32, c0 = blockIdx.y*32;
    int tx = threadIdx.x & 31, ty = threadIdx.x >> 5;
    #pragma unroll
    for (int i=0;i<4;i++){
        float v = src[(long)(r0+ty+8*i)*C + c0+tx];
        bf h = __float2bfloat16(v);
        th[ty+8*i][tx] = h;
        tl[ty+8*i][tx] = __float2bfloat16(v - __bfloat162float(h));
    }
    __syncthreads();
    #pragma unroll
    for (int i=0;i<4;i++){
        dh[(long)(c0+ty+8*i)*R + r0+tx] = th[tx][ty+8*i];
        dl[(long)(c0+ty+8*i)*R + r0+tx] = tl[tx][ty+8*i];
    }
}

__global__ void transpose_b(const bf* __restrict__ src, bf* __restrict__ dst, int R, int C){
    __shared__ bf t[32][33];
    int r0 = blockIdx.x*32, c0 = blockIdx.y*32;
    int tx = threadIdx.x & 31, ty = threadIdx.x >> 5;
    #pragma unroll
    for (int i=0;i<4;i++) t[ty+8*i][tx] = src[(long)(r0+ty+8*i)*C + c0+tx];
    __syncthreads();
    #pragma unroll
    for (int i=0;i<4;i++) dst[(long)(c0+ty+8*i)*R + r0+tx] = t[tx][ty+8*i];
}

// ---------------- elementwise / reduction kernels ----------------
__global__ void embed_norm_k(const int* __restrict__ masked, const float* __restrict__ embed,
                             float* __restrict__ xsa, bf* __restrict__ xsab,
                             bf* __restrict__ xsat, bf* __restrict__ acat)
{
    int t = blockIdx.x;
    int g = masked[t];
    float v = embed[(long)g*Ee + threadIdx.x];
    float mean = block_sum256(v) * (1.f/Ee);
    float d = v - mean;
    float var = block_sum256(d*d) * (1.f/(Ee-1));
    float o = v / (1.f + sqrtf(var));
    xsa [(long)t*Ee + threadIdx.x] = o;
    bf ob = __float2bfloat16(o);
    xsab[(long)t*Ee + threadIdx.x] = ob;
    xsat[(long)threadIdx.x*TOK + t] = ob;
    acat[(long)t*768 + 512 + threadIdx.x] = ob;
}

__global__ void update_norm_k(const float* __restrict__ xsad, const float* __restrict__ t1p,
                              float* __restrict__ xsa, bf* __restrict__ xsab,
                              bf* __restrict__ xsat)
{
    long idx = (long)blockIdx.x*Ee + threadIdx.x;
    const long S = (long)TOK*Ee;
    float u = xsad[idx] + t1p[idx] + t1p[idx+S] + t1p[idx+2*S] + t1p[idx+3*S];
    float mean = block_sum256(u) * (1.f/Ee);
    float d = u - mean;
    float var = block_sum256(d*d) * (1.f/(Ee-1));
    float un = u / (1.f + sqrtf(var));
    float w = xsa[idx] + 0.05f * un;
    float mean2 = block_sum256(w) * (1.f/Ee);
    float d2 = w - mean2;
    float var2 = block_sum256(d2*d2) * (1.f/(Ee-1));
    float o = w / (1.f + sqrtf(var2));
    xsa[idx]  = o;
    bf ob = __float2bfloat16(o);
    xsab[idx] = ob;
    xsat[(long)threadIdx.x*TOK + blockIdx.x] = ob;
}

__global__ void gather_split_k(const int* __restrict__ mask, const float* __restrict__ xsa,
                               bf* __restrict__ hi, bf* __restrict__ lo){
    int r = blockIdx.x; int b = r >> 6; int p = mask[r];
    float v = xsa[(long)(b*Ll + p)*Ee + threadIdx.x];
    bf h = __float2bfloat16(v);
    hi[(long)r*Ee + threadIdx.x] = h;
    lo[(long)r*Ee + threadIdx.x] = __float2bfloat16(v - __bfloat162float(h));
}

__global__ void final_k(const float* __restrict__ tval, const float* __restrict__ lse,
                        float* __restrict__ out)
{
    int b = blockIdx.x, j = threadIdx.x;   // 64 threads
    float a[KN]; float m = -INFINITY;
    #pragma unroll
    for (int kn=0;kn<KN;kn++){
        int r = ((b << 6) + j) * KN + kn;
        a[kn] = tval[r] - lse[r];
        m = fmaxf(m, a[kn]);
    }
    float s = 0.f;
    #pragma unroll
    for (int kn=0;kn<KN;kn++) s += expf(a[kn] - m);
    float cent = m + logf(s) - 1.3862943611198906f;   // - log(4)
    __shared__ float sh[64];
    sh[j] = cent; __syncthreads();
    for (int o=32;o;o>>=1){ if (j<o) sh[j] += sh[j+o]; __syncthreads(); }
    if (j==0) out[b] = -sh[0] / (float)LM;
}

// ---------------- host orchestration ----------------
#define GSYM(p, s) cudaGetSymbolAddress((void**)&p, s)

extern "C" void kernel_launch(void* const* d_in, const int* in_sizes, int n_in,
                              void* d_out, int out_size)
{
    (void)in_sizes; (void)n_in; (void)out_size;
    const int*   masked   = (const int*)  d_in[0];
    const int*   unmasked = (const int*)  d_in[1];
    const int*   maskp    = (const int*)  d_in[2];
    const float* embed    = (const float*)d_in[3];
    const float* Wt       = (const float*)d_in[4];
    const float* bt       = (const float*)d_in[5];
    const float* Wtc      = (const float*)d_in[6];
    const float* Wq       = (const float*)d_in[7];
    const float* Wd       = (const float*)d_in[8];
    const float* Wo       = (const float*)d_in[9];
    const float* Wu       = (const float*)d_in[10];
    const float* Wem      = (const float*)d_in[11];
    const float* Wkc      = (const float*)d_in[12];
    const float* bkc      = (const float*)d_in[13];
    float* out = (float*)d_out;

    float *xsa,*xsad,*t1p,*pm,*ps,*lse,*tval;
    bf *xsab,*xsat,*acat,*q2b,*pb,*yb,*midb;
    bf *wq,*wd,*wot,*wc1,*wc2;
    bf *ehi,*elo,*xhlo,*xtlo,*wkhi,*wklo,*wmhi,*wmlo;
    bf *lphi,*lplo,*x1hi,*x1lo,*shi,*slo,*xxhi,*xxlo,*vhi,*vlo;
    GSYM(xsa,g_xsa); GSYM(xsad,g_xsad); GSYM(t1p,g_t1p);
    GSYM(pm,g_pm); GSYM(ps,g_ps); GSYM(lse,g_lse); GSYM(tval,g_tval);
    GSYM(xsab,g_xsab); GSYM(xsat,g_xsat); GSYM(acat,g_acat);
    GSYM(q2b,g_q2b); GSYM(pb,g_pb); GSYM(yb,g_yb); GSYM(midb,g_midb);
    GSYM(wq,g_wq); GSYM(wd,g_wd); GSYM(wot,g_wot); GSYM(wc1,g_wc1); GSYM(wc2,g_wc2);
    GSYM(ehi,g_ehi); GSYM(elo,g_elo); GSYM(xhlo,g_xhlo); GSYM(xtlo,g_xtlo);
    GSYM(wkhi,g_wkhi); GSYM(wklo,g_wklo); GSYM(wmhi,g_wmhi); GSYM(wmlo,g_wmlo);
    GSYM(lphi,g_lphi); GSYM(lplo,g_lplo);
    GSYM(x1hi,g_x1hi); GSYM(x1lo,g_x1lo); GSYM(shi,g_shi); GSYM(slo,g_slo);
    GSYM(xxhi,g_xxhi); GSYM(xxlo,g_xxlo); GSYM(vhi,g_vhi); GSYM(vlo,g_vlo);

    // kernel instantiations
    auto kS1 = bgemm_k<64,64,32,16,true ,false,4,2,false,1>;   // transitions stage1 -> acat bf16
    auto kS2 = bgemm_k<64,64,32,16,false,true ,0,0,false,0>;   // stage2 -> xsad fp32
    auto kWq = bgemm_k<128,128,64,32,false,false,1,0,false,1>; // q -> q2b (perm)
    auto kPV = bgemm_k<128,128,64,32,false,false,2,0,false,1>; // probs@V -> yb (perm)
    auto kWd = bgemm_k<128,128,64,32,true ,false,0,0,false,1>; // dense+relu -> midb
    auto kWo = bgemm_k<64,64,32,16,false,false,0,0,false,0>;   // split-K -> t1p partials
    auto kG1 = bgemm_k<64,64,32,16,false,true ,3,0,true ,2>;   // kchoice -> xx1 hi/lo (perm)
    auto kG2 = bgemm_k<64,64,32,16,false,false,0,0,true ,2>;   // -> s hi/lo
    auto kG3 = bgemm_k<64,64,32,16,false,false,0,0,true ,2>;   // -> xx hi/lo
    auto kG4 = bgemm_k<64,64,32,16,false,false,0,0,true ,2>;   // -> v hi/lo

    constexpr int SM_BIG = 3*(128+128)*20*4;    // 61440 B
    constexpr int SM_SML = 3*(64+64)*20*4;      // 30720 B
    constexpr int SM_CMP = 3*2*(64+64)*20*4;    // 61440 B
    constexpr int SM_QK  = 3*(64+512)*20*4;     // 138240 B

    cudaFuncSetAttribute(kWq, cudaFuncAttributeMaxDynamicSharedMemorySize, SM_BIG);
    cudaFuncSetAttribute(kPV, cudaFuncAttributeMaxDynamicSharedMemorySize, SM_BIG);
    cudaFuncSetAttribute(kWd, cudaFuncAttributeMaxDynamicSharedMemorySize, SM_BIG);
    cudaFuncSetAttribute(kG1, cudaFuncAttributeMaxDynamicSharedMemorySize, SM_CMP);
    cudaFuncSetAttribute(kG2, cudaFuncAttributeMaxDynamicSharedMemorySize, SM_CMP);
    cudaFuncSetAttribute(kG3, cudaFuncAttributeMaxDynamicSharedMemorySize, SM_CMP);
    cudaFuncSetAttribute(kG4, cudaFuncAttributeMaxDynamicSharedMemorySize, SM_CMP);
    cudaFuncSetAttribute(qk_softmax_k, cudaFuncAttributeMaxDynamicSharedMemorySize, SM_QK);
    cudaFuncSetAttribute(glse_k, cudaFuncAttributeMaxDynamicSharedMemorySize, SM_CMP);

    // ---- prep: bf16 weights (per launch; graph-captured) ----
    prep_w_k<<<(Dd*5*65536+1023)/1024,1024>>>(Wt, Wtc, Wu, wc1, wc2);
    conv_b4<<<((long)Dd*KE*Ee/4+255)/256,256>>>((const float4*)Wq, (uint2*)wq, (long)Dd*KE*Ee/4);
    conv_b4<<<((long)Dd*KE*KE/4+255)/256,256>>>((const float4*)Wd, (uint2*)wd, (long)Dd*KE*KE/4);
    t32_f2b<<<dim3(KE/32,Ee/32,Dd),256>>>(Wo, wot, KE, Ee);
    split_b4<<<((long)Gg*Ee/4+255)/256,256>>>((const float4*)embed, (uint2*)ehi, (uint2*)elo, (long)Gg*Ee/4);
    split_b4<<<(KN*Ee*Ee/4+255)/256,256>>>((const float4*)Wkc, (uint2*)wkhi, (uint2*)wklo, KN*Ee*Ee/4);
    t32_f2b2<<<dim3(Ee/32,Ee/32,1),256>>>(Wem, wmhi, wmlo, Ee, Ee);

    embed_norm_k<<<TOK,256>>>(masked, embed, xsa, xsab, xsat, acat);

    for (int d=0; d<Dd; d++){
        // transitions
        kS1<<<dim3(4,32,2),256,SM_SML>>>(xsab,0, wc1+(long)d*131072,0, 0, 0,acat,0,
                                         TOK,Ee,Ee, Ee,Ee, 0, 65536, 0, 1);
        kS2<<<dim3(4,32,1),256,SM_SML>>>(acat,0, wc2+(long)d*196608,0, bt+(long)d*Ee, xsad,0,0,
                                         TOK,Ee,768, 768,768, 0,0,0, 0);

        // attention (QK + softmax fused)
        kWq<<<dim3(16,16,1),256,SM_BIG>>>(xsab,0, wq+(long)d*KE*Ee,0, 0, 0,q2b,0,
                                          TOK,KE,Ee, Ee,Ee, 0,0,0, 0);
        qk_softmax_k<<<dim3(1,64,Bb),512,SM_QK>>>(q2b, xsab, pb,
                                                  (long)Ll*Kk*Ee, (long)Ll*Ee, (long)Ll*Kk*Ll);
        kPV<<<dim3(2,32,Bb),256,SM_BIG>>>(pb,0, xsat,0, 0, 0,yb,0,
                                          Ll*Kk,Ee,Ll, Ll,TOK,
                                          (long)Ll*Kk*Ll, (long)Ll, 0, 0);

        // dense -> relu -> dense (Wo via split-K=4)
        kWd<<<dim3(16,16,1),256,SM_BIG>>>(yb,0, wd+(long)d*KE*KE,0, 0, 0,midb,0,
                                          TOK,KE,KE, KE,KE, 0,0,0, 0);
        kWo<<<dim3(4,32,4),256,SM_SML>>>(midb,0, wot+(long)d*Ee*KE,0, 0, t1p,0,0,
                                         TOK,Ee,512, KE,KE, 512, 512, (long)TOK*Ee, 0);

        update_norm_k<<<TOK,256>>>(xsad, t1p, xsa, xsab, xsat);
    }

    // ---- head (split-bf16 3-mma; hi of xsa == xsab/xsat) ----
    split_lo4<<<(TOK*Ee/4+255)/256,256>>>((const float4*)xsa, (uint2*)xhlo, TOK*Ee/4);
    transpose_b<<<dim3(TOK/32,Ee/32),256>>>(xhlo, xtlo, TOK, Ee);
    gather_split_k<<<Bb*LM,256>>>(maskp, xsa, lphi, lplo);

    kG1<<<dim3(16,4,1),256,SM_CMP>>>(lphi,lplo, wkhi,wklo, bkc, 0,x1hi,x1lo,
                                     Bb*LM, KN*Ee, Ee, Ee,Ee, 0,0,0, 0);
    kG2<<<dim3(8,4,Bb),256,SM_CMP>>>(x1hi,x1lo, xsab,xhlo, 0, 0,shi,slo,
                                     LM*KN, Ll, Ee, Ee,Ee,
                                     (long)LM*KN*Ee, (long)Ll*Ee, (long)LM*KN*Ll, 0);
    kG3<<<dim3(4,4,Bb),256,SM_CMP>>>(shi,slo, xsat,xtlo, 0, 0,xxhi,xxlo,
                                     LM*KN, Ee, Ll, Ll,TOK,
                                     (long)LM*KN*Ll, (long)Ll, (long)LM*KN*Ee, 0);
    kG4<<<dim3(4,16,1),256,SM_CMP>>>(xxhi,xxlo, wmhi,wmlo, 0, 0,vhi,vlo,
                                     Bb*LM*KN, Ee, Ee, Ee,Ee, 0,0,0, 0);

    // fused logits + LSE (no logits buffer)
    glse_k<<<dim3(500,16,1),256,SM_CMP>>>(vhi, vlo, ehi, elo, pm, ps);
    lse_red_k<<<(Bb*LM*KN)/8,256>>>(pm, ps, lse);
    tval_k<<<Bb*LM*KN,256>>>(vhi, vlo, ehi, elo, unmasked, maskp, tval);
    final_k<<<Bb,64>>>(tval, lse, out);
}

// round 10
// speedup vs baseline: 1.8467x; 1.0188x over previous
#include <cuda_runtime.h>
#include <cuda_bf16.h>
#include <math.h>
#include <stdint.h>

// ---------------- problem constants ----------------
#define Bb 4
#define Ll 512
#define Ee 256
#define Kk 8
#define Dd 6
#define LM 64
#define KN 4
#define Gg 32000
#define KE (Kk*Ee)          // 2048
#define TOK (Bb*Ll)         // 2048

typedef __nv_bfloat16 bf;

// ---------------- scratch (static device memory; no allocations) ----------------
__device__ float g_xsa [TOK*Ee];
__device__ float g_xsad[TOK*Ee];
__device__ float g_t1p [4L*TOK*Ee];                  // kWo split-K partials
__device__ bf    g_xsab[TOK*Ee];                     // xsa bf16 [t][e]
__device__ bf    g_xsat[Ee*TOK];                     // xsa bf16 transposed [e][t]
__device__ bf    g_acat[TOK*768];                    // [t1a | t1b | z] bf16
__device__ bf    g_q2b [TOK*KE];
__device__ bf    g_pb  [(long)Bb*Ll*Kk*Ll];          // softmax probs bf16
__device__ bf    g_yb  [TOK*KE];
__device__ bf    g_midb[TOK*KE];
// bf16 weights (prep)
__device__ bf    g_wq [(long)Dd*KE*Ee];
__device__ bf    g_wd [(long)Dd*KE*KE];
__device__ bf    g_wot[(long)Dd*Ee*KE];              // Wo^T  [n=E][k=KE]
__device__ bf    g_wc1[Dd*2*Ee*Ee];                  // [Wt^T][Wtc] as [n][k]
__device__ bf    g_wc2[Dd*Ee*768];                   // [Wtc^T|Wt|Wu] rows n, k=768
// head hi/lo bf16 splits (hi of xsa == xsab/xsat)
__device__ bf    g_ehi[(long)Gg*Ee], g_elo[(long)Gg*Ee];
__device__ bf    g_xhlo[TOK*Ee];
__device__ bf    g_xtlo[Ee*TOK];
__device__ bf    g_wkhi[KN*Ee*Ee],g_wklo[KN*Ee*Ee];
__device__ bf    g_wmhi[Ee*Ee],   g_wmlo[Ee*Ee];     // Wem^T hi/lo
__device__ bf    g_lphi[Bb*LM*Ee],g_lplo[Bb*LM*Ee];
__device__ bf    g_x1hi[Bb*LM*KN*Ee], g_x1lo[Bb*LM*KN*Ee];
__device__ bf    g_shi[(long)Bb*LM*KN*Ll], g_slo[(long)Bb*LM*KN*Ll];
__device__ bf    g_xxhi[Bb*LM*KN*Ee], g_xxlo[Bb*LM*KN*Ee];
__device__ bf    g_vhi[Bb*LM*KN*Ee],  g_vlo[Bb*LM*KN*Ee];
// fused-LSE partials (1024 rows x 250 col-blocks)
__device__ float g_pm[(long)Bb*LM*KN*250];
__device__ float g_ps[(long)Bb*LM*KN*250];
__device__ float g_lse [Bb*LM*KN];
__device__ float g_tval[Bb*LM*KN];

// ---------------- reductions ----------------
__device__ __forceinline__ float warp_sum(float v){
    #pragma unroll
    for (int o=16;o;o>>=1) v += __shfl_xor_sync(0xffffffffu, v, o);
    return v;
}
__device__ float block_sum256(float v){
    __shared__ float sh[8];
    int lane = threadIdx.x & 31, w = threadIdx.x >> 5;
    v = warp_sum(v);
    if (lane==0) sh[w] = v;
    __syncthreads();
    float r = (threadIdx.x < 8) ? sh[threadIdx.x] : 0.f;
    if (w==0){ r = warp_sum(r); if (lane==0) sh[0]=r; }
    __syncthreads();
    float out = sh[0];
    __syncthreads();
    return out;
}

// ---------------- bf16 / mma / cp.async / ldmatrix helpers ----------------
__device__ __forceinline__ uint32_t pk2(float lo, float hi){
    uint32_t r;
    asm("cvt.rn.bf16x2.f32 %0, %1, %2;" : "=r"(r) : "f"(hi), "f"(lo));
    return r;
}
__device__ __forceinline__ void mma_bf16(float* d, const uint32_t* a, const uint32_t* b){
    asm volatile(
      "mma.sync.aligned.m16n8k16.row.col.f32.bf16.bf16.f32 "
      "{%0,%1,%2,%3}, {%4,%5,%6,%7}, {%8,%9}, {%0,%1,%2,%3};\n"
      : "+f"(d[0]),"+f"(d[1]),"+f"(d[2]),"+f"(d[3])
      : "r"(a[0]),"r"(a[1]),"r"(a[2]),"r"(a[3]), "r"(b[0]),"r"(b[1]));
}
__device__ __forceinline__ void cp16b(void* s, const bf* g){
    uint32_t sa = (uint32_t)__cvta_generic_to_shared(s);
    asm volatile("cp.async.ca.shared.global [%0], [%1], 16;\n" :: "r"(sa), "l"(g));
}
__device__ __forceinline__ void cp_commit(){ asm volatile("cp.async.commit_group;\n" ::); }
template<int W> __device__ __forceinline__ void cp_wait(){ asm volatile("cp.async.wait_group %0;\n" :: "n"(W)); }
__device__ __forceinline__ uint32_t s2u(const void* p){
    uint32_t a;
    asm("{ .reg .u64 t; cvta.to.shared.u64 t, %1; cvt.u32.u64 %0, t; }" : "=r"(a) : "l"(p));
    return a;
}
__device__ __forceinline__ void ldsm4(uint32_t& r0, uint32_t& r1, uint32_t& r2, uint32_t& r3,
                                      uint32_t addr){
    asm volatile("ldmatrix.sync.aligned.m8n8.x4.shared.b16 {%0,%1,%2,%3}, [%4];"
        : "=r"(r0),"=r"(r1),"=r"(r2),"=r"(r3) : "r"(addr));
}
__device__ __forceinline__ void ols_merge(float& m, float& s, float mo, float so){
    float mn = fmaxf(m, mo);
    s = s*expf(m - mn) + so*expf(mo - mn);
    m = mn;
}

// PMODE output index mapping (element index):
template<int PMODE>
__device__ __forceinline__ long out_index(int r, int c, int bz, int N, long sC){
    if (PMODE==0) return (long)bz*sC + (long)r*N + c;
    if (PMODE==1) return (((long)(r>>9))<<20) + ((long)(r&511)<<11) + c;
    if (PMODE==2) return (((long)(bz*512 + (r>>3)))<<11) + ((long)(r&7)<<8) + c;
    if (PMODE==3) return (((long)(r>>6))<<16) + ((long)(r&63)<<10) + c;
    return (long)r*768 + ((long)bz<<8) + c;
}

// ---------------- unified bf16 tensor-core GEMM (3-stage pipeline, ldmatrix) ----------------
template<int BM,int BN,int WM,int WN,bool RELU,bool BIAS,int PMODE,int ROLLMODE,bool COMP,int OUTMODE>
__global__ __launch_bounds__(256, 2)
void bgemm_k(const bf* __restrict__ A, const bf* __restrict__ Alo,
             const bf* __restrict__ B, const bf* __restrict__ Blo,
             const float* __restrict__ bias,
             float* __restrict__ C, bf* __restrict__ Cb, bf* __restrict__ Clo,
             int M, int N, int Kd, int lda, int ldb,
             long sA, long sB, long sC, int rollShift)
{
    constexpr int P   = 20;
    constexpr int NST = COMP ? 2 : 1;
    constexpr int TA  = BM*P, TB = BN*P;
    constexpr int STG = NST*(TA+TB);
    constexpr int MI  = WM/16, NI = WN/8;
    constexpr int NJ  = NI/2;
    constexpr int WCOLS = BN/WN;

    extern __shared__ uint32_t smw[];
    const uint32_t smem_u = s2u(smw);

    const int bz = blockIdx.z;
    const bf* Ap  = A + (long)bz*sA;
    const bf* Alp = COMP ? Alo + (long)bz*sA : nullptr;
    const bf* Bp  = B + (long)bz*sB;
    const bf* Blp = COMP ? Blo + (long)bz*sB : nullptr;

    int rs = 0;
    if (ROLLMODE==2) rs = (bz==0) ? rollShift : -rollShift;

    const int row0 = blockIdx.y*BM, col0 = blockIdx.x*BN;
    const int tid  = threadIdx.x;
    const int warp = tid >> 5, lane = tid & 31;
    const int wy = warp / WCOLS, wx = warp % WCOLS;
    const int g = lane >> 2, c4 = lane & 3;

    uint32_t aoff[MI];
    #pragma unroll
    for (int mi=0; mi<MI; mi++)
        aoff[mi] = (uint32_t)(((wy*WM + mi*16 + (lane & 15))*P + (lane>>4)*4) * 4);
    uint32_t boff[NJ];
    #pragma unroll
    for (int j=0; j<NJ; j++)
        boff[j] = (uint32_t)(((wx*WN + j*16 + ((lane>>4)<<3) + (lane & 7))*P + ((lane>>3)&1)*4) * 4);

    auto load_tile = [&](int kt, int st){
        uint32_t* base = smw + st*STG;
        uint32_t* Ah = base;
        uint32_t* Al = base + TA;
        uint32_t* Bh = base + NST*TA;
        uint32_t* Bl = Bh + TB;
        const int k0 = kt*32;
        #pragma unroll
        for (int i=0;i<BM*4/256;i++){
            int id = tid + i*256; int r = id>>2, q = id&3;
            int gr = row0 + r;
            if (ROLLMODE) gr = (gr & ~511) | ((gr - rs) & 511);
            long go = (long)gr*lda + k0 + 8*q;
            cp16b(Ah + r*P + 4*q, Ap + go);
            if (COMP) cp16b(Al + r*P + 4*q, Alp + go);
        }
        #pragma unroll
        for (int i=0;i<BN*4/256;i++){
            int id = tid + i*256; int n = id>>2, q = id&3;
            long go = (long)(col0+n)*ldb + k0 + 8*q;
            cp16b(Bh + n*P + 4*q, Bp + go);
            if (COMP) cp16b(Bl + n*P + 4*q, Blp + go);
        }
        cp_commit();
    };

    float acc[MI][NI][4];
    #pragma unroll
    for (int i=0;i<MI;i++)
        #pragma unroll
        for (int j=0;j<NI;j++)
            #pragma unroll
            for (int t=0;t<4;t++) acc[i][j][t]=0.f;

    const int nit = Kd/32;
    load_tile(0, 0);
    load_tile(1, 1);

    int st = 0;
    for (int it=0; it<nit; it++){
        if (it+2 < nit){ load_tile(it+2, (it+2)%3); cp_wait<2>(); }
        else if (it+1 < nit){ cp_wait<1>(); }
        else { cp_wait<0>(); }
        __syncthreads();

        const uint32_t AhB = smem_u + (uint32_t)(st*STG*4);
        const uint32_t AlB = AhB + TA*4;
        const uint32_t BhB = AhB + NST*TA*4;
        const uint32_t BlB = BhB + TB*4;

        #pragma unroll
        for (int ks=0; ks<2; ks++){
            const uint32_t ko = ks*32;
            uint32_t af[MI][4], bfr[NI][2];
            uint32_t afl[COMP?MI:1][4], bfl[COMP?NI:1][2];
            #pragma unroll
            for (int mi=0; mi<MI; mi++){
                ldsm4(af[mi][0], af[mi][1], af[mi][2], af[mi][3], AhB + aoff[mi] + ko);
                if (COMP)
                    ldsm4(afl[mi][0], afl[mi][1], afl[mi][2], afl[mi][3], AlB + aoff[mi] + ko);
            }
            #pragma unroll
            for (int j=0; j<NJ; j++){
                ldsm4(bfr[2*j][0], bfr[2*j][1], bfr[2*j+1][0], bfr[2*j+1][1], BhB + boff[j] + ko);
                if (COMP)
                    ldsm4(bfl[2*j][0], bfl[2*j][1], bfl[2*j+1][0], bfl[2*j+1][1], BlB + boff[j] + ko);
            }
            #pragma unroll
            for (int mi=0; mi<MI; mi++)
                #pragma unroll
                for (int ni=0; ni<NI; ni++){
                    if (COMP){
                        mma_bf16(acc[mi][ni], afl[mi], bfr[ni]);
                        mma_bf16(acc[mi][ni], af[mi], bfl[ni]);
                    }
                    mma_bf16(acc[mi][ni], af[mi], bfr[ni]);
                }
        }
        __syncthreads();
        st = (st==2) ? 0 : st+1;
    }

    // ---- epilogue ----
    #pragma unroll
    for (int mi=0; mi<MI; mi++){
        #pragma unroll
        for (int half=0; half<2; half++){
            int r = row0 + wy*WM + mi*16 + g + half*8;
            #pragma unroll
            for (int ni=0; ni<NI; ni++){
                int cc = col0 + wx*WN + ni*8 + 2*c4;
                float v0 = acc[mi][ni][half*2+0];
                float v1 = acc[mi][ni][half*2+1];
                if (BIAS){ v0 += bias[cc]; v1 += bias[cc+1]; }
                if (RELU){ v0 = fmaxf(v0,0.f); v1 = fmaxf(v1,0.f); }
                long idx = out_index<PMODE>(r, cc, bz, N, sC);
                if (OUTMODE==0){
                    *(float2*)(C + idx) = make_float2(v0, v1);
                } else if (OUTMODE==1){
                    *(uint32_t*)(Cb + idx) = pk2(v0, v1);
                } else {
                    bf h0 = __float2bfloat16(v0);
                    bf h1 = __float2bfloat16(v1);
                    union { __nv_bfloat162 b; uint32_t u; } cu;
                    cu.b = __halves2bfloat162(h0, h1);
                    *(uint32_t*)(Cb + idx)  = cu.u;
                    *(uint32_t*)(Clo + idx) = pk2(v0 - __bfloat162float(h0),
                                                  v1 - __bfloat162float(h1));
                }
            }
        }
    }
}

// ---------------- fused QK + softmax ----------------
__global__ __launch_bounds__(512, 1)
void qk_softmax_k(const bf* __restrict__ A, const bf* __restrict__ B,
                  bf* __restrict__ Pout, long sA, long sB, long sC)
{
    constexpr int Pw = 20;
    constexpr int TA = 64*Pw, TB = 512*Pw, STG = TA+TB;
    extern __shared__ uint32_t smw[];
    const uint32_t smem_u = s2u(smw);

    const int bz = blockIdx.z;
    const bf* Ap = A + (long)bz*sA;
    const bf* Bp = B + (long)bz*sB;
    const int row0 = blockIdx.y*64;
    const int tid = threadIdx.x, warp = tid>>5, lane = tid&31;
    const int wy = warp>>3, wx = warp&7;
    const int g = lane>>2, c4 = lane&3;

    uint32_t aoff[2];
    #pragma unroll
    for (int mi=0;mi<2;mi++)
        aoff[mi] = (uint32_t)(((wy*32 + mi*16 + (lane & 15))*Pw + (lane>>4)*4) * 4);
    uint32_t boff[4];
    #pragma unroll
    for (int j=0;j<4;j++)
        boff[j] = (uint32_t)(((wx*64 + j*16 + ((lane>>4)<<3) + (lane & 7))*Pw + ((lane>>3)&1)*4) * 4);

    auto load_tile = [&](int kt, int st){
        uint32_t* base = smw + st*STG;
        uint32_t* Ah = base;
        uint32_t* Bh = base + TA;
        const int k0 = kt*32;
        if (tid < 256){
            int r = tid>>2, q = tid&3;
            cp16b(Ah + r*Pw + 4*q, Ap + (long)(row0+r)*256 + k0 + 8*q);
        }
        #pragma unroll
        for (int i=0;i<4;i++){
            int id = tid + i*512; int n = id>>2, q = id&3;
            cp16b(Bh + n*Pw + 4*q, Bp + (long)n*256 + k0 + 8*q);
        }
        cp_commit();
    };

    float acc[2][8][4];
    #pragma unroll
    for (int i=0;i<2;i++)
        #pragma unroll
        for (int j=0;j<8;j++)
            #pragma unroll
            for (int t=0;t<4;t++) acc[i][j][t]=0.f;

    const int nit = 8;
    load_tile(0, 0);
    load_tile(1, 1);
    int st = 0;
    for (int it=0; it<nit; it++){
        if (it+2 < nit){ load_tile(it+2, (it+2)%3); cp_wait<2>(); }
        else if (it+1 < nit){ cp_wait<1>(); }
        else { cp_wait<0>(); }
        __syncthreads();

        const uint32_t AhB = smem_u + (uint32_t)(st*STG*4);
        const uint32_t BhB = AhB + TA*4;
        #pragma unroll
        for (int ks=0; ks<2; ks++){
            const uint32_t ko = ks*32;
            uint32_t af[2][4], bfr[8][2];
            #pragma unroll
            for (int mi=0; mi<2; mi++)
                ldsm4(af[mi][0], af[mi][1], af[mi][2], af[mi][3], AhB + aoff[mi] + ko);
            #pragma unroll
            for (int j=0; j<4; j++)
                ldsm4(bfr[2*j][0], bfr[2*j][1], bfr[2*j+1][0], bfr[2*j+1][1], BhB + boff[j] + ko);
            #pragma unroll
            for (int mi=0; mi<2; mi++)
                #pragma unroll
                for (int ni=0; ni<8; ni++)
                    mma_bf16(acc[mi][ni], af[mi], bfr[ni]);
        }
        __syncthreads();
        st = (st==2) ? 0 : st+1;
    }

    float* red_m = (float*)smw;
    float* red_s = red_m + 64*8;
    #pragma unroll
    for (int mi=0; mi<2; mi++){
        #pragma unroll
        for (int half=0; half<2; half++){
            float mx = -INFINITY;
            #pragma unroll
            for (int ni=0; ni<8; ni++)
                mx = fmaxf(mx, fmaxf(acc[mi][ni][half*2], acc[mi][ni][half*2+1]));
            mx *= 0.0625f;
            float s = 0.f;
            #pragma unroll
            for (int ni=0; ni<8; ni++){
                s += expf(acc[mi][ni][half*2+0]*0.0625f - mx);
                s += expf(acc[mi][ni][half*2+1]*0.0625f - mx);
            }
            float m = mx;
            #pragma unroll
            for (int o=1; o<=2; o<<=1){
                float mo = __shfl_xor_sync(0xffffffffu, m, o);
                float so = __shfl_xor_sync(0xffffffffu, s, o);
                ols_merge(m, s, mo, so);
            }
            int rt = wy*32 + mi*16 + half*8 + g;
            if (c4==0){ red_m[rt*8+wx] = m; red_s[rt*8+wx] = s; }
        }
    }
    __syncthreads();
    if (tid < 64){
        float M = red_m[tid*8], S = red_s[tid*8];
        #pragma unroll
        for (int i=1;i<8;i++) ols_merge(M, S, red_m[tid*8+i], red_s[tid*8+i]);
        red_m[tid*8] = M;
        red_s[tid*8] = 1.f/S;
    }
    __syncthreads();
    #pragma unroll
    for (int mi=0; mi<2; mi++){
        #pragma unroll
        for (int half=0; half<2; half++){
            int rt = wy*32 + mi*16 + half*8 + g;
            float M = red_m[rt*8], inv = red_s[rt*8];
            long rowbase = (long)bz*sC + (long)(row0+rt)*512;
            #pragma unroll
            for (int ni=0; ni<8; ni++){
                int c = wx*64 + ni*8 + 2*c4;
                float p0 = expf(acc[mi][ni][half*2+0]*0.0625f - M)*inv;
                float p1 = expf(acc[mi][ni][half*2+1]*0.0625f - M)*inv;
                *(uint32_t*)(Pout + rowbase + c) = pk2(p0, p1);
            }
        }
    }
}

// ---------------- fused logits GEMM + online-LSE partials (COMP, 128x128 tiles) ----------------
// A = v hi/lo [1024][256], B = embed hi/lo [32000][256].
// Per-block per-row (m,s) partials to pm/ps [row][250]. Warp tile 64x32 (MI=4,NI=4).
__global__ __launch_bounds__(256, 1)
void glse_k(const bf* __restrict__ A, const bf* __restrict__ Alo,
            const bf* __restrict__ B, const bf* __restrict__ Blo,
            float* __restrict__ pm, float* __restrict__ ps)
{
    constexpr int Pw = 20;
    constexpr int TA = 128*Pw, TB = 128*Pw;
    constexpr int STG = 2*(TA+TB);
    extern __shared__ uint32_t smw[];
    const uint32_t smem_u = s2u(smw);

    const int row0 = blockIdx.y*128, col0 = blockIdx.x*128, bx = blockIdx.x;
    const int tid = threadIdx.x, warp = tid>>5, lane = tid&31;
    const int wy = warp>>2, wx = warp&3;     // WM=64, WN=32
    const int g = lane>>2, c4 = lane&3;

    uint32_t aoff[4];
    #pragma unroll
    for (int mi=0;mi<4;mi++)
        aoff[mi] = (uint32_t)(((wy*64 + mi*16 + (lane & 15))*Pw + (lane>>4)*4) * 4);
    uint32_t boff[2];
    #pragma unroll
    for (int j=0;j<2;j++)
        boff[j] = (uint32_t)(((wx*32 + j*16 + ((lane>>4)<<3) + (lane & 7))*Pw + ((lane>>3)&1)*4) * 4);

    auto load_tile = [&](int kt, int st){
        uint32_t* base = smw + st*STG;
        uint32_t* Ah = base;
        uint32_t* Al = base + TA;
        uint32_t* Bh = base + 2*TA;
        uint32_t* Bl = Bh + TB;
        const int k0 = kt*32;
        #pragma unroll
        for (int i=0;i<2;i++){
            int id = tid + i*256; int r = id>>2, q = id&3;
            long go = (long)(row0+r)*256 + k0 + 8*q;
            cp16b(Ah + r*Pw + 4*q, A + go);
            cp16b(Al + r*Pw + 4*q, Alo + go);
            long gb = (long)(col0+r)*256 + k0 + 8*q;
            cp16b(Bh + r*Pw + 4*q, B + gb);
            cp16b(Bl + r*Pw + 4*q, Blo + gb);
        }
        cp_commit();
    };

    float acc[4][4][4];
    #pragma unroll
    for (int i=0;i<4;i++)
        #pragma unroll
        for (int j=0;j<4;j++)
            #pragma unroll
            for (int t=0;t<4;t++) acc[i][j][t]=0.f;

    const int nit = 8;   // K=256
    load_tile(0, 0);
    int st = 0;
    for (int it=0; it<nit; it++){
        if (it+1 < nit){ load_tile(it+1, (it+1)&1); cp_wait<1>(); }
        else { cp_wait<0>(); }
        __syncthreads();

        const uint32_t AhB = smem_u + (uint32_t)(st*STG*4);
        const uint32_t AlB = AhB + TA*4;
        const uint32_t BhB = AhB + 2*TA*4;
        const uint32_t BlB = BhB + TB*4;
        #pragma unroll
        for (int ks=0; ks<2; ks++){
            const uint32_t ko = ks*32;
            uint32_t af[4][4], afl[4][4], bfr[4][2], bfl[4][2];
            #pragma unroll
            for (int mi=0; mi<4; mi++){
                ldsm4(af[mi][0], af[mi][1], af[mi][2], af[mi][3], AhB + aoff[mi] + ko);
                ldsm4(afl[mi][0], afl[mi][1], afl[mi][2], afl[mi][3], AlB + aoff[mi] + ko);
            }
            #pragma unroll
            for (int j=0; j<2; j++){
                ldsm4(bfr[2*j][0], bfr[2*j][1], bfr[2*j+1][0], bfr[2*j+1][1], BhB + boff[j] + ko);
                ldsm4(bfl[2*j][0], bfl[2*j][1], bfl[2*j+1][0], bfl[2*j+1][1], BlB + boff[j] + ko);
            }
            #pragma unroll
            for (int mi=0; mi<4; mi++)
                #pragma unroll
                for (int ni=0; ni<4; ni++){
                    mma_bf16(acc[mi][ni], afl[mi], bfr[ni]);
                    mma_bf16(acc[mi][ni], af[mi], bfl[ni]);
                    mma_bf16(acc[mi][ni], af[mi], bfr[ni]);
                }
        }
        __syncthreads();
        st ^= 1;
    }

    // ---- online-LSE partial epilogue (reduce 128 cols per row) ----
    float* red_m = (float*)smw;       // [128][4]
    float* red_s = red_m + 128*4;
    #pragma unroll
    for (int mi=0; mi<4; mi++){
        #pragma unroll
        for (int half=0; half<2; half++){
            float mx = -INFINITY;
            #pragma unroll
            for (int ni=0; ni<4; ni++)
                mx = fmaxf(mx, fmaxf(acc[mi][ni][half*2], acc[mi][ni][half*2+1]));
            float s = 0.f;
            #pragma unroll
            for (int ni=0; ni<4; ni++){
                s += expf(acc[mi][ni][half*2+0]-mx);
                s += expf(acc[mi][ni][half*2+1]-mx);
            }
            float m = mx;
            #pragma unroll
            for (int o=1; o<=2; o<<=1){
                float mo = __shfl_xor_sync(0xffffffffu, m, o);
                float so = __shfl_xor_sync(0xffffffffu, s, o);
                ols_merge(m, s, mo, so);
            }
            int rt = wy*64 + mi*16 + half*8 + g;
            if (c4==0){ red_m[rt*4+wx] = m; red_s[rt*4+wx] = s; }
        }
    }
    __syncthreads();
    if (tid < 128){
        float M = red_m[tid*4], S = red_s[tid*4];
        #pragma unroll
        for (int i=1;i<4;i++) ols_merge(M, S, red_m[tid*4+i], red_s[tid*4+i]);
        long idx = (long)(row0+tid)*250 + bx;
        pm[idx] = M;
        ps[idx] = S;
    }
}

// merge 250 partials per row -> lse
__global__ void lse_red_k(const float* __restrict__ pm, const float* __restrict__ ps,
                          float* __restrict__ lse){
    int row = blockIdx.x*8 + (threadIdx.x>>5);
    int lane = threadIdx.x & 31;
    float m = -INFINITY, s = 0.f;
    for (int i=lane; i<250; i+=32)
        ols_merge(m, s, pm[(long)row*250+i], ps[(long)row*250+i]);
    #pragma unroll
    for (int o=16;o;o>>=1){
        float mo = __shfl_xor_sync(0xffffffffu, m, o);
        float so = __shfl_xor_sync(0xffffffffu, s, o);
        ols_merge(m, s, mo, so);
    }
    if (lane==0) lse[row] = m + logf(s);
}

// exact fp32 target logit: dot(v[row], embed[tg]) from hi/lo reconstructions
__global__ void tval_k(const bf* __restrict__ vhi, const bf* __restrict__ vlo,
                       const bf* __restrict__ ehi, const bf* __restrict__ elo,
                       const int* __restrict__ unmasked, const int* __restrict__ mask,
                       float* __restrict__ tval){
    int row = blockIdx.x;
    int b = row >> 8, n = row & 255, j = n >> 2;
    int tg = unmasked[b*Ll + mask[b*LM + j]];
    long vi = (long)row*Ee + threadIdx.x;
    long ei = (long)tg*Ee + threadIdx.x;
    float v = (__bfloat162float(vhi[vi]) + __bfloat162float(vlo[vi]))
            * (__bfloat162float(ehi[ei]) + __bfloat162float(elo[ei]));
    float s = block_sum256(v);
    if (threadIdx.x==0) tval[row] = s;
}

// ---------------- prep kernels ----------------
__global__ void prep_w_k(const float* __restrict__ Wt, const float* __restrict__ Wtc,
                         const float* __restrict__ Wu,
                         bf* __restrict__ wc1, bf* __restrict__ wc2)
{
    long idx = (long)blockIdx.x*1024 + threadIdx.x;
    if (idx >= (long)Dd*5*65536) return;
    int d = idx / (5*65536);
    int r = idx % (5*65536);
    int which = r / 65536;
    int e = r % 65536;
    int n = e >> 8, k = e & 255;
    long wb = (long)d*65536;
    if      (which==0) wc1[(long)d*131072 +         n*256+k] = __float2bfloat16(Wt [wb + (long)k*256 + n]);
    else if (which==1) wc1[(long)d*131072 + 65536 + n*256+k] = __float2bfloat16(Wtc[wb + (long)n*256 + k]);
    else if (which==2) wc2[(long)d*196608 + (long)n*768 +       k] = __float2bfloat16(Wtc[wb + (long)k*256 + n]);
    else if (which==3) wc2[(long)d*196608 + (long)n*768 + 256 + k] = __float2bfloat16(Wt [wb + (long)n*256 + k]);
    else               wc2[(long)d*196608 + (long)n*768 + 512 + k] = __float2bfloat16(Wu [wb + (long)n*256 + k]);
}

__global__ void conv_b4(const float4* __restrict__ in, uint2* __restrict__ outp, long n4){
    long i = (long)blockIdx.x*256 + threadIdx.x;
    if (i >= n4) return;
    float4 v = in[i];
    uint2 o; o.x = pk2(v.x, v.y); o.y = pk2(v.z, v.w);
    outp[i] = o;
}

__global__ void split_b4(const float4* __restrict__ in, uint2* __restrict__ hi,
                         uint2* __restrict__ lo, long n4){
    long i = (long)blockIdx.x*256 + threadIdx.x;
    if (i >= n4) return;
    float4 v = in[i];
    bf hx=__float2bfloat16(v.x), hy=__float2bfloat16(v.y);
    bf hz=__float2bfloat16(v.z), hw=__float2bfloat16(v.w);
    union { __nv_bfloat162 b; uint32_t u; } c0, c1;
    c0.b = __halves2bfloat162(hx, hy);
    c1.b = __halves2bfloat162(hz, hw);
    uint2 h; h.x=c0.u; h.y=c1.u;
    uint2 l;
    l.x = pk2(v.x-__bfloat162float(hx), v.y-__bfloat162float(hy));
    l.y = pk2(v.z-__bfloat162float(hz), v.w-__bfloat162float(hw));
    hi[i]=h; lo[i]=l;
}

__global__ void split_lo4(const float4* __restrict__ in, uint2* __restrict__ lo, long n4){
    long i = (long)blockIdx.x*256 + threadIdx.x;
    if (i >= n4) return;
    float4 v = in[i];
    bf hx=__float2bfloat16(v.x), hy=__float2bfloat16(v.y);
    bf hz=__float2bfloat16(v.z), hw=__float2bfloat16(v.w);
    uint2 l;
    l.x = pk2(v.x-__bfloat162float(hx), v.y-__bfloat162float(hy));
    l.y = pk2(v.z-__bfloat162float(hz), v.w-__bfloat162float(hw));
    lo[i]=l;
}

__global__ void t32_f2b(const float* __restrict__ src, bf* __restrict__ dst, int R, int C){
    __shared__ bf t[32][33];
    const float* s = src + (long)blockIdx.z*R*C;
    bf* d = dst + (long)blockIdx.z*R*C;
    int r0 = blockIdx.x*32, c0 = blockIdx.y*32;
    int tx = threadIdx.x & 31, ty = threadIdx.x >> 5;
    #pragma unroll
    for (int i=0;i<4;i++) t[ty+8*i][tx] = __float2bfloat16(s[(long)(r0+ty+8*i)*C + c0+tx]);
    __syncthreads();
    #pragma unroll
    for (int i=0;i<4;i++) d[(long)(c0+ty+8*i)*R + r0+tx] = t[tx][ty+8*i];
}

__global__ void t32_f2b2(const float* __restrict__ src, bf* __restrict__ dh,
                         bf* __restrict__ dl, int R, int C){
    __shared__ bf th[32][33];
    __shared__ bf tl[32][33];
    int r0 = blockIdx.x*32, c0 = blockIdx.y*32;
    int tx = threadIdx.x & 31, ty = threadIdx.x >> 5;
    #pragma unroll
    for (int i=0;i<4;i++){
        float v = src[(long)(r0+ty+8*i)*C + c0+tx];
        bf h = __float2bfloat16(v);
        th[ty+8*i][tx] = h;
        tl[ty+8*i][tx] = __float2bfloat16(v - __bfloat162float(h));
    }
    __syncthreads();
    #pragma unroll
    for (int i=0;i<4;i++){
        dh[(long)(c0+ty+8*i)*R + r0+tx] = th[tx][ty+8*i];
        dl[(long)(c0+ty+8*i)*R + r0+tx] = tl[tx][ty+8*i];
    }
}

__global__ void transpose_b(const bf* __restrict__ src, bf* __restrict__ dst, int R, int C){
    __shared__ bf t[32][33];
    int r0 = blockIdx.x*32, c0 = blockIdx.y*32;
    int tx = threadIdx.x & 31, ty = threadIdx.x >> 5;
    #pragma unroll
    for (int i=0;i<4;i++) t[ty+8*i][tx] = src[(long)(r0+ty+8*i)*C + c0+tx];
    __syncthreads();
    #pragma unroll
    for (int i=0;i<4;i++) dst[(long)(c0+ty+8*i)*R + r0+tx] = t[tx][ty+8*i];
}

// ---------------- elementwise / reduction kernels ----------------
__global__ void embed_norm_k(const int* __restrict__ masked, const float* __restrict__ embed,
                             float* __restrict__ xsa, bf* __restrict__ xsab,
                             bf* __restrict__ xsat, bf* __restrict__ acat)
{
    int t = blockIdx.x;
    int g = masked[t];
    float v = embed[(long)g*Ee + threadIdx.x];
    float mean = block_sum256(v) * (1.f/Ee);
    float d = v - mean;
    float var = block_sum256(d*d) * (1.f/(Ee-1));
    float o = v / (1.f + sqrtf(var));
    xsa [(long)t*Ee + threadIdx.x] = o;
    bf ob = __float2bfloat16(o);
    xsab[(long)t*Ee + threadIdx.x] = ob;
    xsat[(long)threadIdx.x*TOK + t] = ob;
    acat[(long)t*768 + 512 + threadIdx.x] = ob;
}

__global__ void update_norm_k(const float* __restrict__ xsad, const float* __restrict__ t1p,
                              float* __restrict__ xsa, bf* __restrict__ xsab,
                              bf* __restrict__ xsat)
{
    long idx = (long)blockIdx.x*Ee + threadIdx.x;
    const long S = (long)TOK*Ee;
    float u = xsad[idx] + t1p[idx] + t1p[idx+S] + t1p[idx+2*S] + t1p[idx+3*S];
    float mean = block_sum256(u) * (1.f/Ee);
    float d = u - mean;
    float var = block_sum256(d*d) * (1.f/(Ee-1));
    float un = u / (1.f + sqrtf(var));
    float w = xsa[idx] + 0.05f * un;
    float mean2 = block_sum256(w) * (1.f/Ee);
    float d2 = w - mean2;
    float var2 = block_sum256(d2*d2) * (1.f/(Ee-1));
    float o = w / (1.f + sqrtf(var2));
    xsa[idx]  = o;
    bf ob = __float2bfloat16(o);
    xsab[idx] = ob;
    xsat[(long)threadIdx.x*TOK + blockIdx.x] = ob;
}

__global__ void gather_split_k(const int* __restrict__ mask, const float* __restrict__ xsa,
                               bf* __restrict__ hi, bf* __restrict__ lo){
    int r = blockIdx.x; int b = r >> 6; int p = mask[r];
    float v = xsa[(long)(b*Ll + p)*Ee + threadIdx.x];
    bf h = __float2bfloat16(v);
    hi[(long)r*Ee + threadIdx.x] = h;
    lo[(long)r*Ee + threadIdx.x] = __float2bfloat16(v - __bfloat162float(h));
}

__global__ void final_k(const float* __restrict__ tval, const float* __restrict__ lse,
                        float* __restrict__ out)
{
    int b = blockIdx.x, j = threadIdx.x;   // 64 threads
    float a[KN]; float m = -INFINITY;
    #pragma unroll
    for (int kn=0;kn<KN;kn++){
        int r = ((b << 6) + j) * KN + kn;
        a[kn] = tval[r] - lse[r];
        m = fmaxf(m, a[kn]);
    }
    float s = 0.f;
    #pragma unroll
    for (int kn=0;kn<KN;kn++) s += expf(a[kn] - m);
    float cent = m + logf(s) - 1.3862943611198906f;   // - log(4)
    __shared__ float sh[64];
    sh[j] = cent; __syncthreads();
    for (int o=32;o;o>>=1){ if (j<o) sh[j] += sh[j+o]; __syncthreads(); }
    if (j==0) out[b] = -sh[0] / (float)LM;
}

// ---------------- host orchestration ----------------
#define GSYM(p, s) cudaGetSymbolAddress((void**)&p, s)

extern "C" void kernel_launch(void* const* d_in, const int* in_sizes, int n_in,
                              void* d_out, int out_size)
{
    (void)in_sizes; (void)n_in; (void)out_size;
    const int*   masked   = (const int*)  d_in[0];
    const int*   unmasked = (const int*)  d_in[1];
    const int*   maskp    = (const int*)  d_in[2];
    const float* embed    = (const float*)d_in[3];
    const float* Wt       = (const float*)d_in[4];
    const float* bt       = (const float*)d_in[5];
    const float* Wtc      = (const float*)d_in[6];
    const float* Wq       = (const float*)d_in[7];
    const float* Wd       = (const float*)d_in[8];
    const float* Wo       = (const float*)d_in[9];
    const float* Wu       = (const float*)d_in[10];
    const float* Wem      = (const float*)d_in[11];
    const float* Wkc      = (const float*)d_in[12];
    const float* bkc      = (const float*)d_in[13];
    float* out = (float*)d_out;

    float *xsa,*xsad,*t1p,*pm,*ps,*lse,*tval;
    bf *xsab,*xsat,*acat,*q2b,*pb,*yb,*midb;
    bf *wq,*wd,*wot,*wc1,*wc2;
    bf *ehi,*elo,*xhlo,*xtlo,*wkhi,*wklo,*wmhi,*wmlo;
    bf *lphi,*lplo,*x1hi,*x1lo,*shi,*slo,*xxhi,*xxlo,*vhi,*vlo;
    GSYM(xsa,g_xsa); GSYM(xsad,g_xsad); GSYM(t1p,g_t1p);
    GSYM(pm,g_pm); GSYM(ps,g_ps); GSYM(lse,g_lse); GSYM(tval,g_tval);
    GSYM(xsab,g_xsab); GSYM(xsat,g_xsat); GSYM(acat,g_acat);
    GSYM(q2b,g_q2b); GSYM(pb,g_pb); GSYM(yb,g_yb); GSYM(midb,g_midb);
    GSYM(wq,g_wq); GSYM(wd,g_wd); GSYM(wot,g_wot); GSYM(wc1,g_wc1); GSYM(wc2,g_wc2);
    GSYM(ehi,g_ehi); GSYM(elo,g_elo); GSYM(xhlo,g_xhlo); GSYM(xtlo,g_xtlo);
    GSYM(wkhi,g_wkhi); GSYM(wklo,g_wklo); GSYM(wmhi,g_wmhi); GSYM(wmlo,g_wmlo);
    GSYM(lphi,g_lphi); GSYM(lplo,g_lplo);
    GSYM(x1hi,g_x1hi); GSYM(x1lo,g_x1lo); GSYM(shi,g_shi); GSYM(slo,g_slo);
    GSYM(xxhi,g_xxhi); GSYM(xxlo,g_xxlo); GSYM(vhi,g_vhi); GSYM(vlo,g_vlo);

    // kernel instantiations
    auto kS1 = bgemm_k<64,64,32,16,true ,false,4,2,false,1>;   // transitions stage1 -> acat bf16
    auto kS2 = bgemm_k<64,64,32,16,false,true ,0,0,false,0>;   // stage2 -> xsad fp32
    auto kWq = bgemm_k<128,128,64,32,false,false,1,0,false,1>; // q -> q2b (perm)
    auto kPV = bgemm_k<128,128,64,32,false,false,2,0,false,1>; // probs@V -> yb (perm)
    auto kWd = bgemm_k<128,128,64,32,true ,false,0,0,false,1>; // dense+relu -> midb
    auto kWo = bgemm_k<64,64,32,16,false,false,0,0,false,0>;   // split-K -> t1p partials
    auto kG1 = bgemm_k<64,64,32,16,false,true ,3,0,true ,2>;   // kchoice -> xx1 hi/lo (perm)
    auto kG2 = bgemm_k<64,64,32,16,false,false,0,0,true ,2>;   // -> s hi/lo
    auto kG3 = bgemm_k<64,64,32,16,false,false,0,0,true ,2>;   // -> xx hi/lo
    auto kG4 = bgemm_k<64,64,32,16,false,false,0,0,true ,2>;   // -> v hi/lo

    constexpr int SM_BIG  = 3*(128+128)*20*4;    // 61440 B
    constexpr int SM_SML  = 3*(64+64)*20*4;      // 30720 B
    constexpr int SM_CMP  = 3*2*(64+64)*20*4;    // 61440 B
    constexpr int SM_QK   = 3*(64+512)*20*4;     // 138240 B
    constexpr int SM_GLSE = 2*2*(128+128)*20*4;  // 81920 B

    cudaFuncSetAttribute(kWq, cudaFuncAttributeMaxDynamicSharedMemorySize, SM_BIG);
    cudaFuncSetAttribute(kPV, cudaFuncAttributeMaxDynamicSharedMemorySize, SM_BIG);
    cudaFuncSetAttribute(kWd, cudaFuncAttributeMaxDynamicSharedMemorySize, SM_BIG);
    cudaFuncSetAttribute(kG1, cudaFuncAttributeMaxDynamicSharedMemorySize, SM_CMP);
    cudaFuncSetAttribute(kG2, cudaFuncAttributeMaxDynamicSharedMemorySize, SM_CMP);
    cudaFuncSetAttribute(kG3, cudaFuncAttributeMaxDynamicSharedMemorySize, SM_CMP);
    cudaFuncSetAttribute(kG4, cudaFuncAttributeMaxDynamicSharedMemorySize, SM_CMP);
    cudaFuncSetAttribute(qk_softmax_k, cudaFuncAttributeMaxDynamicSharedMemorySize, SM_QK);
    cudaFuncSetAttribute(glse_k, cudaFuncAttributeMaxDynamicSharedMemorySize, SM_GLSE);

    // ---- prep: bf16 weights (per launch; graph-captured) ----
    prep_w_k<<<(Dd*5*65536+1023)/1024,1024>>>(Wt, Wtc, Wu, wc1, wc2);
    conv_b4<<<((long)Dd*KE*Ee/4+255)/256,256>>>((const float4*)Wq, (uint2*)wq, (long)Dd*KE*Ee/4);
    conv_b4<<<((long)Dd*KE*KE/4+255)/256,256>>>((const float4*)Wd, (uint2*)wd, (long)Dd*KE*KE/4);
    t32_f2b<<<dim3(KE/32,Ee/32,Dd),256>>>(Wo, wot, KE, Ee);
    split_b4<<<((long)Gg*Ee/4+255)/256,256>>>((const float4*)embed, (uint2*)ehi, (uint2*)elo, (long)Gg*Ee/4);
    split_b4<<<(KN*Ee*Ee/4+255)/256,256>>>((const float4*)Wkc, (uint2*)wkhi, (uint2*)wklo, KN*Ee*Ee/4);
    t32_f2b2<<<dim3(Ee/32,Ee/32,1),256>>>(Wem, wmhi, wmlo, Ee, Ee);

    embed_norm_k<<<TOK,256>>>(masked, embed, xsa, xsab, xsat, acat);

    for (int d=0; d<Dd; d++){
        // transitions
        kS1<<<dim3(4,32,2),256,SM_SML>>>(xsab,0, wc1+(long)d*131072,0, 0, 0,acat,0,
                                         TOK,Ee,Ee, Ee,Ee, 0, 65536, 0, 1);
        kS2<<<dim3(4,32,1),256,SM_SML>>>(acat,0, wc2+(long)d*196608,0, bt+(long)d*Ee, xsad,0,0,
                                         TOK,Ee,768, 768,768, 0,0,0, 0);

        // attention (QK + softmax fused)
        kWq<<<dim3(16,16,1),256,SM_BIG>>>(xsab,0, wq+(long)d*KE*Ee,0, 0, 0,q2b,0,
                                          TOK,KE,Ee, Ee,Ee, 0,0,0, 0);
        qk_softmax_k<<<dim3(1,64,Bb),512,SM_QK>>>(q2b, xsab, pb,
                                                  (long)Ll*Kk*Ee, (long)Ll*Ee, (long)Ll*Kk*Ll);
        kPV<<<dim3(2,32,Bb),256,SM_BIG>>>(pb,0, xsat,0, 0, 0,yb,0,
                                          Ll*Kk,Ee,Ll, Ll,TOK,
                                          (long)Ll*Kk*Ll, (long)Ll, 0, 0);

        // dense -> relu -> dense (Wo via split-K=4)
        kWd<<<dim3(16,16,1),256,SM_BIG>>>(yb,0, wd+(long)d*KE*KE,0, 0, 0,midb,0,
                                          TOK,KE,KE, KE,KE, 0,0,0, 0);
        kWo<<<dim3(4,32,4),256,SM_SML>>>(midb,0, wot+(long)d*Ee*KE,0, 0, t1p,0,0,
                                         TOK,Ee,512, KE,KE, 512, 512, (long)TOK*Ee, 0);

        update_norm_k<<<TOK,256>>>(xsad, t1p, xsa, xsab, xsat);
    }

    // ---- head (split-bf16 3-mma; hi of xsa == xsab/xsat) ----
    split_lo4<<<(TOK*Ee/4+255)/256,256>>>((const float4*)xsa, (uint2*)xhlo, TOK*Ee/4);
    transpose_b<<<dim3(TOK/32,Ee/32),256>>>(xhlo, xtlo, TOK, Ee);
    gather_split_k<<<Bb*LM,256>>>(maskp, xsa, lphi, lplo);

    kG1<<<dim3(16,4,1),256,SM_CMP>>>(lphi,lplo, wkhi,wklo, bkc, 0,x1hi,x1lo,
                                     Bb*LM, KN*Ee, Ee, Ee,Ee, 0,0,0, 0);
    kG2<<<dim3(8,4,Bb),256,SM_CMP>>>(x1hi,x1lo, xsab,xhlo, 0, 0,shi,slo,
                                     LM*KN, Ll, Ee, Ee,Ee,
                                     (long)LM*KN*Ee, (long)Ll*Ee, (long)LM*KN*Ll, 0);
    kG3<<<dim3(4,4,Bb),256,SM_CMP>>>(shi,slo, xsat,xtlo, 0, 0,xxhi,xxlo,
                                     LM*KN, Ee, Ll, Ll,TOK,
                                     (long)LM*KN*Ll, (long)Ll, (long)LM*KN*Ee, 0);
    kG4<<<dim3(4,16,1),256,SM_CMP>>>(xxhi,xxlo, wmhi,wmlo, 0, 0,vhi,vlo,
                                     Bb*LM*KN, Ee, Ee, Ee,Ee, 0,0,0, 0);

    // fused logits + LSE (no logits buffer), 128x128 tiles
    glse_k<<<dim3(250,8,1),256,SM_GLSE>>>(vhi, vlo, ehi, elo, pm, ps);
    lse_red_k<<<(Bb*LM*KN)/8,256>>>(pm, ps, lse);
    tval_k<<<Bb*LM*KN,256>>>(vhi, vlo, ehi, elo, unmasked, maskp, tval);
    final_k<<<Bb,64>>>(tval, lse, out);
}

// round 12
// speedup vs baseline: 1.8602x; 1.0073x over previous
#include <cuda_runtime.h>
#include <cuda_bf16.h>
#include <math.h>
#include <stdint.h>

// ---------------- problem constants ----------------
#define Bb 4
#define Ll 512
#define Ee 256
#define Kk 8
#define Dd 6
#define LM 64
#define KN 4
#define Gg 32000
#define KE (Kk*Ee)          // 2048
#define TOK (Bb*Ll)         // 2048

typedef __nv_bfloat16 bf;

// ---------------- scratch (static device memory; no allocations) ----------------
__device__ float g_xsa [TOK*Ee];
__device__ float g_xsad[TOK*Ee];
__device__ float g_t1p [4L*TOK*Ee];                  // kWo split-K partials
__device__ bf    g_xsab[TOK*Ee];                     // xsa bf16 [t][e]
__device__ bf    g_xsat[Ee*TOK];                     // xsa bf16 transposed [e][t]
__device__ bf    g_acat[TOK*768];                    // [t1a | t1b | z] bf16
__device__ bf    g_q2b [TOK*KE];
__device__ bf    g_yb  [TOK*KE];
__device__ bf    g_midb[TOK*KE];
// bf16 weights (prep)
__device__ bf    g_wq [(long)Dd*KE*Ee];
__device__ bf    g_wd [(long)Dd*KE*KE];
__device__ bf    g_wot[(long)Dd*Ee*KE];              // Wo^T  [n=E][k=KE]
__device__ bf    g_wc1[Dd*2*Ee*Ee];                  // [Wt^T][Wtc] as [n][k]
__device__ bf    g_wc2[Dd*Ee*768];                   // [Wtc^T|Wt|Wu] rows n, k=768
// head hi/lo bf16 splits (hi of xsa == xsab/xsat)
__device__ bf    g_ehi[(long)Gg*Ee], g_elo[(long)Gg*Ee];
__device__ bf    g_xhlo[TOK*Ee];
__device__ bf    g_xtlo[Ee*TOK];
__device__ bf    g_wkhi[KN*Ee*Ee],g_wklo[KN*Ee*Ee];
__device__ bf    g_wmhi[Ee*Ee],   g_wmlo[Ee*Ee];     // Wem^T hi/lo
__device__ bf    g_lphi[Bb*LM*Ee],g_lplo[Bb*LM*Ee];
__device__ bf    g_x1hi[Bb*LM*KN*Ee], g_x1lo[Bb*LM*KN*Ee];
__device__ bf    g_shi[(long)Bb*LM*KN*Ll], g_slo[(long)Bb*LM*KN*Ll];
__device__ bf    g_xxhi[Bb*LM*KN*Ee], g_xxlo[Bb*LM*KN*Ee];
__device__ bf    g_vhi[Bb*LM*KN*Ee],  g_vlo[Bb*LM*KN*Ee];
// fused-LSE partials (1024 rows x 250 col-blocks)
__device__ float g_pm[(long)Bb*LM*KN*250];
__device__ float g_ps[(long)Bb*LM*KN*250];
__device__ float g_lse [Bb*LM*KN];
__device__ float g_tval[Bb*LM*KN];

// ---------------- reductions ----------------
__device__ __forceinline__ float warp_sum(float v){
    #pragma unroll
    for (int o=16;o;o>>=1) v += __shfl_xor_sync(0xffffffffu, v, o);
    return v;
}
__device__ float block_sum256(float v){
    __shared__ float sh[8];
    int lane = threadIdx.x & 31, w = threadIdx.x >> 5;
    v = warp_sum(v);
    if (lane==0) sh[w] = v;
    __syncthreads();
    float r = (threadIdx.x < 8) ? sh[threadIdx.x] : 0.f;
    if (w==0){ r = warp_sum(r); if (lane==0) sh[0]=r; }
    __syncthreads();
    float out = sh[0];
    __syncthreads();
    return out;
}

// ---------------- bf16 / mma / cp.async / ldmatrix helpers ----------------
__device__ __forceinline__ uint32_t pk2(float lo, float hi){
    uint32_t r;
    asm("cvt.rn.bf16x2.f32 %0, %1, %2;" : "=r"(r) : "f"(hi), "f"(lo));
    return r;
}
__device__ __forceinline__ void mma_bf16(float* d, const uint32_t* a, const uint32_t* b){
    asm volatile(
      "mma.sync.aligned.m16n8k16.row.col.f32.bf16.bf16.f32 "
      "{%0,%1,%2,%3}, {%4,%5,%6,%7}, {%8,%9}, {%0,%1,%2,%3};\n"
      : "+f"(d[0]),"+f"(d[1]),"+f"(d[2]),"+f"(d[3])
      : "r"(a[0]),"r"(a[1]),"r"(a[2]),"r"(a[3]), "r"(b[0]),"r"(b[1]));
}
__device__ __forceinline__ void cp16b(void* s, const bf* g){
    uint32_t sa = (uint32_t)__cvta_generic_to_shared(s);
    asm volatile("cp.async.ca.shared.global [%0], [%1], 16;\n" :: "r"(sa), "l"(g));
}
__device__ __forceinline__ void cp_commit(){ asm volatile("cp.async.commit_group;\n" ::); }
template<int W> __device__ __forceinline__ void cp_wait(){ asm volatile("cp.async.wait_group %0;\n" :: "n"(W)); }
__device__ __forceinline__ uint32_t s2u(const void* p){
    uint32_t a;
    asm("{ .reg .u64 t; cvta.to.shared.u64 t, %1; cvt.u32.u64 %0, t; }" : "=r"(a) : "l"(p));
    return a;
}
__device__ __forceinline__ void ldsm4(uint32_t& r0, uint32_t& r1, uint32_t& r2, uint32_t& r3,
                                      uint32_t addr){
    asm volatile("ldmatrix.sync.aligned.m8n8.x4.shared.b16 {%0,%1,%2,%3}, [%4];"
        : "=r"(r0),"=r"(r1),"=r"(r2),"=r"(r3) : "r"(addr));
}
__device__ __forceinline__ void ols_merge(float& m, float& s, float mo, float so){
    float mn = fmaxf(m, mo);
    s = s*expf(m - mn) + so*expf(mo - mn);
    m = mn;
}

// PMODE output index mapping (element index):
template<int PMODE>
__device__ __forceinline__ long out_index(int r, int c, int bz, int N, long sC){
    if (PMODE==0) return (long)bz*sC + (long)r*N + c;
    if (PMODE==1) return (((long)(r>>9))<<20) + ((long)(r&511)<<11) + c;
    if (PMODE==2) return (((long)(bz*512 + (r>>3)))<<11) + ((long)(r&7)<<8) + c;
    if (PMODE==3) return (((long)(r>>6))<<16) + ((long)(r&63)<<10) + c;
    return (long)r*768 + ((long)bz<<8) + c;
}

// ---------------- unified bf16 tensor-core GEMM (3-stage pipeline, ldmatrix) ----------------
template<int BM,int BN,int WM,int WN,bool RELU,bool BIAS,int PMODE,int ROLLMODE,bool COMP,int OUTMODE>
__global__ __launch_bounds__(256, 2)
void bgemm_k(const bf* __restrict__ A, const bf* __restrict__ Alo,
             const bf* __restrict__ B, const bf* __restrict__ Blo,
             const float* __restrict__ bias,
             float* __restrict__ C, bf* __restrict__ Cb, bf* __restrict__ Clo,
             int M, int N, int Kd, int lda, int ldb,
             long sA, long sB, long sC, int rollShift)
{
    constexpr int P   = 20;
    constexpr int NST = COMP ? 2 : 1;
    constexpr int TA  = BM*P, TB = BN*P;
    constexpr int STG = NST*(TA+TB);
    constexpr int MI  = WM/16, NI = WN/8;
    constexpr int NJ  = NI/2;
    constexpr int WCOLS = BN/WN;

    extern __shared__ uint32_t smw[];
    const uint32_t smem_u = s2u(smw);

    const int bz = blockIdx.z;
    const bf* Ap  = A + (long)bz*sA;
    const bf* Alp = COMP ? Alo + (long)bz*sA : nullptr;
    const bf* Bp  = B + (long)bz*sB;
    const bf* Blp = COMP ? Blo + (long)bz*sB : nullptr;

    int rs = 0;
    if (ROLLMODE==2) rs = (bz==0) ? rollShift : -rollShift;

    const int row0 = blockIdx.y*BM, col0 = blockIdx.x*BN;
    const int tid  = threadIdx.x;
    const int warp = tid >> 5, lane = tid & 31;
    const int wy = warp / WCOLS, wx = warp % WCOLS;
    const int g = lane >> 2, c4 = lane & 3;

    uint32_t aoff[MI];
    #pragma unroll
    for (int mi=0; mi<MI; mi++)
        aoff[mi] = (uint32_t)(((wy*WM + mi*16 + (lane & 15))*P + (lane>>4)*4) * 4);
    uint32_t boff[NJ];
    #pragma unroll
    for (int j=0; j<NJ; j++)
        boff[j] = (uint32_t)(((wx*WN + j*16 + ((lane>>4)<<3) + (lane & 7))*P + ((lane>>3)&1)*4) * 4);

    auto load_tile = [&](int kt, int st){
        uint32_t* base = smw + st*STG;
        uint32_t* Ah = base;
        uint32_t* Al = base + TA;
        uint32_t* Bh = base + NST*TA;
        uint32_t* Bl = Bh + TB;
        const int k0 = kt*32;
        #pragma unroll
        for (int i=0;i<BM*4/256;i++){
            int id = tid + i*256; int r = id>>2, q = id&3;
            int gr = row0 + r;
            if (ROLLMODE) gr = (gr & ~511) | ((gr - rs) & 511);
            long go = (long)gr*lda + k0 + 8*q;
            cp16b(Ah + r*P + 4*q, Ap + go);
            if (COMP) cp16b(Al + r*P + 4*q, Alp + go);
        }
        #pragma unroll
        for (int i=0;i<BN*4/256;i++){
            int id = tid + i*256; int n = id>>2, q = id&3;
            long go = (long)(col0+n)*ldb + k0 + 8*q;
            cp16b(Bh + n*P + 4*q, Bp + go);
            if (COMP) cp16b(Bl + n*P + 4*q, Blp + go);
        }
        cp_commit();
    };

    float acc[MI][NI][4];
    #pragma unroll
    for (int i=0;i<MI;i++)
        #pragma unroll
        for (int j=0;j<NI;j++)
            #pragma unroll
            for (int t=0;t<4;t++) acc[i][j][t]=0.f;

    const int nit = Kd/32;
    load_tile(0, 0);
    load_tile(1, 1);

    int st = 0;
    for (int it=0; it<nit; it++){
        if (it+2 < nit){ load_tile(it+2, (it+2)%3); cp_wait<2>(); }
        else if (it+1 < nit){ cp_wait<1>(); }
        else { cp_wait<0>(); }
        __syncthreads();

        const uint32_t AhB = smem_u + (uint32_t)(st*STG*4);
        const uint32_t AlB = AhB + TA*4;
        const uint32_t BhB = AhB + NST*TA*4;
        const uint32_t BlB = BhB + TB*4;

        #pragma unroll
        for (int ks=0; ks<2; ks++){
            const uint32_t ko = ks*32;
            uint32_t af[MI][4], bfr[NI][2];
            uint32_t afl[COMP?MI:1][4], bfl[COMP?NI:1][2];
            #pragma unroll
            for (int mi=0; mi<MI; mi++){
                ldsm4(af[mi][0], af[mi][1], af[mi][2], af[mi][3], AhB + aoff[mi] + ko);
                if (COMP)
                    ldsm4(afl[mi][0], afl[mi][1], afl[mi][2], afl[mi][3], AlB + aoff[mi] + ko);
            }
            #pragma unroll
            for (int j=0; j<NJ; j++){
                ldsm4(bfr[2*j][0], bfr[2*j][1], bfr[2*j+1][0], bfr[2*j+1][1], BhB + boff[j] + ko);
                if (COMP)
                    ldsm4(bfl[2*j][0], bfl[2*j][1], bfl[2*j+1][0], bfl[2*j+1][1], BlB + boff[j] + ko);
            }
            #pragma unroll
            for (int mi=0; mi<MI; mi++)
                #pragma unroll
                for (int ni=0; ni<NI; ni++){
                    if (COMP){
                        mma_bf16(acc[mi][ni], afl[mi], bfr[ni]);
                        mma_bf16(acc[mi][ni], af[mi], bfl[ni]);
                    }
                    mma_bf16(acc[mi][ni], af[mi], bfr[ni]);
                }
        }
        __syncthreads();
        st = (st==2) ? 0 : st+1;
    }

    // ---- epilogue ----
    #pragma unroll
    for (int mi=0; mi<MI; mi++){
        #pragma unroll
        for (int half=0; half<2; half++){
            int r = row0 + wy*WM + mi*16 + g + half*8;
            #pragma unroll
            for (int ni=0; ni<NI; ni++){
                int cc = col0 + wx*WN + ni*8 + 2*c4;
                float v0 = acc[mi][ni][half*2+0];
                float v1 = acc[mi][ni][half*2+1];
                if (BIAS){ v0 += bias[cc]; v1 += bias[cc+1]; }
                if (RELU){ v0 = fmaxf(v0,0.f); v1 = fmaxf(v1,0.f); }
                long idx = out_index<PMODE>(r, cc, bz, N, sC);
                if (OUTMODE==0){
                    *(float2*)(C + idx) = make_float2(v0, v1);
                } else if (OUTMODE==1){
                    *(uint32_t*)(Cb + idx) = pk2(v0, v1);
                } else {
                    bf h0 = __float2bfloat16(v0);
                    bf h1 = __float2bfloat16(v1);
                    union { __nv_bfloat162 b; uint32_t u; } cu;
                    cu.b = __halves2bfloat162(h0, h1);
                    *(uint32_t*)(Cb + idx)  = cu.u;
                    *(uint32_t*)(Clo + idx) = pk2(v0 - __bfloat162float(h0),
                                                  v1 - __bfloat162float(h1));
                }
            }
        }
    }
}

// ---------------- fully fused attention: QK -> softmax -> P@V ----------------
// Per block: 64 q-rows x full 512 kv of one batch. Phase 1 computes scores +
// softmax (identical math to previous qk_softmax_k). Probs stored to SMEM in
// per-32k-chunk pitch-20 layout, then phase 2 runs y = P(64x512) @ V^T(256x512)
// with V rows streamed from xsat. Epilogue writes yb in PMODE2 layout.
__global__ __launch_bounds__(512, 1)
void fa_k(const bf* __restrict__ A, const bf* __restrict__ B,
          const bf* __restrict__ Vt, bf* __restrict__ Y,
          long sA, long sB)
{
    constexpr int Pw  = 20;
    constexpr int TA1 = 64*Pw, TB1 = 512*Pw, STG1 = TA1+TB1;
    constexpr int PWW = 16*64*Pw;            // P region: 16 chunks x 64 rows (20480 words)
    constexpr int TB2 = 256*Pw;              // V tile stage (5120 words)
    extern __shared__ uint32_t smw[];
    const uint32_t smem_u = s2u(smw);

    const int bz = blockIdx.z;
    const bf* Ap = A + (long)bz*sA;
    const bf* Bp = B + (long)bz*sB;
    const int row0 = blockIdx.y*64;
    const int tid = threadIdx.x, warp = tid>>5, lane = tid&31;
    const int g = lane>>2, c4 = lane&3;
    const int wy = warp>>3, wx = warp&7;     // 2 x 8 warps

    // ======== phase 1: scores (warp tile 32x64) ========
    uint32_t aoff1[2];
    #pragma unroll
    for (int mi=0;mi<2;mi++)
        aoff1[mi] = (uint32_t)(((wy*32 + mi*16 + (lane & 15))*Pw + (lane>>4)*4) * 4);
    uint32_t boff1[4];
    #pragma unroll
    for (int j=0;j<4;j++)
        boff1[j] = (uint32_t)(((wx*64 + j*16 + ((lane>>4)<<3) + (lane & 7))*Pw + ((lane>>3)&1)*4) * 4);

    auto load_tile1 = [&](int kt, int st){
        uint32_t* base = smw + st*STG1;
        uint32_t* Ah = base;
        uint32_t* Bh = base + TA1;
        const int k0 = kt*32;
        if (tid < 256){
            int r = tid>>2, q = tid&3;
            cp16b(Ah + r*Pw + 4*q, Ap + (long)(row0+r)*256 + k0 + 8*q);
        }
        #pragma unroll
        for (int i=0;i<4;i++){
            int id = tid + i*512; int n = id>>2, q = id&3;
            cp16b(Bh + n*Pw + 4*q, Bp + (long)n*256 + k0 + 8*q);
        }
        cp_commit();
    };

    float acc[2][8][4];
    #pragma unroll
    for (int i=0;i<2;i++)
        #pragma unroll
        for (int j=0;j<8;j++)
            #pragma unroll
            for (int t=0;t<4;t++) acc[i][j][t]=0.f;

    {
        const int nit = 8;   // K=256
        load_tile1(0, 0);
        load_tile1(1, 1);
        int st = 0;
        for (int it=0; it<nit; it++){
            if (it+2 < nit){ load_tile1(it+2, (it+2)%3); cp_wait<2>(); }
            else if (it+1 < nit){ cp_wait<1>(); }
            else { cp_wait<0>(); }
            __syncthreads();

            const uint32_t AhB = smem_u + (uint32_t)(st*STG1*4);
            const uint32_t BhB = AhB + TA1*4;
            #pragma unroll
            for (int ks=0; ks<2; ks++){
                const uint32_t ko = ks*32;
                uint32_t af[2][4], bfr[8][2];
                #pragma unroll
                for (int mi=0; mi<2; mi++)
                    ldsm4(af[mi][0], af[mi][1], af[mi][2], af[mi][3], AhB + aoff1[mi] + ko);
                #pragma unroll
                for (int j=0; j<4; j++)
                    ldsm4(bfr[2*j][0], bfr[2*j][1], bfr[2*j+1][0], bfr[2*j+1][1], BhB + boff1[j] + ko);
                #pragma unroll
                for (int mi=0; mi<2; mi++)
                    #pragma unroll
                    for (int ni=0; ni<8; ni++)
                        mma_bf16(acc[mi][ni], af[mi], bfr[ni]);
            }
            __syncthreads();
            st = (st==2) ? 0 : st+1;
        }
    }

    // ======== softmax (scale 1/16); reduction scratch beyond P+V regions ========
    float* red_m = (float*)(smw + PWW + 2*TB2);   // [64][8]
    float* red_s = red_m + 64*8;
    #pragma unroll
    for (int mi=0; mi<2; mi++){
        #pragma unroll
        for (int half=0; half<2; half++){
            float mx = -INFINITY;
            #pragma unroll
            for (int ni=0; ni<8; ni++)
                mx = fmaxf(mx, fmaxf(acc[mi][ni][half*2], acc[mi][ni][half*2+1]));
            mx *= 0.0625f;
            float s = 0.f;
            #pragma unroll
            for (int ni=0; ni<8; ni++){
                s += expf(acc[mi][ni][half*2+0]*0.0625f - mx);
                s += expf(acc[mi][ni][half*2+1]*0.0625f - mx);
            }
            float m = mx;
            #pragma unroll
            for (int o=1; o<=2; o<<=1){
                float mo = __shfl_xor_sync(0xffffffffu, m, o);
                float so = __shfl_xor_sync(0xffffffffu, s, o);
                ols_merge(m, s, mo, so);
            }
            int rt = wy*32 + mi*16 + half*8 + g;
            if (c4==0){ red_m[rt*8+wx] = m; red_s[rt*8+wx] = s; }
        }
    }
    __syncthreads();
    if (tid < 64){
        float M = red_m[tid*8], S = red_s[tid*8];
        #pragma unroll
        for (int i=1;i<8;i++) ols_merge(M, S, red_m[tid*8+i], red_s[tid*8+i]);
        red_m[tid*8] = M;
        red_s[tid*8] = 1.f/S;
    }
    __syncthreads();
    // store probs to P region (chunked pitch-20 layout; conflict-free)
    #pragma unroll
    for (int mi=0; mi<2; mi++){
        #pragma unroll
        for (int half=0; half<2; half++){
            int rt = wy*32 + mi*16 + half*8 + g;
            float M = red_m[rt*8], inv = red_s[rt*8];
            #pragma unroll
            for (int ni=0; ni<8; ni++){
                int c = wx*64 + ni*8 + 2*c4;
                float p0 = expf(acc[mi][ni][half*2+0]*0.0625f - M)*inv;
                float p1 = expf(acc[mi][ni][half*2+1]*0.0625f - M)*inv;
                smw[(c>>5)*(64*Pw) + rt*Pw + ((c&31)>>1)] = pk2(p0, p1);
            }
        }
    }
    __syncthreads();

    // ======== phase 2: y(64x256) = P @ V^T, K=512 (warp tile 32x32) ========
    const int wx2 = warp&7, wy2 = warp>>3;
    uint32_t aoff2[2];
    #pragma unroll
    for (int mi=0;mi<2;mi++)
        aoff2[mi] = (uint32_t)(((wy2*32 + mi*16 + (lane & 15))*Pw + (lane>>4)*4) * 4);
    uint32_t boff2 = (uint32_t)(((wx2*32 + ((lane>>4)<<4) + ((lane>>3)&1)*8 - ((lane>>4)<<4) + ((lane>>4)<<4)))*0);
    // (computed properly below)
    uint32_t boff2a[2];
    #pragma unroll
    for (int j=0;j<2;j++)
        boff2a[j] = (uint32_t)(((wx2*32 + j*16 + ((lane>>4)<<3) + (lane & 7))*Pw + ((lane>>3)&1)*4) * 4);
    (void)boff2;

    auto load_v = [&](int kt, int st){
        uint32_t* Bh = smw + PWW + st*TB2;
        const int k0 = kt*32;
        #pragma unroll
        for (int i=0;i<2;i++){
            int id = tid + i*512; int n = id>>2, q = id&3;
            cp16b(Bh + n*Pw + 4*q, Vt + (long)n*TOK + bz*512 + k0 + 8*q);
        }
        cp_commit();
    };

    float acc2[2][4][4];
    #pragma unroll
    for (int i=0;i<2;i++)
        #pragma unroll
        for (int j=0;j<4;j++)
            #pragma unroll
            for (int t=0;t<4;t++) acc2[i][j][t]=0.f;

    {
        const int nit = 16;  // K=512
        load_v(0, 0);
        int st = 0;
        for (int it=0; it<nit; it++){
            if (it+1 < nit){ load_v(it+1, st^1); cp_wait<1>(); }
            else { cp_wait<0>(); }
            __syncthreads();

            const uint32_t AB = smem_u + (uint32_t)(it*64*Pw*4);
            const uint32_t BB = smem_u + (uint32_t)((PWW + st*TB2)*4);
            #pragma unroll
            for (int ks=0; ks<2; ks++){
                const uint32_t ko = ks*32;
                uint32_t af[2][4], bfr[4][2];
                #pragma unroll
                for (int mi=0; mi<2; mi++)
                    ldsm4(af[mi][0], af[mi][1], af[mi][2], af[mi][3], AB + aoff2[mi] + ko);
                #pragma unroll
                for (int j=0; j<2; j++)
                    ldsm4(bfr[2*j][0], bfr[2*j][1], bfr[2*j+1][0], bfr[2*j+1][1], BB + boff2a[j] + ko);
                #pragma unroll
                for (int mi=0; mi<2; mi++)
                    #pragma unroll
                    for (int ni=0; ni<4; ni++)
                        mma_bf16(acc2[mi][ni], af[mi], bfr[ni]);
            }
            __syncthreads();
            st ^= 1;
        }
    }

    // epilogue: write yb in PMODE2 layout
    #pragma unroll
    for (int mi=0; mi<2; mi++){
        #pragma unroll
        for (int half=0; half<2; half++){
            int r = row0 + wy2*32 + mi*16 + g + half*8;
            #pragma unroll
            for (int ni=0; ni<4; ni++){
                int cc = wx2*32 + ni*8 + 2*c4;
                long idx = (((long)(bz*512 + (r>>3)))<<11) + ((long)(r&7)<<8) + cc;
                *(uint32_t*)(Y + idx) = pk2(acc2[mi][ni][half*2+0], acc2[mi][ni][half*2+1]);
            }
        }
    }
}

// ---------------- fused logits GEMM + online-LSE partials (COMP, 128x128 tiles) ----------------
__global__ __launch_bounds__(256, 1)
void glse_k(const bf* __restrict__ A, const bf* __restrict__ Alo,
            const bf* __restrict__ B, const bf* __restrict__ Blo,
            float* __restrict__ pm, float* __restrict__ ps)
{
    constexpr int Pw = 20;
    constexpr int TA = 128*Pw, TB = 128*Pw;
    constexpr int STG = 2*(TA+TB);
    extern __shared__ uint32_t smw[];
    const uint32_t smem_u = s2u(smw);

    const int row0 = blockIdx.y*128, col0 = blockIdx.x*128, bx = blockIdx.x;
    const int tid = threadIdx.x, warp = tid>>5, lane = tid&31;
    const int wy = warp>>2, wx = warp&3;     // WM=64, WN=32
    const int g = lane>>2, c4 = lane&3;

    uint32_t aoff[4];
    #pragma unroll
    for (int mi=0;mi<4;mi++)
        aoff[mi] = (uint32_t)(((wy*64 + mi*16 + (lane & 15))*Pw + (lane>>4)*4) * 4);
    uint32_t boff[2];
    #pragma unroll
    for (int j=0;j<2;j++)
        boff[j] = (uint32_t)(((wx*32 + j*16 + ((lane>>4)<<3) + (lane & 7))*Pw + ((lane>>3)&1)*4) * 4);

    auto load_tile = [&](int kt, int st){
        uint32_t* base = smw + st*STG;
        uint32_t* Ah = base;
        uint32_t* Al = base + TA;
        uint32_t* Bh = base + 2*TA;
        uint32_t* Bl = Bh + TB;
        const int k0 = kt*32;
        #pragma unroll
        for (int i=0;i<2;i++){
            int id = tid + i*256; int r = id>>2, q = id&3;
            long go = (long)(row0+r)*256 + k0 + 8*q;
            cp16b(Ah + r*Pw + 4*q, A + go);
            cp16b(Al + r*Pw + 4*q, Alo + go);
            long gb = (long)(col0+r)*256 + k0 + 8*q;
            cp16b(Bh + r*Pw + 4*q, B + gb);
            cp16b(Bl + r*Pw + 4*q, Blo + gb);
        }
        cp_commit();
    };

    float acc[4][4][4];
    #pragma unroll
    for (int i=0;i<4;i++)
        #pragma unroll
        for (int j=0;j<4;j++)
            #pragma unroll
            for (int t=0;t<4;t++) acc[i][j][t]=0.f;

    const int nit = 8;   // K=256
    load_tile(0, 0);
    int st = 0;
    for (int it=0; it<nit; it++){
        if (it+1 < nit){ load_tile(it+1, (it+1)&1); cp_wait<1>(); }
        else { cp_wait<0>(); }
        __syncthreads();

        const uint32_t AhB = smem_u + (uint32_t)(st*STG*4);
        const uint32_t AlB = AhB + TA*4;
        const uint32_t BhB = AhB + 2*TA*4;
        const uint32_t BlB = BhB + TB*4;
        #pragma unroll
        for (int ks=0; ks<2; ks++){
            const uint32_t ko = ks*32;
            uint32_t af[4][4], afl[4][4], bfr[4][2], bfl[4][2];
            #pragma unroll
            for (int mi=0; mi<4; mi++){
                ldsm4(af[mi][0], af[mi][1], af[mi][2], af[mi][3], AhB + aoff[mi] + ko);
                ldsm4(afl[mi][0], afl[mi][1], afl[mi][2], afl[mi][3], AlB + aoff[mi] + ko);
            }
            #pragma unroll
            for (int j=0; j<2; j++){
                ldsm4(bfr[2*j][0], bfr[2*j][1], bfr[2*j+1][0], bfr[2*j+1][1], BhB + boff[j] + ko);
                ldsm4(bfl[2*j][0], bfl[2*j][1], bfl[2*j+1][0], bfl[2*j+1][1], BlB + boff[j] + ko);
            }
            #pragma unroll
            for (int mi=0; mi<4; mi++)
                #pragma unroll
                for (int ni=0; ni<4; ni++){
                    mma_bf16(acc[mi][ni], afl[mi], bfr[ni]);
                    mma_bf16(acc[mi][ni], af[mi], bfl[ni]);
                    mma_bf16(acc[mi][ni], af[mi], bfr[ni]);
                }
        }
        __syncthreads();
        st ^= 1;
    }

    float* red_m = (float*)smw;       // [128][4]
    float* red_s = red_m + 128*4;
    #pragma unroll
    for (int mi=0; mi<4; mi++){
        #pragma unroll
        for (int half=0; half<2; half++){
            float mx = -INFINITY;
            #pragma unroll
            for (int ni=0; ni<4; ni++)
                mx = fmaxf(mx, fmaxf(acc[mi][ni][half*2], acc[mi][ni][half*2+1]));
            float s = 0.f;
            #pragma unroll
            for (int ni=0; ni<4; ni++){
                s += expf(acc[mi][ni][half*2+0]-mx);
                s += expf(acc[mi][ni][half*2+1]-mx);
            }
            float m = mx;
            #pragma unroll
            for (int o=1; o<=2; o<<=1){
                float mo = __shfl_xor_sync(0xffffffffu, m, o);
                float so = __shfl_xor_sync(0xffffffffu, s, o);
                ols_merge(m, s, mo, so);
            }
            int rt = wy*64 + mi*16 + half*8 + g;
            if (c4==0){ red_m[rt*4+wx] = m; red_s[rt*4+wx] = s; }
        }
    }
    __syncthreads();
    if (tid < 128){
        float M = red_m[tid*4], S = red_s[tid*4];
        #pragma unroll
        for (int i=1;i<4;i++) ols_merge(M, S, red_m[tid*4+i], red_s[tid*4+i]);
        long idx = (long)(row0+tid)*250 + bx;
        pm[idx] = M;
        ps[idx] = S;
    }
}

// merge 250 partials per row -> lse
__global__ void lse_red_k(const float* __restrict__ pm, const float* __restrict__ ps,
                          float* __restrict__ lse){
    int row = blockIdx.x*8 + (threadIdx.x>>5);
    int lane = threadIdx.x & 31;
    float m = -INFINITY, s = 0.f;
    for (int i=lane; i<250; i+=32)
        ols_merge(m, s, pm[(long)row*250+i], ps[(long)row*250+i]);
    #pragma unroll
    for (int o=16;o;o>>=1){
        float mo = __shfl_xor_sync(0xffffffffu, m, o);
        float so = __shfl_xor_sync(0xffffffffu, s, o);
        ols_merge(m, s, mo, so);
    }
    if (lane==0) lse[row] = m + logf(s);
}

// exact fp32 target logit
__global__ void tval_k(const bf* __restrict__ vhi, const bf* __restrict__ vlo,
                       const bf* __restrict__ ehi, const bf* __restrict__ elo,
                       const int* __restrict__ unmasked, const int* __restrict__ mask,
                       float* __restrict__ tval){
    int row = blockIdx.x;
    int b = row >> 8, n = row & 255, j = n >> 2;
    int tg = unmasked[b*Ll + mask[b*LM + j]];
    long vi = (long)row*Ee + threadIdx.x;
    long ei = (long)tg*Ee + threadIdx.x;
    float v = (__bfloat162float(vhi[vi]) + __bfloat162float(vlo[vi]))
            * (__bfloat162float(ehi[ei]) + __bfloat162float(elo[ei]));
    float s = block_sum256(v);
    if (threadIdx.x==0) tval[row] = s;
}

// ---------------- prep kernels ----------------
__global__ void prep_w_k(const float* __restrict__ Wt, const float* __restrict__ Wtc,
                         const float* __restrict__ Wu,
                         bf* __restrict__ wc1, bf* __restrict__ wc2)
{
    long idx = (long)blockIdx.x*1024 + threadIdx.x;
    if (idx >= (long)Dd*5*65536) return;
    int d = idx / (5*65536);
    int r = idx % (5*65536);
    int which = r / 65536;
    int e = r % 65536;
    int n = e >> 8, k = e & 255;
    long wb = (long)d*65536;
    if      (which==0) wc1[(long)d*131072 +         n*256+k] = __float2bfloat16(Wt [wb + (long)k*256 + n]);
    else if (which==1) wc1[(long)d*131072 + 65536 + n*256+k] = __float2bfloat16(Wtc[wb + (long)n*256 + k]);
    else if (which==2) wc2[(long)d*196608 + (long)n*768 +       k] = __float2bfloat16(Wtc[wb + (long)k*256 + n]);
    else if (which==3) wc2[(long)d*196608 + (long)n*768 + 256 + k] = __float2bfloat16(Wt [wb + (long)n*256 + k]);
    else               wc2[(long)d*196608 + (long)n*768 + 512 + k] = __float2bfloat16(Wu [wb + (long)n*256 + k]);
}

__global__ void conv_b4(const float4* __restrict__ in, uint2* __restrict__ outp, long n4){
    long i = (long)blockIdx.x*256 + threadIdx.x;
    if (i >= n4) return;
    float4 v = in[i];
    uint2 o; o.x = pk2(v.x, v.y); o.y = pk2(v.z, v.w);
    outp[i] = o;
}

__global__ void split_b4(const float4* __restrict__ in, uint2* __restrict__ hi,
                         uint2* __restrict__ lo, long n4){
    long i = (long)blockIdx.x*256 + threadIdx.x;
    if (i >= n4) return;
    float4 v = in[i];
    bf hx=__float2bfloat16(v.x), hy=__float2bfloat16(v.y);
    bf hz=__float2bfloat16(v.z), hw=__float2bfloat16(v.w);
    union { __nv_bfloat162 b; uint32_t u; } c0, c1;
    c0.b = __halves2bfloat162(hx, hy);
    c1.b = __halves2bfloat162(hz, hw);
    uint2 h; h.x=c0.u; h.y=c1.u;
    uint2 l;
    l.x = pk2(v.x-__bfloat162float(hx), v.y-__bfloat162float(hy));
    l.y = pk2(v.z-__bfloat162float(hz), v.w-__bfloat162float(hw));
    hi[i]=h; lo[i]=l;
}

__global__ void split_lo4(const float4* __restrict__ in, uint2* __restrict__ lo, long n4){
    long i = (long)blockIdx.x*256 + threadIdx.x;
    if (i >= n4) return;
    float4 v = in[i];
    bf hx=__float2bfloat16(v.x), hy=__float2bfloat16(v.y);
    bf hz=__float2bfloat16(v.z), hw=__float2bfloat16(v.w);
    uint2 l;
    l.x = pk2(v.x-__bfloat162float(hx), v.y-__bfloat162float(hy));
    l.y = pk2(v.z-__bfloat162float(hz), v.w-__bfloat162float(hw));
    lo[i]=l;
}

__global__ void t32_f2b(const float* __restrict__ src, bf* __restrict__ dst, int R, int C){
    __shared__ bf t[32][33];
    const float* s = src + (long)blockIdx.z*R*C;
    bf* d = dst + (long)blockIdx.z*R*C;
    int r0 = blockIdx.x*32, c0 = blockIdx.y*32;
    int tx = threadIdx.x & 31, ty = threadIdx.x >> 5;
    #pragma unroll
    for (int i=0;i<4;i++) t[ty+8*i][tx] = __float2bfloat16(s[(long)(r0+ty+8*i)*C + c0+tx]);
    __syncthreads();
    #pragma unroll
    for (int i=0;i<4;i++) d[(long)(c0+ty+8*i)*R + r0+tx] = t[tx][ty+8*i];
}

__global__ void t32_f2b2(const float* __restrict__ src, bf* __restrict__ dh,
                         bf* __restrict__ dl, int R, int C){
    __shared__ bf th[32][33];
    __shared__ bf tl[32][33];
    int r0 = blockIdx.x*32, c0 = blockIdx.y*32;
    int tx = threadIdx.x & 31, ty = threadIdx.x >> 5;
    #pragma unroll
    for (int i=0;i<4;i++){
        float v = src[(long)(r0+ty+8*i)*C + c0+tx];
        bf h = __float2bfloat16(v);
        th[ty+8*i][tx] = h;
        tl[ty+8*i][tx] = __float2bfloat16(v - __bfloat162float(h));
    }
    __syncthreads();
    #pragma unroll
    for (int i=0;i<4;i++){
        dh[(long)(c0+ty+8*i)*R + r0+tx] = th[tx][ty+8*i];
        dl[(long)(c0+ty+8*i)*R + r0+tx] = tl[tx][ty+8*i];
    }
}

__global__ void transpose_b(const bf* __restrict__ src, bf* __restrict__ dst, int R, int C){
    __shared__ bf t[32][33];
    int r0 = blockIdx.x*32, c0 = blockIdx.y*32;
    int tx = threadIdx.x & 31, ty = threadIdx.x >> 5;
    #pragma unroll
    for (int i=0;i<4;i++) t[ty+8*i][tx] = src[(long)(r0+ty+8*i)*C + c0+tx];
    __syncthreads();
    #pragma unroll
    for (int i=0;i<4;i++) dst[(long)(c0+ty+8*i)*R + r0+tx] = t[tx][ty+8*i];
}

// ---------------- elementwise / reduction kernels ----------------
__global__ void embed_norm_k(const int* __restrict__ masked, const float* __restrict__ embed,
                             float* __restrict__ xsa, bf* __restrict__ xsab,
                             bf* __restrict__ xsat, bf* __restrict__ acat)
{
    int t = blockIdx.x;
    int g = masked[t];
    float v = embed[(long)g*Ee + threadIdx.x];
    float mean = block_sum256(v) * (1.f/Ee);
    float d = v - mean;
    float var = block_sum256(d*d) * (1.f/(Ee-1));
    float o = v / (1.f + sqrtf(var));
    xsa [(long)t*Ee + threadIdx.x] = o;
    bf ob = __float2bfloat16(o);
    xsab[(long)t*Ee + threadIdx.x] = ob;
    xsat[(long)threadIdx.x*TOK + t] = ob;
    acat[(long)t*768 + 512 + threadIdx.x] = ob;
}

__global__ void update_norm_k(const float* __restrict__ xsad, const float* __restrict__ t1p,
                              float* __restrict__ xsa, bf* __restrict__ xsab,
                              bf* __restrict__ xsat)
{
    long idx = (long)blockIdx.x*Ee + threadIdx.x;
    const long S = (long)TOK*Ee;
    float u = xsad[idx] + t1p[idx] + t1p[idx+S] + t1p[idx+2*S] + t1p[idx+3*S];
    float mean = block_sum256(u) * (1.f/Ee);
    float d = u - mean;
    float var = block_sum256(d*d) * (1.f/(Ee-1));
    float un = u / (1.f + sqrtf(var));
    float w = xsa[idx] + 0.05f * un;
    float mean2 = block_sum256(w) * (1.f/Ee);
    float d2 = w - mean2;
    float var2 = block_sum256(d2*d2) * (1.f/(Ee-1));
    float o = w / (1.f + sqrtf(var2));
    xsa[idx]  = o;
    bf ob = __float2bfloat16(o);
    xsab[idx] = ob;
    xsat[(long)threadIdx.x*TOK + blockIdx.x] = ob;
}

__global__ void gather_split_k(const int* __restrict__ mask, const float* __restrict__ xsa,
                               bf* __restrict__ hi, bf* __restrict__ lo){
    int r = blockIdx.x; int b = r >> 6; int p = mask[r];
    float v = xsa[(long)(b*Ll + p)*Ee + threadIdx.x];
    bf h = __float2bfloat16(v);
    hi[(long)r*Ee + threadIdx.x] = h;
    lo[(long)r*Ee + threadIdx.x] = __float2bfloat16(v - __bfloat162float(h));
}

__global__ void final_k(const float* __restrict__ tval, const float* __restrict__ lse,
                        float* __restrict__ out)
{
    int b = blockIdx.x, j = threadIdx.x;   // 64 threads
    float a[KN]; float m = -INFINITY;
    #pragma unroll
    for (int kn=0;kn<KN;kn++){
        int r = ((b << 6) + j) * KN + kn;
        a[kn] = tval[r] - lse[r];
        m = fmaxf(m, a[kn]);
    }
    float s = 0.f;
    #pragma unroll
    for (int kn=0;kn<KN;kn++) s += expf(a[kn] - m);
    float cent = m + logf(s) - 1.3862943611198906f;   // - log(4)
    __shared__ float sh[64];
    sh[j] = cent; __syncthreads();
    for (int o=32;o;o>>=1){ if (j<o) sh[j] += sh[j+o]; __syncthreads(); }
    if (j==0) out[b] = -sh[0] / (float)LM;
}

// ---------------- host orchestration ----------------
#define GSYM(p, s) cudaGetSymbolAddress((void**)&p, s)

extern "C" void kernel_launch(void* const* d_in, const int* in_sizes, int n_in,
                              void* d_out, int out_size)
{
    (void)in_sizes; (void)n_in; (void)out_size;
    const int*   masked   = (const int*)  d_in[0];
    const int*   unmasked = (const int*)  d_in[1];
    const int*   maskp    = (const int*)  d_in[2];
    const float* embed    = (const float*)d_in[3];
    const float* Wt       = (const float*)d_in[4];
    const float* bt       = (const float*)d_in[5];
    const float* Wtc      = (const float*)d_in[6];
    const float* Wq       = (const float*)d_in[7];
    const float* Wd       = (const float*)d_in[8];
    const float* Wo       = (const float*)d_in[9];
    const float* Wu       = (const float*)d_in[10];
    const float* Wem      = (const float*)d_in[11];
    const float* Wkc      = (const float*)d_in[12];
    const float* bkc      = (const float*)d_in[13];
    float* out = (float*)d_out;

    float *xsa,*xsad,*t1p,*pm,*ps,*lse,*tval;
    bf *xsab,*xsat,*acat,*q2b,*yb,*midb;
    bf *wq,*wd,*wot,*wc1,*wc2;
    bf *ehi,*elo,*xhlo,*xtlo,*wkhi,*wklo,*wmhi,*wmlo;
    bf *lphi,*lplo,*x1hi,*x1lo,*shi,*slo,*xxhi,*xxlo,*vhi,*vlo;
    GSYM(xsa,g_xsa); GSYM(xsad,g_xsad); GSYM(t1p,g_t1p);
    GSYM(pm,g_pm); GSYM(ps,g_ps); GSYM(lse,g_lse); GSYM(tval,g_tval);
    GSYM(xsab,g_xsab); GSYM(xsat,g_xsat); GSYM(acat,g_acat);
    GSYM(q2b,g_q2b); GSYM(yb,g_yb); GSYM(midb,g_midb);
    GSYM(wq,g_wq); GSYM(wd,g_wd); GSYM(wot,g_wot); GSYM(wc1,g_wc1); GSYM(wc2,g_wc2);
    GSYM(ehi,g_ehi); GSYM(elo,g_elo); GSYM(xhlo,g_xhlo); GSYM(xtlo,g_xtlo);
    GSYM(wkhi,g_wkhi); GSYM(wklo,g_wklo); GSYM(wmhi,g_wmhi); GSYM(wmlo,g_wmlo);
    GSYM(lphi,g_lphi); GSYM(lplo,g_lplo);
    GSYM(x1hi,g_x1hi); GSYM(x1lo,g_x1lo); GSYM(shi,g_shi); GSYM(slo,g_slo);
    GSYM(xxhi,g_xxhi); GSYM(xxlo,g_xxlo); GSYM(vhi,g_vhi); GSYM(vlo,g_vlo);

    // kernel instantiations
    auto kS1 = bgemm_k<64,64,32,16,true ,false,4,2,false,1>;   // transitions stage1 -> acat bf16
    auto kS2 = bgemm_k<64,64,32,16,false,true ,0,0,false,0>;   // stage2 -> xsad fp32
    auto kWq = bgemm_k<128,128,64,32,false,false,1,0,false,1>; // q -> q2b (perm)
    auto kWd = bgemm_k<128,128,64,32,true ,false,0,0,false,1>; // dense+relu -> midb
    auto kWo = bgemm_k<64,64,32,16,false,false,0,0,false,0>;   // split-K -> t1p partials
    auto kG1 = bgemm_k<64,64,32,16,false,true ,3,0,true ,2>;   // kchoice -> xx1 hi/lo (perm)
    auto kG2 = bgemm_k<64,64,32,16,false,false,0,0,true ,2>;   // -> s hi/lo
    auto kG3 = bgemm_k<64,64,32,16,false,false,0,0,true ,2>;   // -> xx hi/lo
    auto kG4 = bgemm_k<64,64,32,16,false,false,0,0,true ,2>;   // -> v hi/lo

    constexpr int SM_BIG  = 3*(128+128)*20*4;    // 61440 B
    constexpr int SM_SML  = 3*(64+64)*20*4;      // 30720 B
    constexpr int SM_CMP  = 3*2*(64+64)*20*4;    // 61440 B
    constexpr int SM_FA   = 3*(64+512)*20*4;     // 138240 B (phase1 tiles; covers P+V+red)
    constexpr int SM_GLSE = 2*2*(128+128)*20*4;  // 81920 B

    cudaFuncSetAttribute(kWq, cudaFuncAttributeMaxDynamicSharedMemorySize, SM_BIG);
    cudaFuncSetAttribute(kWd, cudaFuncAttributeMaxDynamicSharedMemorySize, SM_BIG);
    cudaFuncSetAttribute(kG1, cudaFuncAttributeMaxDynamicSharedMemorySize, SM_CMP);
    cudaFuncSetAttribute(kG2, cudaFuncAttributeMaxDynamicSharedMemorySize, SM_CMP);
    cudaFuncSetAttribute(kG3, cudaFuncAttributeMaxDynamicSharedMemorySize, SM_CMP);
    cudaFuncSetAttribute(kG4, cudaFuncAttributeMaxDynamicSharedMemorySize, SM_CMP);
    cudaFuncSetAttribute(fa_k, cudaFuncAttributeMaxDynamicSharedMemorySize, SM_FA);
    cudaFuncSetAttribute(glse_k, cudaFuncAttributeMaxDynamicSharedMemorySize, SM_GLSE);

    // ---- prep: bf16 weights (per launch; graph-captured) ----
    prep_w_k<<<(Dd*5*65536+1023)/1024,1024>>>(Wt, Wtc, Wu, wc1, wc2);
    conv_b4<<<((long)Dd*KE*Ee/4+255)/256,256>>>((const float4*)Wq, (uint2*)wq, (long)Dd*KE*Ee/4);
    conv_b4<<<((long)Dd*KE*KE/4+255)/256,256>>>((const float4*)Wd, (uint2*)wd, (long)Dd*KE*KE/4);
    t32_f2b<<<dim3(KE/32,Ee/32,Dd),256>>>(Wo, wot, KE, Ee);
    split_b4<<<((long)Gg*Ee/4+255)/256,256>>>((const float4*)embed, (uint2*)ehi, (uint2*)elo, (long)Gg*Ee/4);
    split_b4<<<(KN*Ee*Ee/4+255)/256,256>>>((const float4*)Wkc, (uint2*)wkhi, (uint2*)wklo, KN*Ee*Ee/4);
    t32_f2b2<<<dim3(Ee/32,Ee/32,1),256>>>(Wem, wmhi, wmlo, Ee, Ee);

    embed_norm_k<<<TOK,256>>>(masked, embed, xsa, xsab, xsat, acat);

    for (int d=0; d<Dd; d++){
        // transitions
        kS1<<<dim3(4,32,2),256,SM_SML>>>(xsab,0, wc1+(long)d*131072,0, 0, 0,acat,0,
                                         TOK,Ee,Ee, Ee,Ee, 0, 65536, 0, 1);
        kS2<<<dim3(4,32,1),256,SM_SML>>>(acat,0, wc2+(long)d*196608,0, bt+(long)d*Ee, xsad,0,0,
                                         TOK,Ee,768, 768,768, 0,0,0, 0);

        // attention (fully fused: QK -> softmax -> P@V)
        kWq<<<dim3(16,16,1),256,SM_BIG>>>(xsab,0, wq+(long)d*KE*Ee,0, 0, 0,q2b,0,
                                          TOK,KE,Ee, Ee,Ee, 0,0,0, 0);
        fa_k<<<dim3(1,64,Bb),512,SM_FA>>>(q2b, xsab, xsat, yb,
                                          (long)Ll*Kk*Ee, (long)Ll*Ee);

        // dense -> relu -> dense (Wo via split-K=4)
        kWd<<<dim3(16,16,1),256,SM_BIG>>>(yb,0, wd+(long)d*KE*KE,0, 0, 0,midb,0,
                                          TOK,KE,KE, KE,KE, 0,0,0, 0);
        kWo<<<dim3(4,32,4),256,SM_SML>>>(midb,0, wot+(long)d*Ee*KE,0, 0, t1p,0,0,
                                         TOK,Ee,512, KE,KE, 512, 512, (long)TOK*Ee, 0);

        update_norm_k<<<TOK,256>>>(xsad, t1p, xsa, xsab, xsat);
    }

    // ---- head (split-bf16 3-mma; hi of xsa == xsab/xsat) ----
    split_lo4<<<(TOK*Ee/4+255)/256,256>>>((const float4*)xsa, (uint2*)xhlo, TOK*Ee/4);
    transpose_b<<<dim3(TOK/32,Ee/32),256>>>(xhlo, xtlo, TOK, Ee);
    gather_split_k<<<Bb*LM,256>>>(maskp, xsa, lphi, lplo);

    kG1<<<dim3(16,4,1),256,SM_CMP>>>(lphi,lplo, wkhi,wklo, bkc, 0,x1hi,x1lo,
                                     Bb*LM, KN*Ee, Ee, Ee,Ee, 0,0,0, 0);
    kG2<<<dim3(8,4,Bb),256,SM_CMP>>>(x1hi,x1lo, xsab,xhlo, 0, 0,shi,slo,
                                     LM*KN, Ll, Ee, Ee,Ee,
                                     (long)LM*KN*Ee, (long)Ll*Ee, (long)LM*KN*Ll, 0);
    kG3<<<dim3(4,4,Bb),256,SM_CMP>>>(shi,slo, xsat,xtlo, 0, 0,xxhi,xxlo,
                                     LM*KN, Ee, Ll, Ll,TOK,
                                     (long)LM*KN*Ll, (long)Ll, (long)LM*KN*Ee, 0);
    kG4<<<dim3(4,16,1),256,SM_CMP>>>(xxhi,xxlo, wmhi,wmlo, 0, 0,vhi,vlo,
                                     Bb*LM*KN, Ee, Ee, Ee,Ee, 0,0,0, 0);

    // fused logits + LSE (no logits buffer), 128x128 tiles
    glse_k<<<dim3(250,8,1),256,SM_GLSE>>>(vhi, vlo, ehi, elo, pm, ps);
    lse_red_k<<<(Bb*LM*KN)/8,256>>>(pm, ps, lse);
    tval_k<<<Bb*LM*KN,256>>>(vhi, vlo, ehi, elo, unmasked, maskp, tval);
    final_k<<<Bb,64>>>(tval, lse, out);
}

// round 13
// speedup vs baseline: 2.0876x; 1.1222x over previous
#include <cuda_runtime.h>
#include <cuda_bf16.h>
#include <math.h>
#include <stdint.h>

// ---------------- problem constants ----------------
#define Bb 4
#define Ll 512
#define Ee 256
#define Kk 8
#define Dd 6
#define LM 64
#define KN 4
#define Gg 32000
#define KE (Kk*Ee)          // 2048
#define TOK (Bb*Ll)         // 2048

typedef __nv_bfloat16 bf;

// ---------------- scratch (static device memory; no allocations) ----------------
__device__ float g_xsa [TOK*Ee];
__device__ float g_xsad[TOK*Ee];
__device__ float g_t1p [4L*TOK*Ee];                  // kWo split-K partials
__device__ bf    g_xsab[TOK*Ee];                     // xsa bf16 [t][e]
__device__ bf    g_xsat[Ee*TOK];                     // xsa bf16 transposed [e][t]
__device__ bf    g_acat[TOK*768];                    // [t1a | t1b | z] bf16
__device__ bf    g_q2b [TOK*KE];
__device__ bf    g_yb  [TOK*KE];
__device__ bf    g_midb[TOK*KE];
// bf16 weights (prep)
__device__ bf    g_wq [(long)Dd*KE*Ee];
__device__ bf    g_wd [(long)Dd*KE*KE];
__device__ bf    g_wot[(long)Dd*Ee*KE];              // Wo^T  [n=E][k=KE]
__device__ bf    g_wc1[Dd*2*Ee*Ee];                  // [Wt^T][Wtc] as [n][k]
__device__ bf    g_wc2[Dd*Ee*768];                   // [Wtc^T|Wt|Wu] rows n, k=768
// head hi/lo bf16 splits (hi of xsa == xsab/xsat)
__device__ bf    g_ehi[(long)Gg*Ee], g_elo[(long)Gg*Ee];
__device__ bf    g_xhlo[TOK*Ee];
__device__ bf    g_xtlo[Ee*TOK];
__device__ bf    g_wkhi[KN*Ee*Ee],g_wklo[KN*Ee*Ee];
__device__ bf    g_wmhi[Ee*Ee],   g_wmlo[Ee*Ee];     // Wem^T hi/lo
__device__ bf    g_lphi[Bb*LM*Ee],g_lplo[Bb*LM*Ee];
__device__ bf    g_x1hi[Bb*LM*KN*Ee], g_x1lo[Bb*LM*KN*Ee];
__device__ bf    g_shi[(long)Bb*LM*KN*Ll], g_slo[(long)Bb*LM*KN*Ll];
__device__ bf    g_xxhi[Bb*LM*KN*Ee], g_xxlo[Bb*LM*KN*Ee];
__device__ bf    g_vhi[Bb*LM*KN*Ee],  g_vlo[Bb*LM*KN*Ee];
// fused-LSE partials (1024 rows x 250 col-blocks)
__device__ float g_pm[(long)Bb*LM*KN*250];
__device__ float g_ps[(long)Bb*LM*KN*250];
__device__ float g_lse [Bb*LM*KN];
__device__ float g_tval[Bb*LM*KN];

// ---------------- reductions ----------------
__device__ __forceinline__ float warp_sum(float v){
    #pragma unroll
    for (int o=16;o;o>>=1) v += __shfl_xor_sync(0xffffffffu, v, o);
    return v;
}
__device__ float block_sum256(float v){
    __shared__ float sh[8];
    int lane = threadIdx.x & 31, w = threadIdx.x >> 5;
    v = warp_sum(v);
    if (lane==0) sh[w] = v;
    __syncthreads();
    float r = (threadIdx.x < 8) ? sh[threadIdx.x] : 0.f;
    if (w==0){ r = warp_sum(r); if (lane==0) sh[0]=r; }
    __syncthreads();
    float out = sh[0];
    __syncthreads();
    return out;
}

// ---------------- bf16 / mma / cp.async / ldmatrix helpers ----------------
__device__ __forceinline__ uint32_t pk2(float lo, float hi){
    uint32_t r;
    asm("cvt.rn.bf16x2.f32 %0, %1, %2;" : "=r"(r) : "f"(hi), "f"(lo));
    return r;
}
__device__ __forceinline__ void mma_bf16(float* d, const uint32_t* a, const uint32_t* b){
    asm volatile(
      "mma.sync.aligned.m16n8k16.row.col.f32.bf16.bf16.f32 "
      "{%0,%1,%2,%3}, {%4,%5,%6,%7}, {%8,%9}, {%0,%1,%2,%3};\n"
      : "+f"(d[0]),"+f"(d[1]),"+f"(d[2]),"+f"(d[3])
      : "r"(a[0]),"r"(a[1]),"r"(a[2]),"r"(a[3]), "r"(b[0]),"r"(b[1]));
}
__device__ __forceinline__ void cp16b(void* s, const bf* g){
    uint32_t sa = (uint32_t)__cvta_generic_to_shared(s);
    asm volatile("cp.async.ca.shared.global [%0], [%1], 16;\n" :: "r"(sa), "l"(g));
}
__device__ __forceinline__ void cp_commit(){ asm volatile("cp.async.commit_group;\n" ::); }
template<int W> __device__ __forceinline__ void cp_wait(){ asm volatile("cp.async.wait_group %0;\n" :: "n"(W)); }
__device__ __forceinline__ uint32_t s2u(const void* p){
    uint32_t a;
    asm("{ .reg .u64 t; cvta.to.shared.u64 t, %1; cvt.u32.u64 %0, t; }" : "=r"(a) : "l"(p));
    return a;
}
__device__ __forceinline__ void ldsm4(uint32_t& r0, uint32_t& r1, uint32_t& r2, uint32_t& r3,
                                      uint32_t addr){
    asm volatile("ldmatrix.sync.aligned.m8n8.x4.shared.b16 {%0,%1,%2,%3}, [%4];"
        : "=r"(r0),"=r"(r1),"=r"(r2),"=r"(r3) : "r"(addr));
}
__device__ __forceinline__ void ols_merge(float& m, float& s, float mo, float so){
    float mn = fmaxf(m, mo);
    s = s*expf(m - mn) + so*expf(mo - mn);
    m = mn;
}

// PMODE output index mapping (element index):
template<int PMODE>
__device__ __forceinline__ long out_index(int r, int c, int bz, int N, long sC){
    if (PMODE==0) return (long)bz*sC + (long)r*N + c;
    if (PMODE==1) return (((long)(r>>9))<<20) + ((long)(r&511)<<11) + c;
    if (PMODE==2) return (((long)(bz*512 + (r>>3)))<<11) + ((long)(r&7)<<8) + c;
    if (PMODE==3) return (((long)(r>>6))<<16) + ((long)(r&63)<<10) + c;
    return (long)r*768 + ((long)bz<<8) + c;
}

// ---------------- unified bf16 tensor-core GEMM (ldmatrix, templated K-chunk) ----------------
// KCH = K elements per smem tile (32 -> pitch 20, 3-stage; 64 -> pitch 36, 2-stage).
template<int BM,int BN,int WM,int WN,int KCH,bool RELU,bool BIAS,int PMODE,int ROLLMODE,bool COMP,int OUTMODE>
__global__ __launch_bounds__(256, 2)
void bgemm_k(const bf* __restrict__ A, const bf* __restrict__ Alo,
             const bf* __restrict__ B, const bf* __restrict__ Blo,
             const float* __restrict__ bias,
             float* __restrict__ C, bf* __restrict__ Cb, bf* __restrict__ Clo,
             int M, int N, int Kd, int lda, int ldb,
             long sA, long sB, long sC, int rollShift)
{
    constexpr int P    = KCH/2 + 4;          // words per smem row
    constexpr int CH   = KCH/8;              // 16B chunks per row
    constexpr int NSTG = (KCH==64) ? 2 : 3;
    constexpr int NST  = COMP ? 2 : 1;
    constexpr int TA   = BM*P, TB = BN*P;
    constexpr int STG  = NST*(TA+TB);
    constexpr int MI   = WM/16, NI = WN/8;
    constexpr int NJ   = NI/2;
    constexpr int WCOLS = BN/WN;
    constexpr int KS   = KCH/16;

    extern __shared__ uint32_t smw[];
    const uint32_t smem_u = s2u(smw);

    const int bz = blockIdx.z;
    const bf* Ap  = A + (long)bz*sA;
    const bf* Alp = COMP ? Alo + (long)bz*sA : nullptr;
    const bf* Bp  = B + (long)bz*sB;
    const bf* Blp = COMP ? Blo + (long)bz*sB : nullptr;

    int rs = 0;
    if (ROLLMODE==2) rs = (bz==0) ? rollShift : -rollShift;

    const int row0 = blockIdx.y*BM, col0 = blockIdx.x*BN;
    const int tid  = threadIdx.x;
    const int warp = tid >> 5, lane = tid & 31;
    const int wy = warp / WCOLS, wx = warp % WCOLS;
    const int g = lane >> 2, c4 = lane & 3;

    uint32_t aoff[MI];
    #pragma unroll
    for (int mi=0; mi<MI; mi++)
        aoff[mi] = (uint32_t)(((wy*WM + mi*16 + (lane & 15))*P + (lane>>4)*4) * 4);
    uint32_t boff[NJ];
    #pragma unroll
    for (int j=0; j<NJ; j++)
        boff[j] = (uint32_t)(((wx*WN + j*16 + ((lane>>4)<<3) + (lane & 7))*P + ((lane>>3)&1)*4) * 4);

    auto load_tile = [&](int kt, int st){
        uint32_t* base = smw + st*STG;
        uint32_t* Ah = base;
        uint32_t* Al = base + TA;
        uint32_t* Bh = base + NST*TA;
        uint32_t* Bl = Bh + TB;
        const int k0 = kt*KCH;
        #pragma unroll
        for (int i=0;i<BM*CH/256;i++){
            int id = tid + i*256; int r = id/CH, q = id%CH;
            int gr = row0 + r;
            if (ROLLMODE) gr = (gr & ~511) | ((gr - rs) & 511);
            long go = (long)gr*lda + k0 + 8*q;
            cp16b(Ah + r*P + 4*q, Ap + go);
            if (COMP) cp16b(Al + r*P + 4*q, Alp + go);
        }
        #pragma unroll
        for (int i=0;i<BN*CH/256;i++){
            int id = tid + i*256; int n = id/CH, q = id%CH;
            long go = (long)(col0+n)*ldb + k0 + 8*q;
            cp16b(Bh + n*P + 4*q, Bp + go);
            if (COMP) cp16b(Bl + n*P + 4*q, Blp + go);
        }
        cp_commit();
    };

    float acc[MI][NI][4];
    #pragma unroll
    for (int i=0;i<MI;i++)
        #pragma unroll
        for (int j=0;j<NI;j++)
            #pragma unroll
            for (int t=0;t<4;t++) acc[i][j][t]=0.f;

    const int nit = Kd/KCH;
    load_tile(0, 0);
    if (NSTG==3 && nit>1) load_tile(1, 1);

    int st = 0;
    for (int it=0; it<nit; it++){
        if (NSTG==3){
            if (it+2 < nit){ load_tile(it+2, (it+2)%3); cp_wait<2>(); }
            else if (it+1 < nit){ cp_wait<1>(); }
            else { cp_wait<0>(); }
        } else {
            if (it+1 < nit){ load_tile(it+1, (it+1)&1); cp_wait<1>(); }
            else { cp_wait<0>(); }
        }
        __syncthreads();

        const uint32_t AhB = smem_u + (uint32_t)(st*STG*4);
        const uint32_t AlB = AhB + TA*4;
        const uint32_t BhB = AhB + NST*TA*4;
        const uint32_t BlB = BhB + TB*4;

        #pragma unroll
        for (int ks=0; ks<KS; ks++){
            const uint32_t ko = ks*32;
            uint32_t af[MI][4], bfr[NI][2];
            uint32_t afl[COMP?MI:1][4], bfl[COMP?NI:1][2];
            #pragma unroll
            for (int mi=0; mi<MI; mi++){
                ldsm4(af[mi][0], af[mi][1], af[mi][2], af[mi][3], AhB + aoff[mi] + ko);
                if (COMP)
                    ldsm4(afl[mi][0], afl[mi][1], afl[mi][2], afl[mi][3], AlB + aoff[mi] + ko);
            }
            #pragma unroll
            for (int j=0; j<NJ; j++){
                ldsm4(bfr[2*j][0], bfr[2*j][1], bfr[2*j+1][0], bfr[2*j+1][1], BhB + boff[j] + ko);
                if (COMP)
                    ldsm4(bfl[2*j][0], bfl[2*j][1], bfl[2*j+1][0], bfl[2*j+1][1], BlB + boff[j] + ko);
            }
            #pragma unroll
            for (int mi=0; mi<MI; mi++)
                #pragma unroll
                for (int ni=0; ni<NI; ni++){
                    if (COMP){
                        mma_bf16(acc[mi][ni], afl[mi], bfr[ni]);
                        mma_bf16(acc[mi][ni], af[mi], bfl[ni]);
                    }
                    mma_bf16(acc[mi][ni], af[mi], bfr[ni]);
                }
        }
        __syncthreads();
        st = (NSTG==3) ? ((st==2)?0:st+1) : (st^1);
    }

    // ---- epilogue ----
    #pragma unroll
    for (int mi=0; mi<MI; mi++){
        #pragma unroll
        for (int half=0; half<2; half++){
            int r = row0 + wy*WM + mi*16 + g + half*8;
            #pragma unroll
            for (int ni=0; ni<NI; ni++){
                int cc = col0 + wx*WN + ni*8 + 2*c4;
                float v0 = acc[mi][ni][half*2+0];
                float v1 = acc[mi][ni][half*2+1];
                if (BIAS){ v0 += bias[cc]; v1 += bias[cc+1]; }
                if (RELU){ v0 = fmaxf(v0,0.f); v1 = fmaxf(v1,0.f); }
                long idx = out_index<PMODE>(r, cc, bz, N, sC);
                if (OUTMODE==0){
                    *(float2*)(C + idx) = make_float2(v0, v1);
                } else if (OUTMODE==1){
                    *(uint32_t*)(Cb + idx) = pk2(v0, v1);
                } else {
                    bf h0 = __float2bfloat16(v0);
                    bf h1 = __float2bfloat16(v1);
                    union { __nv_bfloat162 b; uint32_t u; } cu;
                    cu.b = __halves2bfloat162(h0, h1);
                    *(uint32_t*)(Cb + idx)  = cu.u;
                    *(uint32_t*)(Clo + idx) = pk2(v0 - __bfloat162float(h0),
                                                  v1 - __bfloat162float(h1));
                }
            }
        }
    }
}

// ---------------- fully fused attention: QK -> softmax -> P@V ----------------
__global__ __launch_bounds__(512, 1)
void fa_k(const bf* __restrict__ A, const bf* __restrict__ B,
          const bf* __restrict__ Vt, bf* __restrict__ Y,
          long sA, long sB)
{
    constexpr int Pw  = 20;
    constexpr int TA1 = 64*Pw, TB1 = 512*Pw, STG1 = TA1+TB1;
    constexpr int PWW = 16*64*Pw;            // P region (20480 words)
    constexpr int TB2 = 256*Pw;              // V tile stage (5120 words)
    extern __shared__ uint32_t smw[];
    const uint32_t smem_u = s2u(smw);

    const int bz = blockIdx.z;
    const bf* Ap = A + (long)bz*sA;
    const bf* Bp = B + (long)bz*sB;
    const int row0 = blockIdx.y*64;
    const int tid = threadIdx.x, warp = tid>>5, lane = tid&31;
    const int g = lane>>2, c4 = lane&3;
    const int wy = warp>>3, wx = warp&7;     // 2 x 8 warps

    uint32_t aoff1[2];
    #pragma unroll
    for (int mi=0;mi<2;mi++)
        aoff1[mi] = (uint32_t)(((wy*32 + mi*16 + (lane & 15))*Pw + (lane>>4)*4) * 4);
    uint32_t boff1[4];
    #pragma unroll
    for (int j=0;j<4;j++)
        boff1[j] = (uint32_t)(((wx*64 + j*16 + ((lane>>4)<<3) + (lane & 7))*Pw + ((lane>>3)&1)*4) * 4);

    auto load_tile1 = [&](int kt, int st){
        uint32_t* base = smw + st*STG1;
        uint32_t* Ah = base;
        uint32_t* Bh = base + TA1;
        const int k0 = kt*32;
        if (tid < 256){
            int r = tid>>2, q = tid&3;
            cp16b(Ah + r*Pw + 4*q, Ap + (long)(row0+r)*256 + k0 + 8*q);
        }
        #pragma unroll
        for (int i=0;i<4;i++){
            int id = tid + i*512; int n = id>>2, q = id&3;
            cp16b(Bh + n*Pw + 4*q, Bp + (long)n*256 + k0 + 8*q);
        }
        cp_commit();
    };

    float acc[2][8][4];
    #pragma unroll
    for (int i=0;i<2;i++)
        #pragma unroll
        for (int j=0;j<8;j++)
            #pragma unroll
            for (int t=0;t<4;t++) acc[i][j][t]=0.f;

    {
        const int nit = 8;   // K=256
        load_tile1(0, 0);
        load_tile1(1, 1);
        int st = 0;
        for (int it=0; it<nit; it++){
            if (it+2 < nit){ load_tile1(it+2, (it+2)%3); cp_wait<2>(); }
            else if (it+1 < nit){ cp_wait<1>(); }
            else { cp_wait<0>(); }
            __syncthreads();

            const uint32_t AhB = smem_u + (uint32_t)(st*STG1*4);
            const uint32_t BhB = AhB + TA1*4;
            #pragma unroll
            for (int ks=0; ks<2; ks++){
                const uint32_t ko = ks*32;
                uint32_t af[2][4], bfr[8][2];
                #pragma unroll
                for (int mi=0; mi<2; mi++)
                    ldsm4(af[mi][0], af[mi][1], af[mi][2], af[mi][3], AhB + aoff1[mi] + ko);
                #pragma unroll
                for (int j=0; j<4; j++)
                    ldsm4(bfr[2*j][0], bfr[2*j][1], bfr[2*j+1][0], bfr[2*j+1][1], BhB + boff1[j] + ko);
                #pragma unroll
                for (int mi=0; mi<2; mi++)
                    #pragma unroll
                    for (int ni=0; ni<8; ni++)
                        mma_bf16(acc[mi][ni], af[mi], bfr[ni]);
            }
            __syncthreads();
            st = (st==2) ? 0 : st+1;
        }
    }

    // softmax (scale 1/16)
    float* red_m = (float*)(smw + PWW + 2*TB2);
    float* red_s = red_m + 64*8;
    #pragma unroll
    for (int mi=0; mi<2; mi++){
        #pragma unroll
        for (int half=0; half<2; half++){
            float mx = -INFINITY;
            #pragma unroll
            for (int ni=0; ni<8; ni++)
                mx = fmaxf(mx, fmaxf(acc[mi][ni][half*2], acc[mi][ni][half*2+1]));
            mx *= 0.0625f;
            float s = 0.f;
            #pragma unroll
            for (int ni=0; ni<8; ni++){
                s += expf(acc[mi][ni][half*2+0]*0.0625f - mx);
                s += expf(acc[mi][ni][half*2+1]*0.0625f - mx);
            }
            float m = mx;
            #pragma unroll
            for (int o=1; o<=2; o<<=1){
                float mo = __shfl_xor_sync(0xffffffffu, m, o);
                float so = __shfl_xor_sync(0xffffffffu, s, o);
                ols_merge(m, s, mo, so);
            }
            int rt = wy*32 + mi*16 + half*8 + g;
            if (c4==0){ red_m[rt*8+wx] = m; red_s[rt*8+wx] = s; }
        }
    }
    __syncthreads();
    if (tid < 64){
        float M = red_m[tid*8], S = red_s[tid*8];
        #pragma unroll
        for (int i=1;i<8;i++) ols_merge(M, S, red_m[tid*8+i], red_s[tid*8+i]);
        red_m[tid*8] = M;
        red_s[tid*8] = 1.f/S;
    }
    __syncthreads();
    #pragma unroll
    for (int mi=0; mi<2; mi++){
        #pragma unroll
        for (int half=0; half<2; half++){
            int rt = wy*32 + mi*16 + half*8 + g;
            float M = red_m[rt*8], inv = red_s[rt*8];
            #pragma unroll
            for (int ni=0; ni<8; ni++){
                int c = wx*64 + ni*8 + 2*c4;
                float p0 = expf(acc[mi][ni][half*2+0]*0.0625f - M)*inv;
                float p1 = expf(acc[mi][ni][half*2+1]*0.0625f - M)*inv;
                smw[(c>>5)*(64*Pw) + rt*Pw + ((c&31)>>1)] = pk2(p0, p1);
            }
        }
    }
    __syncthreads();

    // phase 2: y(64x256) = P @ V^T, K=512
    const int wx2 = warp&7, wy2 = warp>>3;
    uint32_t aoff2[2];
    #pragma unroll
    for (int mi=0;mi<2;mi++)
        aoff2[mi] = (uint32_t)(((wy2*32 + mi*16 + (lane & 15))*Pw + (lane>>4)*4) * 4);
    uint32_t boff2a[2];
    #pragma unroll
    for (int j=0;j<2;j++)
        boff2a[j] = (uint32_t)(((wx2*32 + j*16 + ((lane>>4)<<3) + (lane & 7))*Pw + ((lane>>3)&1)*4) * 4);

    auto load_v = [&](int kt, int st){
        uint32_t* Bh = smw + PWW + st*TB2;
        const int k0 = kt*32;
        #pragma unroll
        for (int i=0;i<2;i++){
            int id = tid + i*512; int n = id>>2, q = id&3;
            cp16b(Bh + n*Pw + 4*q, Vt + (long)n*TOK + bz*512 + k0 + 8*q);
        }
        cp_commit();
    };

    float acc2[2][4][4];
    #pragma unroll
    for (int i=0;i<2;i++)
        #pragma unroll
        for (int j=0;j<4;j++)
            #pragma unroll
            for (int t=0;t<4;t++) acc2[i][j][t]=0.f;

    {
        const int nit = 16;  // K=512
        load_v(0, 0);
        int st = 0;
        for (int it=0; it<nit; it++){
            if (it+1 < nit){ load_v(it+1, st^1); cp_wait<1>(); }
            else { cp_wait<0>(); }
            __syncthreads();

            const uint32_t AB = smem_u + (uint32_t)(it*64*Pw*4);
            const uint32_t BB = smem_u + (uint32_t)((PWW + st*TB2)*4);
            #pragma unroll
            for (int ks=0; ks<2; ks++){
                const uint32_t ko = ks*32;
                uint32_t af[2][4], bfr[4][2];
                #pragma unroll
                for (int mi=0; mi<2; mi++)
                    ldsm4(af[mi][0], af[mi][1], af[mi][2], af[mi][3], AB + aoff2[mi] + ko);
                #pragma unroll
                for (int j=0; j<2; j++)
                    ldsm4(bfr[2*j][0], bfr[2*j][1], bfr[2*j+1][0], bfr[2*j+1][1], BB + boff2a[j] + ko);
                #pragma unroll
                for (int mi=0; mi<2; mi++)
                    #pragma unroll
                    for (int ni=0; ni<4; ni++)
                        mma_bf16(acc2[mi][ni], af[mi], bfr[ni]);
            }
            __syncthreads();
            st ^= 1;
        }
    }

    #pragma unroll
    for (int mi=0; mi<2; mi++){
        #pragma unroll
        for (int half=0; half<2; half++){
            int r = row0 + wy2*32 + mi*16 + g + half*8;
            #pragma unroll
            for (int ni=0; ni<4; ni++){
                int cc = wx2*32 + ni*8 + 2*c4;
                long idx = (((long)(bz*512 + (r>>3)))<<11) + ((long)(r&7)<<8) + cc;
                *(uint32_t*)(Y + idx) = pk2(acc2[mi][ni][half*2+0], acc2[mi][ni][half*2+1]);
            }
        }
    }
}

// ---------------- fused logits GEMM + online-LSE partials (COMP, 128x128 tiles) ----------------
__global__ __launch_bounds__(256, 1)
void glse_k(const bf* __restrict__ A, const bf* __restrict__ Alo,
            const bf* __restrict__ B, const bf* __restrict__ Blo,
            float* __restrict__ pm, float* __restrict__ ps)
{
    constexpr int Pw = 20;
    constexpr int TA = 128*Pw, TB = 128*Pw;
    constexpr int STG = 2*(TA+TB);
    extern __shared__ uint32_t smw[];
    const uint32_t smem_u = s2u(smw);

    const int row0 = blockIdx.y*128, col0 = blockIdx.x*128, bx = blockIdx.x;
    const int tid = threadIdx.x, warp = tid>>5, lane = tid&31;
    const int wy = warp>>2, wx = warp&3;     // WM=64, WN=32
    const int g = lane>>2, c4 = lane&3;

    uint32_t aoff[4];
    #pragma unroll
    for (int mi=0;mi<4;mi++)
        aoff[mi] = (uint32_t)(((wy*64 + mi*16 + (lane & 15))*Pw + (lane>>4)*4) * 4);
    uint32_t boff[2];
    #pragma unroll
    for (int j=0;j<2;j++)
        boff[j] = (uint32_t)(((wx*32 + j*16 + ((lane>>4)<<3) + (lane & 7))*Pw + ((lane>>3)&1)*4) * 4);

    auto load_tile = [&](int kt, int st){
        uint32_t* base = smw + st*STG;
        uint32_t* Ah = base;
        uint32_t* Al = base + TA;
        uint32_t* Bh = base + 2*TA;
        uint32_t* Bl = Bh + TB;
        const int k0 = kt*32;
        #pragma unroll
        for (int i=0;i<2;i++){
            int id = tid + i*256; int r = id>>2, q = id&3;
            long go = (long)(row0+r)*256 + k0 + 8*q;
            cp16b(Ah + r*Pw + 4*q, A + go);
            cp16b(Al + r*Pw + 4*q, Alo + go);
            long gb = (long)(col0+r)*256 + k0 + 8*q;
            cp16b(Bh + r*Pw + 4*q, B + gb);
            cp16b(Bl + r*Pw + 4*q, Blo + gb);
        }
        cp_commit();
    };

    float acc[4][4][4];
    #pragma unroll
    for (int i=0;i<4;i++)
        #pragma unroll
        for (int j=0;j<4;j++)
            #pragma unroll
            for (int t=0;t<4;t++) acc[i][j][t]=0.f;

    const int nit = 8;   // K=256
    load_tile(0, 0);
    int st = 0;
    for (int it=0; it<nit; it++){
        if (it+1 < nit){ load_tile(it+1, (it+1)&1); cp_wait<1>(); }
        else { cp_wait<0>(); }
        __syncthreads();

        const uint32_t AhB = smem_u + (uint32_t)(st*STG*4);
        const uint32_t AlB = AhB + TA*4;
        const uint32_t BhB = AhB + 2*TA*4;
        const uint32_t BlB = BhB + TB*4;
        #pragma unroll
        for (int ks=0; ks<2; ks++){
            const uint32_t ko = ks*32;
            uint32_t af[4][4], afl[4][4], bfr[4][2], bfl[4][2];
            #pragma unroll
            for (int mi=0; mi<4; mi++){
                ldsm4(af[mi][0], af[mi][1], af[mi][2], af[mi][3], AhB + aoff[mi] + ko);
                ldsm4(afl[mi][0], afl[mi][1], afl[mi][2], afl[mi][3], AlB + aoff[mi] + ko);
            }
            #pragma unroll
            for (int j=0; j<2; j++){
                ldsm4(bfr[2*j][0], bfr[2*j][1], bfr[2*j+1][0], bfr[2*j+1][1], BhB + boff[j] + ko);
                ldsm4(bfl[2*j][0], bfl[2*j][1], bfl[2*j+1][0], bfl[2*j+1][1], BlB + boff[j] + ko);
            }
            #pragma unroll
            for (int mi=0; mi<4; mi++)
                #pragma unroll
                for (int ni=0; ni<4; ni++){
                    mma_bf16(acc[mi][ni], afl[mi], bfr[ni]);
                    mma_bf16(acc[mi][ni], af[mi], bfl[ni]);
                    mma_bf16(acc[mi][ni], af[mi], bfr[ni]);
                }
        }
        __syncthreads();
        st ^= 1;
    }

    float* red_m = (float*)smw;       // [128][4]
    float* red_s = red_m + 128*4;
    #pragma unroll
    for (int mi=0; mi<4; mi++){
        #pragma unroll
        for (int half=0; half<2; half++){
            float mx = -INFINITY;
            #pragma unroll
            for (int ni=0; ni<4; ni++)
                mx = fmaxf(mx, fmaxf(acc[mi][ni][half*2], acc[mi][ni][half*2+1]));
            float s = 0.f;
            #pragma unroll
            for (int ni=0; ni<4; ni++){
                s += expf(acc[mi][ni][half*2+0]-mx);
                s += expf(acc[mi][ni][half*2+1]-mx);
            }
            float m = mx;
            #pragma unroll
            for (int o=1; o<=2; o<<=1){
                float mo = __shfl_xor_sync(0xffffffffu, m, o);
                float so = __shfl_xor_sync(0xffffffffu, s, o);
                ols_merge(m, s, mo, so);
            }
            int rt = wy*64 + mi*16 + half*8 + g;
            if (c4==0){ red_m[rt*4+wx] = m; red_s[rt*4+wx] = s; }
        }
    }
    __syncthreads();
    if (tid < 128){
        float M = red_m[tid*4], S = red_s[tid*4];
        #pragma unroll
        for (int i=1;i<4;i++) ols_merge(M, S, red_m[tid*4+i], red_s[tid*4+i]);
        long idx = (long)(row0+tid)*250 + bx;
        pm[idx] = M;
        ps[idx] = S;
    }
}

// merge 250 partials per row -> lse
__global__ void lse_red_k(const float* __restrict__ pm, const float* __restrict__ ps,
                          float* __restrict__ lse){
    int row = blockIdx.x*8 + (threadIdx.x>>5);
    int lane = threadIdx.x & 31;
    float m = -INFINITY, s = 0.f;
    for (int i=lane; i<250; i+=32)
        ols_merge(m, s, pm[(long)row*250+i], ps[(long)row*250+i]);
    #pragma unroll
    for (int o=16;o;o>>=1){
        float mo = __shfl_xor_sync(0xffffffffu, m, o);
        float so = __shfl_xor_sync(0xffffffffu, s, o);
        ols_merge(m, s, mo, so);
    }
    if (lane==0) lse[row] = m + logf(s);
}

// exact fp32 target logit
__global__ void tval_k(const bf* __restrict__ vhi, const bf* __restrict__ vlo,
                       const bf* __restrict__ ehi, const bf* __restrict__ elo,
                       const int* __restrict__ unmasked, const int* __restrict__ mask,
                       float* __restrict__ tval){
    int row = blockIdx.x;
    int b = row >> 8, n = row & 255, j = n >> 2;
    int tg = unmasked[b*Ll + mask[b*LM + j]];
    long vi = (long)row*Ee + threadIdx.x;
    long ei = (long)tg*Ee + threadIdx.x;
    float v = (__bfloat162float(vhi[vi]) + __bfloat162float(vlo[vi]))
            * (__bfloat162float(ehi[ei]) + __bfloat162float(elo[ei]));
    float s = block_sum256(v);
    if (threadIdx.x==0) tval[row] = s;
}

// ---------------- prep kernels ----------------
__global__ void prep_w_k(const float* __restrict__ Wt, const float* __restrict__ Wtc,
                         const float* __restrict__ Wu,
                         bf* __restrict__ wc1, bf* __restrict__ wc2)
{
    long idx = (long)blockIdx.x*1024 + threadIdx.x;
    if (idx >= (long)Dd*5*65536) return;
    int d = idx / (5*65536);
    int r = idx % (5*65536);
    int which = r / 65536;
    int e = r % 65536;
    int n = e >> 8, k = e & 255;
    long wb = (long)d*65536;
    if      (which==0) wc1[(long)d*131072 +         n*256+k] = __float2bfloat16(Wt [wb + (long)k*256 + n]);
    else if (which==1) wc1[(long)d*131072 + 65536 + n*256+k] = __float2bfloat16(Wtc[wb + (long)n*256 + k]);
    else if (which==2) wc2[(long)d*196608 + (long)n*768 +       k] = __float2bfloat16(Wtc[wb + (long)k*256 + n]);
    else if (which==3) wc2[(long)d*196608 + (long)n*768 + 256 + k] = __float2bfloat16(Wt [wb + (long)n*256 + k]);
    else               wc2[(long)d*196608 + (long)n*768 + 512 + k] = __float2bfloat16(Wu [wb + (long)n*256 + k]);
}

__global__ void conv_b4(const float4* __restrict__ in, uint2* __restrict__ outp, long n4){
    long i = (long)blockIdx.x*256 + threadIdx.x;
    if (i >= n4) return;
    float4 v = in[i];
    uint2 o; o.x = pk2(v.x, v.y); o.y = pk2(v.z, v.w);
    outp[i] = o;
}

__global__ void split_b4(const float4* __restrict__ in, uint2* __restrict__ hi,
                         uint2* __restrict__ lo, long n4){
    long i = (long)blockIdx.x*256 + threadIdx.x;
    if (i >= n4) return;
    float4 v = in[i];
    bf hx=__float2bfloat16(v.x), hy=__float2bfloat16(v.y);
    bf hz=__float2bfloat16(v.z), hw=__float2bfloat16(v.w);
    union { __nv_bfloat162 b; uint32_t u; } c0, c1;
    c0.b = __halves2bfloat162(hx, hy);
    c1.b = __halves2bfloat162(hz, hw);
    uint2 h; h.x=c0.u; h.y=c1.u;
    uint2 l;
    l.x = pk2(v.x-__bfloat162float(hx), v.y-__bfloat162float(hy));
    l.y = pk2(v.z-__bfloat162float(hz), v.w-__bfloat162float(hw));
    hi[i]=h; lo[i]=l;
}

__global__ void split_lo4(const float4* __restrict__ in, uint2* __restrict__ lo, long n4){
    long i = (long)blockIdx.x*256 + threadIdx.x;
    if (i >= n4) return;
    float4 v = in[i];
    bf hx=__float2bfloat16(v.x), hy=__float2bfloat16(v.y);
    bf hz=__float2bfloat16(v.z), hw=__float2bfloat16(v.w);
    uint2 l;
    l.x = pk2(v.x-__bfloat162float(hx), v.y-__bfloat162float(hy));
    l.y = pk2(v.z-__bfloat162float(hz), v.w-__bfloat162float(hw));
    lo[i]=l;
}

__global__ void t32_f2b(const float* __restrict__ src, bf* __restrict__ dst, int R, int C){
    __shared__ bf t[32][33];
    const float* s = src + (long)blockIdx.z*R*C;
    bf* d = dst + (long)blockIdx.z*R*C;
    int r0 = blockIdx.x*32, c0 = blockIdx.y*32;
    int tx = threadIdx.x & 31, ty = threadIdx.x >> 5;
    #pragma unroll
    for (int i=0;i<4;i++) t[ty+8*i][tx] = __float2bfloat16(s[(long)(r0+ty+8*i)*C + c0+tx]);
    __syncthreads();
    #pragma unroll
    for (int i=0;i<4;i++) d[(long)(c0+ty+8*i)*R + r0+tx] = t[tx][ty+8*i];
}

__global__ void t32_f2b2(const float* __restrict__ src, bf* __restrict__ dh,
                         bf* __restrict__ dl, int R, int C){
    __shared__ bf th[32][33];
    __shared__ bf tl[32][33];
    int r0 = blockIdx.x*32, c0 = blockIdx.y*32;
    int tx = threadIdx.x & 31, ty = threadIdx.x >> 5;
    #pragma unroll
    for (int i=0;i<4;i++){
        float v = src[(long)(r0+ty+8*i)*C + c0+tx];
        bf h = __float2bfloat16(v);
        th[ty+8*i][tx] = h;
        tl[ty+8*i][tx] = __float2bfloat16(v - __bfloat162float(h));
    }
    __syncthreads();
    #pragma unroll
    for (int i=0;i<4;i++){
        dh[(long)(c0+ty+8*i)*R + r0+tx] = th[tx][ty+8*i];
        dl[(long)(c0+ty+8*i)*R + r0+tx] = tl[tx][ty+8*i];
    }
}

__global__ void transpose_b(const bf* __restrict__ src, bf* __restrict__ dst, int R, int C){
    __shared__ bf t[32][33];
    int r0 = blockIdx.x*32, c0 = blockIdx.y*32;
    int tx = threadIdx.x & 31, ty = threadIdx.x >> 5;
    #pragma unroll
    for (int i=0;i<4;i++) t[ty+8*i][tx] = src[(long)(r0+ty+8*i)*C + c0+tx];
    __syncthreads();
    #pragma unroll
    for (int i=0;i<4;i++) dst[(long)(c0+ty+8*i)*R + r0+tx] = t[tx][ty+8*i];
}

// ---------------- elementwise / reduction kernels ----------------
__global__ void embed_norm_k(const int* __restrict__ masked, const float* __restrict__ embed,
                             float* __restrict__ xsa, bf* __restrict__ xsab,
                             bf* __restrict__ xsat, bf* __restrict__ acat)
{
    int t = blockIdx.x;
    int g = masked[t];
    float v = embed[(long)g*Ee + threadIdx.x];
    float mean = block_sum256(v) * (1.f/Ee);
    float d = v - mean;
    float var = block_sum256(d*d) * (1.f/(Ee-1));
    float o = v / (1.f + sqrtf(var));
    xsa [(long)t*Ee + threadIdx.x] = o;
    bf ob = __float2bfloat16(o);
    xsab[(long)t*Ee + threadIdx.x] = ob;
    xsat[(long)threadIdx.x*TOK + t] = ob;
    acat[(long)t*768 + 512 + threadIdx.x] = ob;
}

__global__ void update_norm_k(const float* __restrict__ xsad, const float* __restrict__ t1p,
                              float* __restrict__ xsa, bf* __restrict__ xsab,
                              bf* __restrict__ xsat)
{
    long idx = (long)blockIdx.x*Ee + threadIdx.x;
    const long S = (long)TOK*Ee;
    float u = xsad[idx] + t1p[idx] + t1p[idx+S] + t1p[idx+2*S] + t1p[idx+3*S];
    float mean = block_sum256(u) * (1.f/Ee);
    float d = u - mean;
    float var = block_sum256(d*d) * (1.f/(Ee-1));
    float un = u / (1.f + sqrtf(var));
    float w = xsa[idx] + 0.05f * un;
    float mean2 = block_sum256(w) * (1.f/Ee);
    float d2 = w - mean2;
    float var2 = block_sum256(d2*d2) * (1.f/(Ee-1));
    float o = w / (1.f + sqrtf(var2));
    xsa[idx]  = o;
    bf ob = __float2bfloat16(o);
    xsab[idx] = ob;
    xsat[(long)threadIdx.x*TOK + blockIdx.x] = ob;
}

__global__ void gather_split_k(const int* __restrict__ mask, const float* __restrict__ xsa,
                               bf* __restrict__ hi, bf* __restrict__ lo){
    int r = blockIdx.x; int b = r >> 6; int p = mask[r];
    float v = xsa[(long)(b*Ll + p)*Ee + threadIdx.x];
    bf h = __float2bfloat16(v);
    hi[(long)r*Ee + threadIdx.x] = h;
    lo[(long)r*Ee + threadIdx.x] = __float2bfloat16(v - __bfloat162float(h));
}

__global__ void final_k(const float* __restrict__ tval, const float* __restrict__ lse,
                        float* __restrict__ out)
{
    int b = blockIdx.x, j = threadIdx.x;   // 64 threads
    float a[KN]; float m = -INFINITY;
    #pragma unroll
    for (int kn=0;kn<KN;kn++){
        int r = ((b << 6) + j) * KN + kn;
        a[kn] = tval[r] - lse[r];
        m = fmaxf(m, a[kn]);
    }
    float s = 0.f;
    #pragma unroll
    for (int kn=0;kn<KN;kn++) s += expf(a[kn] - m);
    float cent = m + logf(s) - 1.3862943611198906f;   // - log(4)
    __shared__ float sh[64];
    sh[j] = cent; __syncthreads();
    for (int o=32;o;o>>=1){ if (j<o) sh[j] += sh[j+o]; __syncthreads(); }
    if (j==0) out[b] = -sh[0] / (float)LM;
}

// ---------------- host orchestration ----------------
#define GSYM(p, s) cudaGetSymbolAddress((void**)&p, s)

extern "C" void kernel_launch(void* const* d_in, const int* in_sizes, int n_in,
                              void* d_out, int out_size)
{
    (void)in_sizes; (void)n_in; (void)out_size;
    const int*   masked   = (const int*)  d_in[0];
    const int*   unmasked = (const int*)  d_in[1];
    const int*   maskp    = (const int*)  d_in[2];
    const float* embed    = (const float*)d_in[3];
    const float* Wt       = (const float*)d_in[4];
    const float* bt       = (const float*)d_in[5];
    const float* Wtc      = (const float*)d_in[6];
    const float* Wq       = (const float*)d_in[7];
    const float* Wd       = (const float*)d_in[8];
    const float* Wo       = (const float*)d_in[9];
    const float* Wu       = (const float*)d_in[10];
    const float* Wem      = (const float*)d_in[11];
    const float* Wkc      = (const float*)d_in[12];
    const float* bkc      = (const float*)d_in[13];
    float* out = (float*)d_out;

    float *xsa,*xsad,*t1p,*pm,*ps,*lse,*tval;
    bf *xsab,*xsat,*acat,*q2b,*yb,*midb;
    bf *wq,*wd,*wot,*wc1,*wc2;
    bf *ehi,*elo,*xhlo,*xtlo,*wkhi,*wklo,*wmhi,*wmlo;
    bf *lphi,*lplo,*x1hi,*x1lo,*shi,*slo,*xxhi,*xxlo,*vhi,*vlo;
    GSYM(xsa,g_xsa); GSYM(xsad,g_xsad); GSYM(t1p,g_t1p);
    GSYM(pm,g_pm); GSYM(ps,g_ps); GSYM(lse,g_lse); GSYM(tval,g_tval);
    GSYM(xsab,g_xsab); GSYM(xsat,g_xsat); GSYM(acat,g_acat);
    GSYM(q2b,g_q2b); GSYM(yb,g_yb); GSYM(midb,g_midb);
    GSYM(wq,g_wq); GSYM(wd,g_wd); GSYM(wot,g_wot); GSYM(wc1,g_wc1); GSYM(wc2,g_wc2);
    GSYM(ehi,g_ehi); GSYM(elo,g_elo); GSYM(xhlo,g_xhlo); GSYM(xtlo,g_xtlo);
    GSYM(wkhi,g_wkhi); GSYM(wklo,g_wklo); GSYM(wmhi,g_wmhi); GSYM(wmlo,g_wmlo);
    GSYM(lphi,g_lphi); GSYM(lplo,g_lplo);
    GSYM(x1hi,g_x1hi); GSYM(x1lo,g_x1lo); GSYM(shi,g_shi); GSYM(slo,g_slo);
    GSYM(xxhi,g_xxhi); GSYM(xxlo,g_xxlo); GSYM(vhi,g_vhi); GSYM(vlo,g_vlo);

    // kernel instantiations (layer GEMMs: KCH=64; head COMP GEMMs: KCH=32)
    auto kS1 = bgemm_k<64,64,32,16,64,true ,false,4,2,false,1>;
    auto kS2 = bgemm_k<64,64,32,16,64,false,true ,0,0,false,0>;
    auto kWq = bgemm_k<128,128,64,32,64,false,false,1,0,false,1>;
    auto kWd = bgemm_k<128,128,64,32,64,true ,false,0,0,false,1>;
    auto kWo = bgemm_k<64,64,32,16,64,false,false,0,0,false,0>;
    auto kG1 = bgemm_k<64,64,32,16,32,false,true ,3,0,true ,2>;
    auto kG2 = bgemm_k<64,64,32,16,32,false,false,0,0,true ,2>;
    auto kG3 = bgemm_k<64,64,32,16,32,false,false,0,0,true ,2>;
    auto kG4 = bgemm_k<64,64,32,16,32,false,false,0,0,true ,2>;

    constexpr int SM_BIG64 = 2*(128+128)*36*4;   // 73728 B
    constexpr int SM_SML64 = 2*(64+64)*36*4;     // 36864 B
    constexpr int SM_CMP   = 3*2*(64+64)*20*4;   // 61440 B
    constexpr int SM_FA    = 3*(64+512)*20*4;    // 138240 B
    constexpr int SM_GLSE  = 2*2*(128+128)*20*4; // 81920 B

    cudaFuncSetAttribute(kS1, cudaFuncAttributeMaxDynamicSharedMemorySize, SM_SML64);
    cudaFuncSetAttribute(kS2, cudaFuncAttributeMaxDynamicSharedMemorySize, SM_SML64);
    cudaFuncSetAttribute(kWo, cudaFuncAttributeMaxDynamicSharedMemorySize, SM_SML64);
    cudaFuncSetAttribute(kWq, cudaFuncAttributeMaxDynamicSharedMemorySize, SM_BIG64);
    cudaFuncSetAttribute(kWd, cudaFuncAttributeMaxDynamicSharedMemorySize, SM_BIG64);
    cudaFuncSetAttribute(kG1, cudaFuncAttributeMaxDynamicSharedMemorySize, SM_CMP);
    cudaFuncSetAttribute(kG2, cudaFuncAttributeMaxDynamicSharedMemorySize, SM_CMP);
    cudaFuncSetAttribute(kG3, cudaFuncAttributeMaxDynamicSharedMemorySize, SM_CMP);
    cudaFuncSetAttribute(kG4, cudaFuncAttributeMaxDynamicSharedMemorySize, SM_CMP);
    cudaFuncSetAttribute(fa_k, cudaFuncAttributeMaxDynamicSharedMemorySize, SM_FA);
    cudaFuncSetAttribute(glse_k, cudaFuncAttributeMaxDynamicSharedMemorySize, SM_GLSE);

    // ---- prep: bf16 weights (per launch; graph-captured) ----
    prep_w_k<<<(Dd*5*65536+1023)/1024,1024>>>(Wt, Wtc, Wu, wc1, wc2);
    conv_b4<<<((long)Dd*KE*Ee/4+255)/256,256>>>((const float4*)Wq, (uint2*)wq, (long)Dd*KE*Ee/4);
    conv_b4<<<((long)Dd*KE*KE/4+255)/256,256>>>((const float4*)Wd, (uint2*)wd, (long)Dd*KE*KE/4);
    t32_f2b<<<dim3(KE/32,Ee/32,Dd),256>>>(Wo, wot, KE, Ee);
    split_b4<<<((long)Gg*Ee/4+255)/256,256>>>((const float4*)embed, (uint2*)ehi, (uint2*)elo, (long)Gg*Ee/4);
    split_b4<<<(KN*Ee*Ee/4+255)/256,256>>>((const float4*)Wkc, (uint2*)wkhi, (uint2*)wklo, KN*Ee*Ee/4);
    t32_f2b2<<<dim3(Ee/32,Ee/32,1),256>>>(Wem, wmhi, wmlo, Ee, Ee);

    embed_norm_k<<<TOK,256>>>(masked, embed, xsa, xsab, xsat, acat);

    for (int d=0; d<Dd; d++){
        // transitions
        kS1<<<dim3(4,32,2),256,SM_SML64>>>(xsab,0, wc1+(long)d*131072,0, 0, 0,acat,0,
                                           TOK,Ee,Ee, Ee,Ee, 0, 65536, 0, 1);
        kS2<<<dim3(4,32,1),256,SM_SML64>>>(acat,0, wc2+(long)d*196608,0, bt+(long)d*Ee, xsad,0,0,
                                           TOK,Ee,768, 768,768, 0,0,0, 0);

        // attention (fully fused: QK -> softmax -> P@V)
        kWq<<<dim3(16,16,1),256,SM_BIG64>>>(xsab,0, wq+(long)d*KE*Ee,0, 0, 0,q2b,0,
                                            TOK,KE,Ee, Ee,Ee, 0,0,0, 0);
        fa_k<<<dim3(1,64,Bb),512,SM_FA>>>(q2b, xsab, xsat, yb,
                                          (long)Ll*Kk*Ee, (long)Ll*Ee);

        // dense -> relu -> dense (Wo via split-K=4)
        kWd<<<dim3(16,16,1),256,SM_BIG64>>>(yb,0, wd+(long)d*KE*KE,0, 0, 0,midb,0,
                                            TOK,KE,KE, KE,KE, 0,0,0, 0);
        kWo<<<dim3(4,32,4),256,SM_SML64>>>(midb,0, wot+(long)d*Ee*KE,0, 0, t1p,0,0,
                                           TOK,Ee,512, KE,KE, 512, 512, (long)TOK*Ee, 0);

        update_norm_k<<<TOK,256>>>(xsad, t1p, xsa, xsab, xsat);
    }

    // ---- head (split-bf16 3-mma; hi of xsa == xsab/xsat) ----
    split_lo4<<<(TOK*Ee/4+255)/256,256>>>((const float4*)xsa, (uint2*)xhlo, TOK*Ee/4);
    transpose_b<<<dim3(TOK/32,Ee/32),256>>>(xhlo, xtlo, TOK, Ee);
    gather_split_k<<<Bb*LM,256>>>(maskp, xsa, lphi, lplo);

    kG1<<<dim3(16,4,1),256,SM_CMP>>>(lphi,lplo, wkhi,wklo, bkc, 0,x1hi,x1lo,
                                     Bb*LM, KN*Ee, Ee, Ee,Ee, 0,0,0, 0);
    kG2<<<dim3(8,4,Bb),256,SM_CMP>>>(x1hi,x1lo, xsab,xhlo, 0, 0,shi,slo,
                                     LM*KN, Ll, Ee, Ee,Ee,
                                     (long)LM*KN*Ee, (long)Ll*Ee, (long)LM*KN*Ll, 0);
    kG3<<<dim3(4,4,Bb),256,SM_CMP>>>(shi,slo, xsat,xtlo, 0, 0,xxhi,xxlo,
                                     LM*KN, Ee, Ll, Ll,TOK,
                                     (long)LM*KN*Ll, (long)Ll, (long)LM*KN*Ee, 0);
    kG4<<<dim3(4,16,1),256,SM_CMP>>>(xxhi,xxlo, wmhi,wmlo, 0, 0,vhi,vlo,
                                     Bb*LM*KN, Ee, Ee, Ee,Ee, 0,0,0, 0);

    // fused logits + LSE (no logits buffer), 128x128 tiles
    glse_k<<<dim3(250,8,1),256,SM_GLSE>>>(vhi, vlo, ehi, elo, pm, ps);
    lse_red_k<<<(Bb*LM*KN)/8,256>>>(pm, ps, lse);
    tval_k<<<Bb*LM*KN,256>>>(vhi, vlo, ehi, elo, unmasked, maskp, tval);
    final_k<<<Bb,64>>>(tval, lse, out);
}

// round 14
// speedup vs baseline: 2.1422x; 1.0262x over previous
#include <cuda_runtime.h>
#include <cuda_bf16.h>
#include <math.h>
#include <stdint.h>

// ---------------- problem constants ----------------
#define Bb 4
#define Ll 512
#define Ee 256
#define Kk 8
#define Dd 6
#define LM 64
#define KN 4
#define Gg 32000
#define KE (Kk*Ee)          // 2048
#define TOK (Bb*Ll)         // 2048

typedef __nv_bfloat16 bf;

// ---------------- scratch (static device memory; no allocations) ----------------
__device__ float g_xsa [TOK*Ee];
__device__ float g_xsad[TOK*Ee];
__device__ float g_t1p [4L*TOK*Ee];                  // kWo split-K partials
__device__ bf    g_xsab[TOK*Ee];                     // xsa bf16 [t][e]
__device__ bf    g_xsat[Ee*TOK];                     // xsa bf16 transposed [e][t]
__device__ bf    g_acat[TOK*768];                    // [t1a | t1b | z] bf16
__device__ bf    g_q2b [TOK*KE];
__device__ bf    g_yb  [TOK*KE];
__device__ bf    g_midb[TOK*KE];
// bf16 weights (prep)
__device__ bf    g_wq [(long)Dd*KE*Ee];
__device__ bf    g_wd [(long)Dd*KE*KE];
__device__ bf    g_wot[(long)Dd*Ee*KE];              // Wo^T  [n=E][k=KE]
__device__ bf    g_wc1[Dd*2*Ee*Ee];                  // [Wt^T][Wtc] as [n][k]
__device__ bf    g_wc2[Dd*Ee*768];                   // [Wtc^T|Wt|Wu] rows n, k=768
// head hi/lo bf16 splits (hi of xsa == xsab/xsat)
__device__ bf    g_ehi[(long)Gg*Ee], g_elo[(long)Gg*Ee];
__device__ bf    g_xhlo[TOK*Ee];
__device__ bf    g_xtlo[Ee*TOK];
__device__ bf    g_wkhi[KN*Ee*Ee],g_wklo[KN*Ee*Ee];
__device__ bf    g_wmhi[Ee*Ee],   g_wmlo[Ee*Ee];     // Wem^T hi/lo
__device__ bf    g_lphi[Bb*LM*Ee],g_lplo[Bb*LM*Ee];
__device__ bf    g_x1hi[Bb*LM*KN*Ee], g_x1lo[Bb*LM*KN*Ee];
__device__ bf    g_shi[(long)Bb*LM*KN*Ll], g_slo[(long)Bb*LM*KN*Ll];
__device__ bf    g_xxhi[Bb*LM*KN*Ee], g_xxlo[Bb*LM*KN*Ee];
__device__ bf    g_vhi[Bb*LM*KN*Ee],  g_vlo[Bb*LM*KN*Ee];
// fused-LSE partials (1024 rows x 250 col-blocks)
__device__ float g_pm[(long)Bb*LM*KN*250];
__device__ float g_ps[(long)Bb*LM*KN*250];
__device__ float g_lse [Bb*LM*KN];
__device__ float g_tval[Bb*LM*KN];

// ---------------- reductions ----------------
__device__ __forceinline__ float warp_sum(float v){
    #pragma unroll
    for (int o=16;o;o>>=1) v += __shfl_xor_sync(0xffffffffu, v, o);
    return v;
}
__device__ float block_sum256(float v){
    __shared__ float sh[8];
    int lane = threadIdx.x & 31, w = threadIdx.x >> 5;
    v = warp_sum(v);
    if (lane==0) sh[w] = v;
    __syncthreads();
    float r = (threadIdx.x < 8) ? sh[threadIdx.x] : 0.f;
    if (w==0){ r = warp_sum(r); if (lane==0) sh[0]=r; }
    __syncthreads();
    float out = sh[0];
    __syncthreads();
    return out;
}

// ---------------- bf16 / mma / cp.async / ldmatrix helpers ----------------
__device__ __forceinline__ uint32_t pk2(float lo, float hi){
    uint32_t r;
    asm("cvt.rn.bf16x2.f32 %0, %1, %2;" : "=r"(r) : "f"(hi), "f"(lo));
    return r;
}
__device__ __forceinline__ void mma_bf16(float* d, const uint32_t* a, const uint32_t* b){
    asm volatile(
      "mma.sync.aligned.m16n8k16.row.col.f32.bf16.bf16.f32 "
      "{%0,%1,%2,%3}, {%4,%5,%6,%7}, {%8,%9}, {%0,%1,%2,%3};\n"
      : "+f"(d[0]),"+f"(d[1]),"+f"(d[2]),"+f"(d[3])
      : "r"(a[0]),"r"(a[1]),"r"(a[2]),"r"(a[3]), "r"(b[0]),"r"(b[1]));
}
__device__ __forceinline__ void cp16b(void* s, const bf* g){
    uint32_t sa = (uint32_t)__cvta_generic_to_shared(s);
    asm volatile("cp.async.ca.shared.global [%0], [%1], 16;\n" :: "r"(sa), "l"(g));
}
__device__ __forceinline__ void cp_commit(){ asm volatile("cp.async.commit_group;\n" ::); }
template<int W> __device__ __forceinline__ void cp_wait(){ asm volatile("cp.async.wait_group %0;\n" :: "n"(W)); }
__device__ __forceinline__ uint32_t s2u(const void* p){
    uint32_t a;
    asm("{ .reg .u64 t; cvta.to.shared.u64 t, %1; cvt.u32.u64 %0, t; }" : "=r"(a) : "l"(p));
    return a;
}
__device__ __forceinline__ void ldsm4(uint32_t& r0, uint32_t& r1, uint32_t& r2, uint32_t& r3,
                                      uint32_t addr){
    asm volatile("ldmatrix.sync.aligned.m8n8.x4.shared.b16 {%0,%1,%2,%3}, [%4];"
        : "=r"(r0),"=r"(r1),"=r"(r2),"=r"(r3) : "r"(addr));
}
__device__ __forceinline__ void ols_merge(float& m, float& s, float mo, float so){
    float mn = fmaxf(m, mo);
    s = s*expf(m - mn) + so*expf(mo - mn);
    m = mn;
}

// PMODE output index mapping (element index):
template<int PMODE>
__device__ __forceinline__ long out_index(int r, int c, int bz, int N, long sC){
    if (PMODE==0) return (long)bz*sC + (long)r*N + c;
    if (PMODE==1) return (((long)(r>>9))<<20) + ((long)(r&511)<<11) + c;
    if (PMODE==2) return (((long)(bz*512 + (r>>3)))<<11) + ((long)(r&7)<<8) + c;
    if (PMODE==3) return (((long)(r>>6))<<16) + ((long)(r&63)<<10) + c;
    return (long)r*768 + ((long)bz<<8) + c;
}

// ---------------- unified bf16 tensor-core GEMM (ldmatrix, templated K-chunk) ----------------
// KCH = K elements per smem tile (32 -> pitch 20, 3-stage; 64 -> pitch 36, 2-stage).
template<int BM,int BN,int WM,int WN,int KCH,bool RELU,bool BIAS,int PMODE,int ROLLMODE,bool COMP,int OUTMODE>
__global__ __launch_bounds__(256, 2)
void bgemm_k(const bf* __restrict__ A, const bf* __restrict__ Alo,
             const bf* __restrict__ B, const bf* __restrict__ Blo,
             const float* __restrict__ bias,
             float* __restrict__ C, bf* __restrict__ Cb, bf* __restrict__ Clo,
             int M, int N, int Kd, int lda, int ldb,
             long sA, long sB, long sC, int rollShift)
{
    constexpr int P    = KCH/2 + 4;          // words per smem row
    constexpr int CH   = KCH/8;              // 16B chunks per row
    constexpr int NSTG = (KCH==64) ? 2 : 3;
    constexpr int NST  = COMP ? 2 : 1;
    constexpr int TA   = BM*P, TB = BN*P;
    constexpr int STG  = NST*(TA+TB);
    constexpr int MI   = WM/16, NI = WN/8;
    constexpr int NJ   = NI/2;
    constexpr int WCOLS = BN/WN;
    constexpr int KS   = KCH/16;

    extern __shared__ uint32_t smw[];
    const uint32_t smem_u = s2u(smw);

    const int bz = blockIdx.z;
    const bf* Ap  = A + (long)bz*sA;
    const bf* Alp = COMP ? Alo + (long)bz*sA : nullptr;
    const bf* Bp  = B + (long)bz*sB;
    const bf* Blp = COMP ? Blo + (long)bz*sB : nullptr;

    int rs = 0;
    if (ROLLMODE==2) rs = (bz==0) ? rollShift : -rollShift;

    const int row0 = blockIdx.y*BM, col0 = blockIdx.x*BN;
    const int tid  = threadIdx.x;
    const int warp = tid >> 5, lane = tid & 31;
    const int wy = warp / WCOLS, wx = warp % WCOLS;
    const int g = lane >> 2, c4 = lane & 3;

    uint32_t aoff[MI];
    #pragma unroll
    for (int mi=0; mi<MI; mi++)
        aoff[mi] = (uint32_t)(((wy*WM + mi*16 + (lane & 15))*P + (lane>>4)*4) * 4);
    uint32_t boff[NJ];
    #pragma unroll
    for (int j=0; j<NJ; j++)
        boff[j] = (uint32_t)(((wx*WN + j*16 + ((lane>>4)<<3) + (lane & 7))*P + ((lane>>3)&1)*4) * 4);

    auto load_tile = [&](int kt, int st){
        uint32_t* base = smw + st*STG;
        uint32_t* Ah = base;
        uint32_t* Al = base + TA;
        uint32_t* Bh = base + NST*TA;
        uint32_t* Bl = Bh + TB;
        const int k0 = kt*KCH;
        #pragma unroll
        for (int i=0;i<BM*CH/256;i++){
            int id = tid + i*256; int r = id/CH, q = id%CH;
            int gr = row0 + r;
            if (ROLLMODE) gr = (gr & ~511) | ((gr - rs) & 511);
            long go = (long)gr*lda + k0 + 8*q;
            cp16b(Ah + r*P + 4*q, Ap + go);
            if (COMP) cp16b(Al + r*P + 4*q, Alp + go);
        }
        #pragma unroll
        for (int i=0;i<BN*CH/256;i++){
            int id = tid + i*256; int n = id/CH, q = id%CH;
            long go = (long)(col0+n)*ldb + k0 + 8*q;
            cp16b(Bh + n*P + 4*q, Bp + go);
            if (COMP) cp16b(Bl + n*P + 4*q, Blp + go);
        }
        cp_commit();
    };

    float acc[MI][NI][4];
    #pragma unroll
    for (int i=0;i<MI;i++)
        #pragma unroll
        for (int j=0;j<NI;j++)
            #pragma unroll
            for (int t=0;t<4;t++) acc[i][j][t]=0.f;

    const int nit = Kd/KCH;
    load_tile(0, 0);
    if (NSTG==3 && nit>1) load_tile(1, 1);

    int st = 0;
    for (int it=0; it<nit; it++){
        if (NSTG==3){
            if (it+2 < nit){ load_tile(it+2, (it+2)%3); cp_wait<2>(); }
            else if (it+1 < nit){ cp_wait<1>(); }
            else { cp_wait<0>(); }
        } else {
            if (it+1 < nit){ load_tile(it+1, (it+1)&1); cp_wait<1>(); }
            else { cp_wait<0>(); }
        }
        __syncthreads();

        const uint32_t AhB = smem_u + (uint32_t)(st*STG*4);
        const uint32_t AlB = AhB + TA*4;
        const uint32_t BhB = AhB + NST*TA*4;
        const uint32_t BlB = BhB + TB*4;

        #pragma unroll
        for (int ks=0; ks<KS; ks++){
            const uint32_t ko = ks*32;
            uint32_t af[MI][4], bfr[NI][2];
            uint32_t afl[COMP?MI:1][4], bfl[COMP?NI:1][2];
            #pragma unroll
            for (int mi=0; mi<MI; mi++){
                ldsm4(af[mi][0], af[mi][1], af[mi][2], af[mi][3], AhB + aoff[mi] + ko);
                if (COMP)
                    ldsm4(afl[mi][0], afl[mi][1], afl[mi][2], afl[mi][3], AlB + aoff[mi] + ko);
            }
            #pragma unroll
            for (int j=0; j<NJ; j++){
                ldsm4(bfr[2*j][0], bfr[2*j][1], bfr[2*j+1][0], bfr[2*j+1][1], BhB + boff[j] + ko);
                if (COMP)
                    ldsm4(bfl[2*j][0], bfl[2*j][1], bfl[2*j+1][0], bfl[2*j+1][1], BlB + boff[j] + ko);
            }
            #pragma unroll
            for (int mi=0; mi<MI; mi++)
                #pragma unroll
                for (int ni=0; ni<NI; ni++){
                    if (COMP){
                        mma_bf16(acc[mi][ni], afl[mi], bfr[ni]);
                        mma_bf16(acc[mi][ni], af[mi], bfl[ni]);
                    }
                    mma_bf16(acc[mi][ni], af[mi], bfr[ni]);
                }
        }
        __syncthreads();
        st = (NSTG==3) ? ((st==2)?0:st+1) : (st^1);
    }

    // ---- epilogue ----
    #pragma unroll
    for (int mi=0; mi<MI; mi++){
        #pragma unroll
        for (int half=0; half<2; half++){
            int r = row0 + wy*WM + mi*16 + g + half*8;
            #pragma unroll
            for (int ni=0; ni<NI; ni++){
                int cc = col0 + wx*WN + ni*8 + 2*c4;
                float v0 = acc[mi][ni][half*2+0];
                float v1 = acc[mi][ni][half*2+1];
                if (BIAS){ v0 += bias[cc]; v1 += bias[cc+1]; }
                if (RELU){ v0 = fmaxf(v0,0.f); v1 = fmaxf(v1,0.f); }
                long idx = out_index<PMODE>(r, cc, bz, N, sC);
                if (OUTMODE==0){
                    *(float2*)(C + idx) = make_float2(v0, v1);
                } else if (OUTMODE==1){
                    *(uint32_t*)(Cb + idx) = pk2(v0, v1);
                } else {
                    bf h0 = __float2bfloat16(v0);
                    bf h1 = __float2bfloat16(v1);
                    union { __nv_bfloat162 b; uint32_t u; } cu;
                    cu.b = __halves2bfloat162(h0, h1);
                    *(uint32_t*)(Cb + idx)  = cu.u;
                    *(uint32_t*)(Clo + idx) = pk2(v0 - __bfloat162float(h0),
                                                  v1 - __bfloat162float(h1));
                }
            }
        }
    }
}

// ---------------- fully fused attention: QK -> softmax -> P@V ----------------
__global__ __launch_bounds__(512, 1)
void fa_k(const bf* __restrict__ A, const bf* __restrict__ B,
          const bf* __restrict__ Vt, bf* __restrict__ Y,
          long sA, long sB)
{
    constexpr int Pw  = 20;
    constexpr int TA1 = 64*Pw, TB1 = 512*Pw, STG1 = TA1+TB1;
    constexpr int PWW = 16*64*Pw;            // P region (20480 words)
    constexpr int TB2 = 256*Pw;              // V tile stage (5120 words)
    extern __shared__ uint32_t smw[];
    const uint32_t smem_u = s2u(smw);

    const int bz = blockIdx.z;
    const bf* Ap = A + (long)bz*sA;
    const bf* Bp = B + (long)bz*sB;
    const int row0 = blockIdx.y*64;
    const int tid = threadIdx.x, warp = tid>>5, lane = tid&31;
    const int g = lane>>2, c4 = lane&3;
    const int wy = warp>>3, wx = warp&7;     // 2 x 8 warps

    uint32_t aoff1[2];
    #pragma unroll
    for (int mi=0;mi<2;mi++)
        aoff1[mi] = (uint32_t)(((wy*32 + mi*16 + (lane & 15))*Pw + (lane>>4)*4) * 4);
    uint32_t boff1[4];
    #pragma unroll
    for (int j=0;j<4;j++)
        boff1[j] = (uint32_t)(((wx*64 + j*16 + ((lane>>4)<<3) + (lane & 7))*Pw + ((lane>>3)&1)*4) * 4);

    auto load_tile1 = [&](int kt, int st){
        uint32_t* base = smw + st*STG1;
        uint32_t* Ah = base;
        uint32_t* Bh = base + TA1;
        const int k0 = kt*32;
        if (tid < 256){
            int r = tid>>2, q = tid&3;
            cp16b(Ah + r*Pw + 4*q, Ap + (long)(row0+r)*256 + k0 + 8*q);
        }
        #pragma unroll
        for (int i=0;i<4;i++){
            int id = tid + i*512; int n = id>>2, q = id&3;
            cp16b(Bh + n*Pw + 4*q, Bp + (long)n*256 + k0 + 8*q);
        }
        cp_commit();
    };

    float acc[2][8][4];
    #pragma unroll
    for (int i=0;i<2;i++)
        #pragma unroll
        for (int j=0;j<8;j++)
            #pragma unroll
            for (int t=0;t<4;t++) acc[i][j][t]=0.f;

    {
        const int nit = 8;   // K=256
        load_tile1(0, 0);
        load_tile1(1, 1);
        int st = 0;
        for (int it=0; it<nit; it++){
            if (it+2 < nit){ load_tile1(it+2, (it+2)%3); cp_wait<2>(); }
            else if (it+1 < nit){ cp_wait<1>(); }
            else { cp_wait<0>(); }
            __syncthreads();

            const uint32_t AhB = smem_u + (uint32_t)(st*STG1*4);
            const uint32_t BhB = AhB + TA1*4;
            #pragma unroll
            for (int ks=0; ks<2; ks++){
                const uint32_t ko = ks*32;
                uint32_t af[2][4], bfr[8][2];
                #pragma unroll
                for (int mi=0; mi<2; mi++)
                    ldsm4(af[mi][0], af[mi][1], af[mi][2], af[mi][3], AhB + aoff1[mi] + ko);
                #pragma unroll
                for (int j=0; j<4; j++)
                    ldsm4(bfr[2*j][0], bfr[2*j][1], bfr[2*j+1][0], bfr[2*j+1][1], BhB + boff1[j] + ko);
                #pragma unroll
                for (int mi=0; mi<2; mi++)
                    #pragma unroll
                    for (int ni=0; ni<8; ni++)
                        mma_bf16(acc[mi][ni], af[mi], bfr[ni]);
            }
            __syncthreads();
            st = (st==2) ? 0 : st+1;
        }
    }

    // softmax (scale 1/16)
    float* red_m = (float*)(smw + PWW + 2*TB2);
    float* red_s = red_m + 64*8;
    #pragma unroll
    for (int mi=0; mi<2; mi++){
        #pragma unroll
        for (int half=0; half<2; half++){
            float mx = -INFINITY;
            #pragma unroll
            for (int ni=0; ni<8; ni++)
                mx = fmaxf(mx, fmaxf(acc[mi][ni][half*2], acc[mi][ni][half*2+1]));
            mx *= 0.0625f;
            float s = 0.f;
            #pragma unroll
            for (int ni=0; ni<8; ni++){
                s += expf(acc[mi][ni][half*2+0]*0.0625f - mx);
                s += expf(acc[mi][ni][half*2+1]*0.0625f - mx);
            }
            float m = mx;
            #pragma unroll
            for (int o=1; o<=2; o<<=1){
                float mo = __shfl_xor_sync(0xffffffffu, m, o);
                float so = __shfl_xor_sync(0xffffffffu, s, o);
                ols_merge(m, s, mo, so);
            }
            int rt = wy*32 + mi*16 + half*8 + g;
            if (c4==0){ red_m[rt*8+wx] = m; red_s[rt*8+wx] = s; }
        }
    }
    __syncthreads();
    if (tid < 64){
        float M = red_m[tid*8], S = red_s[tid*8];
        #pragma unroll
        for (int i=1;i<8;i++) ols_merge(M, S, red_m[tid*8+i], red_s[tid*8+i]);
        red_m[tid*8] = M;
        red_s[tid*8] = 1.f/S;
    }
    __syncthreads();
    #pragma unroll
    for (int mi=0; mi<2; mi++){
        #pragma unroll
        for (int half=0; half<2; half++){
            int rt = wy*32 + mi*16 + half*8 + g;
            float M = red_m[rt*8], inv = red_s[rt*8];
            #pragma unroll
            for (int ni=0; ni<8; ni++){
                int c = wx*64 + ni*8 + 2*c4;
                float p0 = expf(acc[mi][ni][half*2+0]*0.0625f - M)*inv;
                float p1 = expf(acc[mi][ni][half*2+1]*0.0625f - M)*inv;
                smw[(c>>5)*(64*Pw) + rt*Pw + ((c&31)>>1)] = pk2(p0, p1);
            }
        }
    }
    __syncthreads();

    // phase 2: y(64x256) = P @ V^T, K=512
    const int wx2 = warp&7, wy2 = warp>>3;
    uint32_t aoff2[2];
    #pragma unroll
    for (int mi=0;mi<2;mi++)
        aoff2[mi] = (uint32_t)(((wy2*32 + mi*16 + (lane & 15))*Pw + (lane>>4)*4) * 4);
    uint32_t boff2a[2];
    #pragma unroll
    for (int j=0;j<2;j++)
        boff2a[j] = (uint32_t)(((wx2*32 + j*16 + ((lane>>4)<<3) + (lane & 7))*Pw + ((lane>>3)&1)*4) * 4);

    auto load_v = [&](int kt, int st){
        uint32_t* Bh = smw + PWW + st*TB2;
        const int k0 = kt*32;
        #pragma unroll
        for (int i=0;i<2;i++){
            int id = tid + i*512; int n = id>>2, q = id&3;
            cp16b(Bh + n*Pw + 4*q, Vt + (long)n*TOK + bz*512 + k0 + 8*q);
        }
        cp_commit();
    };

    float acc2[2][4][4];
    #pragma unroll
    for (int i=0;i<2;i++)
        #pragma unroll
        for (int j=0;j<4;j++)
            #pragma unroll
            for (int t=0;t<4;t++) acc2[i][j][t]=0.f;

    {
        const int nit = 16;  // K=512
        load_v(0, 0);
        int st = 0;
        for (int it=0; it<nit; it++){
            if (it+1 < nit){ load_v(it+1, st^1); cp_wait<1>(); }
            else { cp_wait<0>(); }
            __syncthreads();

            const uint32_t AB = smem_u + (uint32_t)(it*64*Pw*4);
            const uint32_t BB = smem_u + (uint32_t)((PWW + st*TB2)*4);
            #pragma unroll
            for (int ks=0; ks<2; ks++){
                const uint32_t ko = ks*32;
                uint32_t af[2][4], bfr[4][2];
                #pragma unroll
                for (int mi=0; mi<2; mi++)
                    ldsm4(af[mi][0], af[mi][1], af[mi][2], af[mi][3], AB + aoff2[mi] + ko);
                #pragma unroll
                for (int j=0; j<2; j++)
                    ldsm4(bfr[2*j][0], bfr[2*j][1], bfr[2*j+1][0], bfr[2*j+1][1], BB + boff2a[j] + ko);
                #pragma unroll
                for (int mi=0; mi<2; mi++)
                    #pragma unroll
                    for (int ni=0; ni<4; ni++)
                        mma_bf16(acc2[mi][ni], af[mi], bfr[ni]);
            }
            __syncthreads();
            st ^= 1;
        }
    }

    #pragma unroll
    for (int mi=0; mi<2; mi++){
        #pragma unroll
        for (int half=0; half<2; half++){
            int r = row0 + wy2*32 + mi*16 + g + half*8;
            #pragma unroll
            for (int ni=0; ni<4; ni++){
                int cc = wx2*32 + ni*8 + 2*c4;
                long idx = (((long)(bz*512 + (r>>3)))<<11) + ((long)(r&7)<<8) + cc;
                *(uint32_t*)(Y + idx) = pk2(acc2[mi][ni][half*2+0], acc2[mi][ni][half*2+1]);
            }
        }
    }
}

// ---------------- fused logits GEMM + online-LSE partials (COMP, 128x128, KCH=64) ----------------
__global__ __launch_bounds__(256, 1)
void glse_k(const bf* __restrict__ A, const bf* __restrict__ Alo,
            const bf* __restrict__ B, const bf* __restrict__ Blo,
            float* __restrict__ pm, float* __restrict__ ps)
{
    constexpr int Pw = 36;
    constexpr int TA = 128*Pw, TB = 128*Pw;
    constexpr int STG = 2*(TA+TB);
    extern __shared__ uint32_t smw[];
    const uint32_t smem_u = s2u(smw);

    const int row0 = blockIdx.y*128, col0 = blockIdx.x*128, bx = blockIdx.x;
    const int tid = threadIdx.x, warp = tid>>5, lane = tid&31;
    const int wy = warp>>2, wx = warp&3;     // WM=64, WN=32
    const int g = lane>>2, c4 = lane&3;

    uint32_t aoff[4];
    #pragma unroll
    for (int mi=0;mi<4;mi++)
        aoff[mi] = (uint32_t)(((wy*64 + mi*16 + (lane & 15))*Pw + (lane>>4)*4) * 4);
    uint32_t boff[2];
    #pragma unroll
    for (int j=0;j<2;j++)
        boff[j] = (uint32_t)(((wx*32 + j*16 + ((lane>>4)<<3) + (lane & 7))*Pw + ((lane>>3)&1)*4) * 4);

    auto load_tile = [&](int kt, int st){
        uint32_t* base = smw + st*STG;
        uint32_t* Ah = base;
        uint32_t* Al = base + TA;
        uint32_t* Bh = base + 2*TA;
        uint32_t* Bl = Bh + TB;
        const int k0 = kt*64;
        #pragma unroll
        for (int i=0;i<4;i++){
            int id = tid + i*256; int r = id>>3, q = id&7;
            long go = (long)(row0+r)*256 + k0 + 8*q;
            cp16b(Ah + r*Pw + 4*q, A + go);
            cp16b(Al + r*Pw + 4*q, Alo + go);
            long gb = (long)(col0+r)*256 + k0 + 8*q;
            cp16b(Bh + r*Pw + 4*q, B + gb);
            cp16b(Bl + r*Pw + 4*q, Blo + gb);
        }
        cp_commit();
    };

    float acc[4][4][4];
    #pragma unroll
    for (int i=0;i<4;i++)
        #pragma unroll
        for (int j=0;j<4;j++)
            #pragma unroll
            for (int t=0;t<4;t++) acc[i][j][t]=0.f;

    const int nit = 4;   // K=256, KCH=64
    load_tile(0, 0);
    int st = 0;
    for (int it=0; it<nit; it++){
        if (it+1 < nit){ load_tile(it+1, (it+1)&1); cp_wait<1>(); }
        else { cp_wait<0>(); }
        __syncthreads();

        const uint32_t AhB = smem_u + (uint32_t)(st*STG*4);
        const uint32_t AlB = AhB + TA*4;
        const uint32_t BhB = AhB + 2*TA*4;
        const uint32_t BlB = BhB + TB*4;
        #pragma unroll
        for (int ks=0; ks<4; ks++){
            const uint32_t ko = ks*32;
            uint32_t af[4][4], afl[4][4], bfr[4][2], bfl[4][2];
            #pragma unroll
            for (int mi=0; mi<4; mi++){
                ldsm4(af[mi][0], af[mi][1], af[mi][2], af[mi][3], AhB + aoff[mi] + ko);
                ldsm4(afl[mi][0], afl[mi][1], afl[mi][2], afl[mi][3], AlB + aoff[mi] + ko);
            }
            #pragma unroll
            for (int j=0; j<2; j++){
                ldsm4(bfr[2*j][0], bfr[2*j][1], bfr[2*j+1][0], bfr[2*j+1][1], BhB + boff[j] + ko);
                ldsm4(bfl[2*j][0], bfl[2*j][1], bfl[2*j+1][0], bfl[2*j+1][1], BlB + boff[j] + ko);
            }
            #pragma unroll
            for (int mi=0; mi<4; mi++)
                #pragma unroll
                for (int ni=0; ni<4; ni++){
                    mma_bf16(acc[mi][ni], afl[mi], bfr[ni]);
                    mma_bf16(acc[mi][ni], af[mi], bfl[ni]);
                    mma_bf16(acc[mi][ni], af[mi], bfr[ni]);
                }
        }
        __syncthreads();
        st ^= 1;
    }

    float* red_m = (float*)smw;       // [128][4]
    float* red_s = red_m + 128*4;
    #pragma unroll
    for (int mi=0; mi<4; mi++){
        #pragma unroll
        for (int half=0; half<2; half++){
            float mx = -INFINITY;
            #pragma unroll
            for (int ni=0; ni<4; ni++)
                mx = fmaxf(mx, fmaxf(acc[mi][ni][half*2], acc[mi][ni][half*2+1]));
            float s = 0.f;
            #pragma unroll
            for (int ni=0; ni<4; ni++){
                s += expf(acc[mi][ni][half*2+0]-mx);
                s += expf(acc[mi][ni][half*2+1]-mx);
            }
            float m = mx;
            #pragma unroll
            for (int o=1; o<=2; o<<=1){
                float mo = __shfl_xor_sync(0xffffffffu, m, o);
                float so = __shfl_xor_sync(0xffffffffu, s, o);
                ols_merge(m, s, mo, so);
            }
            int rt = wy*64 + mi*16 + half*8 + g;
            if (c4==0){ red_m[rt*4+wx] = m; red_s[rt*4+wx] = s; }
        }
    }
    __syncthreads();
    if (tid < 128){
        float M = red_m[tid*4], S = red_s[tid*4];
        #pragma unroll
        for (int i=1;i<4;i++) ols_merge(M, S, red_m[tid*4+i], red_s[tid*4+i]);
        long idx = (long)(row0+tid)*250 + bx;
        pm[idx] = M;
        ps[idx] = S;
    }
}

// merge 250 partials per row -> lse
__global__ void lse_red_k(const float* __restrict__ pm, const float* __restrict__ ps,
                          float* __restrict__ lse){
    int row = blockIdx.x*8 + (threadIdx.x>>5);
    int lane = threadIdx.x & 31;
    float m = -INFINITY, s = 0.f;
    for (int i=lane; i<250; i+=32)
        ols_merge(m, s, pm[(long)row*250+i], ps[(long)row*250+i]);
    #pragma unroll
    for (int o=16;o;o>>=1){
        float mo = __shfl_xor_sync(0xffffffffu, m, o);
        float so = __shfl_xor_sync(0xffffffffu, s, o);
        ols_merge(m, s, mo, so);
    }
    if (lane==0) lse[row] = m + logf(s);
}

// exact fp32 target logit
__global__ void tval_k(const bf* __restrict__ vhi, const bf* __restrict__ vlo,
                       const bf* __restrict__ ehi, const bf* __restrict__ elo,
                       const int* __restrict__ unmasked, const int* __restrict__ mask,
                       float* __restrict__ tval){
    int row = blockIdx.x;
    int b = row >> 8, n = row & 255, j = n >> 2;
    int tg = unmasked[b*Ll + mask[b*LM + j]];
    long vi = (long)row*Ee + threadIdx.x;
    long ei = (long)tg*Ee + threadIdx.x;
    float v = (__bfloat162float(vhi[vi]) + __bfloat162float(vlo[vi]))
            * (__bfloat162float(ehi[ei]) + __bfloat162float(elo[ei]));
    float s = block_sum256(v);
    if (threadIdx.x==0) tval[row] = s;
}

// ---------------- prep kernels ----------------
__global__ void prep_w_k(const float* __restrict__ Wt, const float* __restrict__ Wtc,
                         const float* __restrict__ Wu,
                         bf* __restrict__ wc1, bf* __restrict__ wc2)
{
    long idx = (long)blockIdx.x*1024 + threadIdx.x;
    if (idx >= (long)Dd*5*65536) return;
    int d = idx / (5*65536);
    int r = idx % (5*65536);
    int which = r / 65536;
    int e = r % 65536;
    int n = e >> 8, k = e & 255;
    long wb = (long)d*65536;
    if      (which==0) wc1[(long)d*131072 +         n*256+k] = __float2bfloat16(Wt [wb + (long)k*256 + n]);
    else if (which==1) wc1[(long)d*131072 + 65536 + n*256+k] = __float2bfloat16(Wtc[wb + (long)n*256 + k]);
    else if (which==2) wc2[(long)d*196608 + (long)n*768 +       k] = __float2bfloat16(Wtc[wb + (long)k*256 + n]);
    else if (which==3) wc2[(long)d*196608 + (long)n*768 + 256 + k] = __float2bfloat16(Wt [wb + (long)n*256 + k]);
    else               wc2[(long)d*196608 + (long)n*768 + 512 + k] = __float2bfloat16(Wu [wb + (long)n*256 + k]);
}

__global__ void conv_b4(const float4* __restrict__ in, uint2* __restrict__ outp, long n4){
    long i = (long)blockIdx.x*256 + threadIdx.x;
    if (i >= n4) return;
    float4 v = in[i];
    uint2 o; o.x = pk2(v.x, v.y); o.y = pk2(v.z, v.w);
    outp[i] = o;
}

__global__ void split_b4(const float4* __restrict__ in, uint2* __restrict__ hi,
                         uint2* __restrict__ lo, long n4){
    long i = (long)blockIdx.x*256 + threadIdx.x;
    if (i >= n4) return;
    float4 v = in[i];
    bf hx=__float2bfloat16(v.x), hy=__float2bfloat16(v.y);
    bf hz=__float2bfloat16(v.z), hw=__float2bfloat16(v.w);
    union { __nv_bfloat162 b; uint32_t u; } c0, c1;
    c0.b = __halves2bfloat162(hx, hy);
    c1.b = __halves2bfloat162(hz, hw);
    uint2 h; h.x=c0.u; h.y=c1.u;
    uint2 l;
    l.x = pk2(v.x-__bfloat162float(hx), v.y-__bfloat162float(hy));
    l.y = pk2(v.z-__bfloat162float(hz), v.w-__bfloat162float(hw));
    hi[i]=h; lo[i]=l;
}

__global__ void split_lo4(const float4* __restrict__ in, uint2* __restrict__ lo, long n4){
    long i = (long)blockIdx.x*256 + threadIdx.x;
    if (i >= n4) return;
    float4 v = in[i];
    bf hx=__float2bfloat16(v.x), hy=__float2bfloat16(v.y);
    bf hz=__float2bfloat16(v.z), hw=__float2bfloat16(v.w);
    uint2 l;
    l.x = pk2(v.x-__bfloat162float(hx), v.y-__bfloat162float(hy));
    l.y = pk2(v.z-__bfloat162float(hz), v.w-__bfloat162float(hw));
    lo[i]=l;
}

__global__ void t32_f2b(const float* __restrict__ src, bf* __restrict__ dst, int R, int C){
    __shared__ bf t[32][33];
    const float* s = src + (long)blockIdx.z*R*C;
    bf* d = dst + (long)blockIdx.z*R*C;
    int r0 = blockIdx.x*32, c0 = blockIdx.y*32;
    int tx = threadIdx.x & 31, ty = threadIdx.x >> 5;
    #pragma unroll
    for (int i=0;i<4;i++) t[ty+8*i][tx] = __float2bfloat16(s[(long)(r0+ty+8*i)*C + c0+tx]);
    __syncthreads();
    #pragma unroll
    for (int i=0;i<4;i++) d[(long)(c0+ty+8*i)*R + r0+tx] = t[tx][ty+8*i];
}

__global__ void t32_f2b2(const float* __restrict__ src, bf* __restrict__ dh,
                         bf* __restrict__ dl, int R, int C){
    __shared__ bf th[32][33];
    __shared__ bf tl[32][33];
    int r0 = blockIdx.x*32, c0 = blockIdx.y*32;
    int tx = threadIdx.x & 31, ty = threadIdx.x >> 5;
    #pragma unroll
    for (int i=0;i<4;i++){
        float v = src[(long)(r0+ty+8*i)*C + c0+tx];
        bf h = __float2bfloat16(v);
        th[ty+8*i][tx] = h;
        tl[ty+8*i][tx] = __float2bfloat16(v - __bfloat162float(h));
    }
    __syncthreads();
    #pragma unroll
    for (int i=0;i<4;i++){
        dh[(long)(c0+ty+8*i)*R + r0+tx] = th[tx][ty+8*i];
        dl[(long)(c0+ty+8*i)*R + r0+tx] = tl[tx][ty+8*i];
    }
}

__global__ void transpose_b(const bf* __restrict__ src, bf* __restrict__ dst, int R, int C){
    __shared__ bf t[32][33];
    int r0 = blockIdx.x*32, c0 = blockIdx.y*32;
    int tx = threadIdx.x & 31, ty = threadIdx.x >> 5;
    #pragma unroll
    for (int i=0;i<4;i++) t[ty+8*i][tx] = src[(long)(r0+ty+8*i)*C + c0+tx];
    __syncthreads();
    #pragma unroll
    for (int i=0;i<4;i++) dst[(long)(c0+ty+8*i)*R + r0+tx] = t[tx][ty+8*i];
}

// ---------------- elementwise / reduction kernels ----------------
__global__ void embed_norm_k(const int* __restrict__ masked, const float* __restrict__ embed,
                             float* __restrict__ xsa, bf* __restrict__ xsab,
                             bf* __restrict__ xsat, bf* __restrict__ acat)
{
    int t = blockIdx.x;
    int g = masked[t];
    float v = embed[(long)g*Ee + threadIdx.x];
    float mean = block_sum256(v) * (1.f/Ee);
    float d = v - mean;
    float var = block_sum256(d*d) * (1.f/(Ee-1));
    float o = v / (1.f + sqrtf(var));
    xsa [(long)t*Ee + threadIdx.x] = o;
    bf ob = __float2bfloat16(o);
    xsab[(long)t*Ee + threadIdx.x] = ob;
    xsat[(long)threadIdx.x*TOK + t] = ob;
    acat[(long)t*768 + 512 + threadIdx.x] = ob;
}

__global__ void update_norm_k(const float* __restrict__ xsad, const float* __restrict__ t1p,
                              float* __restrict__ xsa, bf* __restrict__ xsab,
                              bf* __restrict__ xsat)
{
    long idx = (long)blockIdx.x*Ee + threadIdx.x;
    const long S = (long)TOK*Ee;
    float u = xsad[idx] + t1p[idx] + t1p[idx+S] + t1p[idx+2*S] + t1p[idx+3*S];
    float mean = block_sum256(u) * (1.f/Ee);
    float d = u - mean;
    float var = block_sum256(d*d) * (1.f/(Ee-1));
    float un = u / (1.f + sqrtf(var));
    float w = xsa[idx] + 0.05f * un;
    float mean2 = block_sum256(w) * (1.f/Ee);
    float d2 = w - mean2;
    float var2 = block_sum256(d2*d2) * (1.f/(Ee-1));
    float o = w / (1.f + sqrtf(var2));
    xsa[idx]  = o;
    bf ob = __float2bfloat16(o);
    xsab[idx] = ob;
    xsat[(long)threadIdx.x*TOK + blockIdx.x] = ob;
}

__global__ void gather_split_k(const int* __restrict__ mask, const float* __restrict__ xsa,
                               bf* __restrict__ hi, bf* __restrict__ lo){
    int r = blockIdx.x; int b = r >> 6; int p = mask[r];
    float v = xsa[(long)(b*Ll + p)*Ee + threadIdx.x];
    bf h = __float2bfloat16(v);
    hi[(long)r*Ee + threadIdx.x] = h;
    lo[(long)r*Ee + threadIdx.x] = __float2bfloat16(v - __bfloat162float(h));
}

__global__ void final_k(const float* __restrict__ tval, const float* __restrict__ lse,
                        float* __restrict__ out)
{
    int b = blockIdx.x, j = threadIdx.x;   // 64 threads
    float a[KN]; float m = -INFINITY;
    #pragma unroll
    for (int kn=0;kn<KN;kn++){
        int r = ((b << 6) + j) * KN + kn;
        a[kn] = tval[r] - lse[r];
        m = fmaxf(m, a[kn]);
    }
    float s = 0.f;
    #pragma unroll
    for (int kn=0;kn<KN;kn++) s += expf(a[kn] - m);
    float cent = m + logf(s) - 1.3862943611198906f;   // - log(4)
    __shared__ float sh[64];
    sh[j] = cent; __syncthreads();
    for (int o=32;o;o>>=1){ if (j<o) sh[j] += sh[j+o]; __syncthreads(); }
    if (j==0) out[b] = -sh[0] / (float)LM;
}

// ---------------- host orchestration ----------------
#define GSYM(p, s) cudaGetSymbolAddress((void**)&p, s)

extern "C" void kernel_launch(void* const* d_in, const int* in_sizes, int n_in,
                              void* d_out, int out_size)
{
    (void)in_sizes; (void)n_in; (void)out_size;
    const int*   masked   = (const int*)  d_in[0];
    const int*   unmasked = (const int*)  d_in[1];
    const int*   maskp    = (const int*)  d_in[2];
    const float* embed    = (const float*)d_in[3];
    const float* Wt       = (const float*)d_in[4];
    const float* bt       = (const float*)d_in[5];
    const float* Wtc      = (const float*)d_in[6];
    const float* Wq       = (const float*)d_in[7];
    const float* Wd       = (const float*)d_in[8];
    const float* Wo       = (const float*)d_in[9];
    const float* Wu       = (const float*)d_in[10];
    const float* Wem      = (const float*)d_in[11];
    const float* Wkc      = (const float*)d_in[12];
    const float* bkc      = (const float*)d_in[13];
    float* out = (float*)d_out;

    float *xsa,*xsad,*t1p,*pm,*ps,*lse,*tval;
    bf *xsab,*xsat,*acat,*q2b,*yb,*midb;
    bf *wq,*wd,*wot,*wc1,*wc2;
    bf *ehi,*elo,*xhlo,*xtlo,*wkhi,*wklo,*wmhi,*wmlo;
    bf *lphi,*lplo,*x1hi,*x1lo,*shi,*slo,*xxhi,*xxlo,*vhi,*vlo;
    GSYM(xsa,g_xsa); GSYM(xsad,g_xsad); GSYM(t1p,g_t1p);
    GSYM(pm,g_pm); GSYM(ps,g_ps); GSYM(lse,g_lse); GSYM(tval,g_tval);
    GSYM(xsab,g_xsab); GSYM(xsat,g_xsat); GSYM(acat,g_acat);
    GSYM(q2b,g_q2b); GSYM(yb,g_yb); GSYM(midb,g_midb);
    GSYM(wq,g_wq); GSYM(wd,g_wd); GSYM(wot,g_wot); GSYM(wc1,g_wc1); GSYM(wc2,g_wc2);
    GSYM(ehi,g_ehi); GSYM(elo,g_elo); GSYM(xhlo,g_xhlo); GSYM(xtlo,g_xtlo);
    GSYM(wkhi,g_wkhi); GSYM(wklo,g_wklo); GSYM(wmhi,g_wmhi); GSYM(wmlo,g_wmlo);
    GSYM(lphi,g_lphi); GSYM(lplo,g_lplo);
    GSYM(x1hi,g_x1hi); GSYM(x1lo,g_x1lo); GSYM(shi,g_shi); GSYM(slo,g_slo);
    GSYM(xxhi,g_xxhi); GSYM(xxlo,g_xxlo); GSYM(vhi,g_vhi); GSYM(vlo,g_vlo);

    // kernel instantiations (all GEMMs: KCH=64)
    auto kS1 = bgemm_k<64,64,32,16,64,true ,false,4,2,false,1>;
    auto kS2 = bgemm_k<64,64,32,16,64,false,true ,0,0,false,0>;
    auto kWq = bgemm_k<128,128,64,32,64,false,false,1,0,false,1>;
    auto kWd = bgemm_k<128,128,64,32,64,true ,false,0,0,false,1>;
    auto kWo = bgemm_k<64,64,32,16,64,false,false,0,0,false,0>;
    auto kG1 = bgemm_k<64,64,32,16,64,false,true ,3,0,true ,2>;
    auto kG2 = bgemm_k<64,64,32,16,64,false,false,0,0,true ,2>;
    auto kG3 = bgemm_k<64,64,32,16,64,false,false,0,0,true ,2>;
    auto kG4 = bgemm_k<64,64,32,16,64,false,false,0,0,true ,2>;

    constexpr int SM_BIG64 = 2*(128+128)*36*4;   // 73728 B
    constexpr int SM_SML64 = 2*(64+64)*36*4;     // 36864 B
    constexpr int SM_CMP64 = 2*2*(64+64)*36*4;   // 73728 B
    constexpr int SM_FA    = 3*(64+512)*20*4;    // 138240 B
    constexpr int SM_GLSE  = 2*2*(128+128)*36*4; // 147456 B

    cudaFuncSetAttribute(kS1, cudaFuncAttributeMaxDynamicSharedMemorySize, SM_SML64);
    cudaFuncSetAttribute(kS2, cudaFuncAttributeMaxDynamicSharedMemorySize, SM_SML64);
    cudaFuncSetAttribute(kWo, cudaFuncAttributeMaxDynamicSharedMemorySize, SM_SML64);
    cudaFuncSetAttribute(kWq, cudaFuncAttributeMaxDynamicSharedMemorySize, SM_BIG64);
    cudaFuncSetAttribute(kWd, cudaFuncAttributeMaxDynamicSharedMemorySize, SM_BIG64);
    cudaFuncSetAttribute(kG1, cudaFuncAttributeMaxDynamicSharedMemorySize, SM_CMP64);
    cudaFuncSetAttribute(kG2, cudaFuncAttributeMaxDynamicSharedMemorySize, SM_CMP64);
    cudaFuncSetAttribute(kG3, cudaFuncAttributeMaxDynamicSharedMemorySize, SM_CMP64);
    cudaFuncSetAttribute(kG4, cudaFuncAttributeMaxDynamicSharedMemorySize, SM_CMP64);
    cudaFuncSetAttribute(fa_k, cudaFuncAttributeMaxDynamicSharedMemorySize, SM_FA);
    cudaFuncSetAttribute(glse_k, cudaFuncAttributeMaxDynamicSharedMemorySize, SM_GLSE);

    // ---- prep: bf16 weights (per launch; graph-captured) ----
    prep_w_k<<<(Dd*5*65536+1023)/1024,1024>>>(Wt, Wtc, Wu, wc1, wc2);
    conv_b4<<<((long)Dd*KE*Ee/4+255)/256,256>>>((const float4*)Wq, (uint2*)wq, (long)Dd*KE*Ee/4);
    conv_b4<<<((long)Dd*KE*KE/4+255)/256,256>>>((const float4*)Wd, (uint2*)wd, (long)Dd*KE*KE/4);
    t32_f2b<<<dim3(KE/32,Ee/32,Dd),256>>>(Wo, wot, KE, Ee);
    split_b4<<<((long)Gg*Ee/4+255)/256,256>>>((const float4*)embed, (uint2*)ehi, (uint2*)elo, (long)Gg*Ee/4);
    split_b4<<<(KN*Ee*Ee/4+255)/256,256>>>((const float4*)Wkc, (uint2*)wkhi, (uint2*)wklo, KN*Ee*Ee/4);
    t32_f2b2<<<dim3(Ee/32,Ee/32,1),256>>>(Wem, wmhi, wmlo, Ee, Ee);

    embed_norm_k<<<TOK,256>>>(masked, embed, xsa, xsab, xsat, acat);

    for (int d=0; d<Dd; d++){
        // transitions
        kS1<<<dim3(4,32,2),256,SM_SML64>>>(xsab,0, wc1+(long)d*131072,0, 0, 0,acat,0,
                                           TOK,Ee,Ee, Ee,Ee, 0, 65536, 0, 1);
        kS2<<<dim3(4,32,1),256,SM_SML64>>>(acat,0, wc2+(long)d*196608,0, bt+(long)d*Ee, xsad,0,0,
                                           TOK,Ee,768, 768,768, 0,0,0, 0);

        // attention (fully fused: QK -> softmax -> P@V)
        kWq<<<dim3(16,16,1),256,SM_BIG64>>>(xsab,0, wq+(long)d*KE*Ee,0, 0, 0,q2b,0,
                                            TOK,KE,Ee, Ee,Ee, 0,0,0, 0);
        fa_k<<<dim3(1,64,Bb),512,SM_FA>>>(q2b, xsab, xsat, yb,
                                          (long)Ll*Kk*Ee, (long)Ll*Ee);

        // dense -> relu -> dense (Wo via split-K=4)
        kWd<<<dim3(16,16,1),256,SM_BIG64>>>(yb,0, wd+(long)d*KE*KE,0, 0, 0,midb,0,
                                            TOK,KE,KE, KE,KE, 0,0,0, 0);
        kWo<<<dim3(4,32,4),256,SM_SML64>>>(midb,0, wot+(long)d*Ee*KE,0, 0, t1p,0,0,
                                           TOK,Ee,512, KE,KE, 512, 512, (long)TOK*Ee, 0);

        update_norm_k<<<TOK,256>>>(xsad, t1p, xsa, xsab, xsat);
    }

    // ---- head (split-bf16 3-mma; hi of xsa == xsab/xsat) ----
    split_lo4<<<(TOK*Ee/4+255)/256,256>>>((const float4*)xsa, (uint2*)xhlo, TOK*Ee/4);
    transpose_b<<<dim3(TOK/32,Ee/32),256>>>(xhlo, xtlo, TOK, Ee);
    gather_split_k<<<Bb*LM,256>>>(maskp, xsa, lphi, lplo);

    kG1<<<dim3(16,4,1),256,SM_CMP64>>>(lphi,lplo, wkhi,wklo, bkc, 0,x1hi,x1lo,
                                       Bb*LM, KN*Ee, Ee, Ee,Ee, 0,0,0, 0);
    kG2<<<dim3(8,4,Bb),256,SM_CMP64>>>(x1hi,x1lo, xsab,xhlo, 0, 0,shi,slo,
                                       LM*KN, Ll, Ee, Ee,Ee,
                                       (long)LM*KN*Ee, (long)Ll*Ee, (long)LM*KN*Ll, 0);
    kG3<<<dim3(4,4,Bb),256,SM_CMP64>>>(shi,slo, xsat,xtlo, 0, 0,xxhi,xxlo,
                                       LM*KN, Ee, Ll, Ll,TOK,
                                       (long)LM*KN*Ll, (long)Ll, (long)LM*KN*Ee, 0);
    kG4<<<dim3(4,16,1),256,SM_CMP64>>>(xxhi,xxlo, wmhi,wmlo, 0, 0,vhi,vlo,
                                       Bb*LM*KN, Ee, Ee, Ee,Ee, 0,0,0, 0);

    // fused logits + LSE (no logits buffer), 128x128 tiles, KCH=64
    glse_k<<<dim3(250,8,1),256,SM_GLSE>>>(vhi, vlo, ehi, elo, pm, ps);
    lse_red_k<<<(Bb*LM*KN)/8,256>>>(pm, ps, lse);
    tval_k<<<Bb*LM*KN,256>>>(vhi, vlo, ehi, elo, unmasked, maskp, tval);
    final_k<<<Bb,64>>>(tval, lse, out);
}